// round 1
// baseline (speedup 1.0000x reference)
#include <cuda_runtime.h>
#include <math.h>

#define D_MODEL 768
#define NHEADS 12
#define HD 64
#define BATCH 2
#define SEQ 8192
#define NTOK (BATCH * SEQ)
#define SE 2048   // s / r for every group

// Scratch (allocation-free rule: __device__ globals)
__device__ float g_q[NTOK * D_MODEL];     // projected q=k=v
__device__ float g_o[NTOK * D_MODEL];     // raw attention outputs (zeros at uncovered slots)
__device__ float g_ln[NTOK * D_MODEL];    // layernormed
__device__ float g_part[32][BATCH * D_MODEL];
__device__ float g_sum[BATCH * D_MODEL];  // per (b, h*64+d) renorm sums

// ---------------------------------------------------------------- zero fill
__global__ void zero_o_kernel() {
    int idx = blockIdx.x * blockDim.x + threadIdx.x;
    const int n4 = NTOK * D_MODEL / 4;
    float4 z = make_float4(0.f, 0.f, 0.f, 0.f);
    for (int i = idx; i < n4; i += gridDim.x * blockDim.x)
        ((float4*)g_o)[i] = z;
}

// ---------------------------------------------------------------- GEMM
// C[M, 768] = A[M,768] @ W[768,768]^T + bias  (both operands K-contiguous)
// 128x64 tile, BK=8, 256 threads, 8x4 micro-tile per thread.
__device__ __forceinline__ void gemm_body(const float* __restrict__ A,
                                          const float* __restrict__ W,
                                          const float* __restrict__ bias,
                                          float* __restrict__ C) {
    __shared__ float As[8][128];
    __shared__ float Ws[8][64];
    const int K = D_MODEL;
    int tid = threadIdx.x;
    int m0 = blockIdx.y * 128;
    int n0 = blockIdx.x * 64;

    float4 acc[8];
#pragma unroll
    for (int i = 0; i < 8; i++) acc[i] = make_float4(0.f, 0.f, 0.f, 0.f);

    int lrow = tid >> 1;          // 0..127
    int lk = (tid & 1) * 4;       // 0 or 4
    int tm = tid >> 4;            // 0..15
    int tn = tid & 15;            // 0..15

    const float* Aptr = A + (size_t)(m0 + lrow) * K + lk;
    const float* Wptr = W + (size_t)(n0 + (lrow & 63)) * K + lk;

    for (int k0 = 0; k0 < K; k0 += 8) {
        float4 av = *(const float4*)(Aptr + k0);
        float4 wv = make_float4(0.f, 0.f, 0.f, 0.f);
        if (tid < 128) wv = *(const float4*)(Wptr + k0);
        __syncthreads();
        As[lk + 0][lrow] = av.x; As[lk + 1][lrow] = av.y;
        As[lk + 2][lrow] = av.z; As[lk + 3][lrow] = av.w;
        if (tid < 128) {
            Ws[lk + 0][lrow] = wv.x; Ws[lk + 1][lrow] = wv.y;
            Ws[lk + 2][lrow] = wv.z; Ws[lk + 3][lrow] = wv.w;
        }
        __syncthreads();
#pragma unroll
        for (int k = 0; k < 8; k++) {
            float4 a0 = *(const float4*)&As[k][tm * 8];
            float4 a1 = *(const float4*)&As[k][tm * 8 + 4];
            float4 bb = *(const float4*)&Ws[k][tn * 4];
            float a[8] = {a0.x, a0.y, a0.z, a0.w, a1.x, a1.y, a1.z, a1.w};
#pragma unroll
            for (int i = 0; i < 8; i++) {
                acc[i].x += a[i] * bb.x;
                acc[i].y += a[i] * bb.y;
                acc[i].z += a[i] * bb.z;
                acc[i].w += a[i] * bb.w;
            }
        }
    }

    int n = n0 + tn * 4;
    float4 bv = *(const float4*)(bias + n);
#pragma unroll
    for (int i = 0; i < 8; i++) {
        int m = m0 + tm * 8 + i;
        float4 r = make_float4(acc[i].x + bv.x, acc[i].y + bv.y,
                               acc[i].z + bv.z, acc[i].w + bv.w);
        *(float4*)(C + (size_t)m * D_MODEL + n) = r;
    }
}

__global__ __launch_bounds__(256) void gemm_in_kernel(const float* __restrict__ x,
                                                      const float* __restrict__ w,
                                                      const float* __restrict__ b) {
    gemm_body(x, w, b, g_q);
}
__global__ __launch_bounds__(256) void gemm_out_kernel(const float* __restrict__ w,
                                                       const float* __restrict__ b,
                                                       float* __restrict__ C) {
    gemm_body(g_ln, w, b, C);
}

// ---------------------------------------------------------------- attention
// One thread = one query row. Block = 128 queries of one (b, group, seg, head)
// instance. K tiles (64 keys x 64 dims) staged in smem; K == V (SAME proj),
// so the same tile serves both the score dot and the PV accumulate.
__global__ __launch_bounds__(128) void attn_kernel() {
    __shared__ float Ks[64][64];

    int inst = blockIdx.y;  // 56 instances: 32 (g0) + 16 (g1) + 8 (g2)
    int b, h, seg, r, off, slen;
    if (inst < 32)      { b = inst >> 4; int t = inst & 15; seg = t >> 2; h = t & 3;        r = 1; off = 0; slen = 2048; }
    else if (inst < 48) { int t = inst - 32; b = t >> 3; t &= 7; seg = t >> 2; h = 4 + (t & 3); r = 2; off = 1; slen = 4096; }
    else                { int t = inst - 48; b = t >> 2; h = 8 + (t & 3); seg = 0;          r = 4; off = 2; slen = 8192; }

    int tid = threadIdx.x;
    int qi = blockIdx.x * 128 + tid;
    int kbase = seg * slen + off;
    int posq = kbase + qi * r;

    const float* qrow = g_q + (size_t)(b * SEQ + posq) * D_MODEL + h * HD;
    float q[HD], o[HD];
#pragma unroll
    for (int i = 0; i < HD / 4; i++) {
        float4 v = *((const float4*)qrow + i);
        q[4 * i + 0] = v.x; q[4 * i + 1] = v.y; q[4 * i + 2] = v.z; q[4 * i + 3] = v.w;
        o[4 * i + 0] = 0.f; o[4 * i + 1] = 0.f; o[4 * i + 2] = 0.f; o[4 * i + 3] = 0.f;
    }
    float m = -1e30f, l = 0.f;

    for (int k0 = 0; k0 < SE; k0 += 64) {
        __syncthreads();
#pragma unroll
        for (int it = 0; it < 8; it++) {
            int lin = tid + it * 128;
            int krow = lin >> 4;
            int c4 = lin & 15;
            int posk = kbase + (k0 + krow) * r;
            *(float4*)&Ks[krow][c4 * 4] =
                *(const float4*)(g_q + (size_t)(b * SEQ + posk) * D_MODEL + h * HD + c4 * 4);
        }
        __syncthreads();

        for (int j = 0; j < 64; j++) {
            float s0 = 0.f, s1 = 0.f, s2 = 0.f, s3 = 0.f;
#pragma unroll
            for (int d = 0; d < HD; d += 4) {
                float4 kv = *(const float4*)&Ks[j][d];
                s0 += q[d + 0] * kv.x;
                s1 += q[d + 1] * kv.y;
                s2 += q[d + 2] * kv.z;
                s3 += q[d + 3] * kv.w;
            }
            float s = ((s0 + s1) + (s2 + s3)) * 0.125f;
            if (s > m) {  // rare: rescale running state
                float alpha = __expf(m - s);
                l *= alpha;
#pragma unroll
                for (int d = 0; d < HD; d++) o[d] *= alpha;
                m = s;
            }
            float p = __expf(s - m);
            l += p;
#pragma unroll
            for (int d = 0; d < HD; d += 4) {
                float4 kv = *(const float4*)&Ks[j][d];
                o[d + 0] += p * kv.x;
                o[d + 1] += p * kv.y;
                o[d + 2] += p * kv.z;
                o[d + 3] += p * kv.w;
            }
        }
    }

    float inv = 1.0f / l;
    float* orow = g_o + (size_t)(b * SEQ + posq) * D_MODEL + h * HD;
#pragma unroll
    for (int i = 0; i < HD / 4; i++) {
        *((float4*)orow + i) = make_float4(o[4 * i + 0] * inv, o[4 * i + 1] * inv,
                                           o[4 * i + 2] * inv, o[4 * i + 3] * inv);
    }
}

// ---------------------------------------------------------------- renorm sums
// Deterministic 2-stage reduction: g_sum[b][c] = sum over all 8192 positions
// of g_o (uncovered slots are exactly 0, so this equals the reference's sum
// over the sliced positions only).
__global__ __launch_bounds__(256) void reduce1_kernel() {
    int bc = blockIdx.x;               // 0..5 : (b, 256-channel block)
    int b = bc / 3, cb = bc % 3;
    int c = cb * 256 + threadIdx.x;
    size_t base = (size_t)(b * SEQ + blockIdx.y * 256) * D_MODEL + c;
    float acc = 0.f;
    for (int rr = 0; rr < 256; rr++) acc += g_o[base + (size_t)rr * D_MODEL];
    g_part[blockIdx.y][b * D_MODEL + c] = acc;
}
__global__ void reduce2_kernel() {
    int idx = blockIdx.x * 256 + threadIdx.x;  // < 1536
    float acc = 0.f;
#pragma unroll
    for (int j = 0; j < 32; j++) acc += g_part[j][idx];
    g_sum[idx] = acc;
}

// ---------------------------------------------------------------- layernorm
__device__ __forceinline__ float blk_sum(float v, float* sh) {
    int lane = threadIdx.x & 31, w = threadIdx.x >> 5;
#pragma unroll
    for (int off = 16; off; off >>= 1) v += __shfl_xor_sync(0xffffffffu, v, off);
    if (lane == 0) sh[w] = v;
    __syncthreads();
    if (threadIdx.x == 0) {
        float t = 0.f;
#pragma unroll
        for (int i = 0; i < 8; i++) t += sh[i];
        sh[8] = t;
    }
    __syncthreads();
    return sh[8];
}

__global__ __launch_bounds__(256) void ln_kernel(const float* __restrict__ gamma,
                                                 const float* __restrict__ beta) {
    __shared__ float sh[9];
    int row = blockIdx.x;
    int b = row >> 13;  // / 8192
    const float* in = g_o + (size_t)row * D_MODEL;
    float v[3];
    float s = 0.f;
#pragma unroll
    for (int i = 0; i < 3; i++) {
        int c = threadIdx.x + i * 256;
        float val = in[c] / (3.0f * g_sum[b * D_MODEL + c]);  // renorm + /num_groups
        v[i] = val;
        s += val;
    }
    float mean = blk_sum(s, sh) * (1.0f / 768.0f);
    float vs = 0.f;
#pragma unroll
    for (int i = 0; i < 3; i++) {
        float d = v[i] - mean;
        vs += d * d;
    }
    float var = blk_sum(vs, sh) * (1.0f / 768.0f);
    float rstd = rsqrtf(var + 1e-5f);
    float* outp = g_ln + (size_t)row * D_MODEL;
#pragma unroll
    for (int i = 0; i < 3; i++) {
        int c = threadIdx.x + i * 256;
        outp[c] = (v[i] - mean) * rstd * gamma[c] + beta[c];
    }
}

// ---------------------------------------------------------------- launch
extern "C" void kernel_launch(void* const* d_in, const int* in_sizes, int n_in,
                              void* d_out, int out_size) {
    const float* x      = (const float*)d_in[0];
    const float* w_in   = (const float*)d_in[1];
    const float* b_in   = (const float*)d_in[2];
    const float* w_out  = (const float*)d_in[3];
    const float* b_out  = (const float*)d_in[4];
    const float* gamma  = (const float*)d_in[5];
    const float* beta   = (const float*)d_in[6];
    float* out = (float*)d_out;

    zero_o_kernel<<<3072, 256>>>();
    gemm_in_kernel<<<dim3(12, 128), 256>>>(x, w_in, b_in);
    attn_kernel<<<dim3(16, 56), 128>>>();
    reduce1_kernel<<<dim3(6, 32), 256>>>();
    reduce2_kernel<<<6, 256>>>();
    ln_kernel<<<NTOK, 256>>>(gamma, beta);
    gemm_out_kernel<<<dim3(12, 128), 256>>>(w_out, b_out, out);
}

// round 5
// speedup vs baseline: 1.2368x; 1.2368x over previous
#include <cuda_runtime.h>
#include <cuda_bf16.h>
#include <stdint.h>
#include <math.h>

#define D_MODEL 768
#define NHEADS 12
#define HD 64
#define BATCH 2
#define SEQ 8192
#define NTOK (BATCH * SEQ)
#define SE 2048   // s / r for every group
#define LOG2E 1.4426950408889634f

// Scratch (allocation-free rule: __device__ globals)
__device__ float g_q[NTOK * D_MODEL];     // projected q=k=v
__device__ float g_o[NTOK * D_MODEL];     // raw attention outputs (zeros at uncovered slots)
__device__ float g_ln[NTOK * D_MODEL];    // layernormed
__device__ float g_part[32][BATCH * D_MODEL];
__device__ float g_sum[BATCH * D_MODEL];  // per (b, h*64+d) renorm sums

// ================================================================ helpers
__device__ __forceinline__ uint32_t smem_u32(const void* p) {
    uint32_t a;
    asm("{ .reg .u64 t; cvta.to.shared.u64 t, %1; cvt.u32.u64 %0, t; }" : "=r"(a) : "l"(p));
    return a;
}

#define SWZ(off) ((off) ^ (((off) >> 3) & 0x70))

__device__ __forceinline__ void ldsm_x4(uint32_t& r0, uint32_t& r1, uint32_t& r2,
                                        uint32_t& r3, uint32_t addr) {
    asm volatile("ldmatrix.sync.aligned.m8n8.x4.shared.b16 {%0,%1,%2,%3}, [%4];"
                 : "=r"(r0), "=r"(r1), "=r"(r2), "=r"(r3) : "r"(addr));
}
__device__ __forceinline__ void ldsm_x4_t(uint32_t& r0, uint32_t& r1, uint32_t& r2,
                                          uint32_t& r3, uint32_t addr) {
    asm volatile("ldmatrix.sync.aligned.m8n8.x4.trans.shared.b16 {%0,%1,%2,%3}, [%4];"
                 : "=r"(r0), "=r"(r1), "=r"(r2), "=r"(r3) : "r"(addr));
}
__device__ __forceinline__ void mma16816(float* c, uint32_t a0, uint32_t a1, uint32_t a2,
                                         uint32_t a3, uint32_t b0, uint32_t b1) {
    asm volatile(
        "mma.sync.aligned.m16n8k16.row.col.f32.bf16.bf16.f32 "
        "{%0,%1,%2,%3}, {%4,%5,%6,%7}, {%8,%9}, {%0,%1,%2,%3};"
        : "+f"(c[0]), "+f"(c[1]), "+f"(c[2]), "+f"(c[3])
        : "r"(a0), "r"(a1), "r"(a2), "r"(a3), "r"(b0), "r"(b1));
}

__device__ __forceinline__ uint32_t pack_bf2(__nv_bfloat16 lo, __nv_bfloat16 hi) {
    return ((uint32_t)__bfloat16_as_ushort(hi) << 16) | (uint32_t)__bfloat16_as_ushort(lo);
}
// 3-term bf16 split of a pair (a -> low half, b -> high half)
__device__ __forceinline__ void split3(float a, float b,
                                       uint32_t& h, uint32_t& m, uint32_t& l) {
    __nv_bfloat16 ah = __float2bfloat16(a), bh = __float2bfloat16(b);
    float ar = a - __bfloat162float(ah), br = b - __bfloat162float(bh);
    __nv_bfloat16 am = __float2bfloat16(ar), bm = __float2bfloat16(br);
    float ar2 = ar - __bfloat162float(am), br2 = br - __bfloat162float(bm);
    __nv_bfloat16 al = __float2bfloat16(ar2), bl = __float2bfloat16(br2);
    h = pack_bf2(ah, bh);
    m = pack_bf2(am, bm);
    l = pack_bf2(al, bl);
}

// FMA-pipe exp2 (no MUFU): clamp, round-to-int magic, deg-6 Taylor, exponent add.
__device__ __forceinline__ float fexp2(float f) {
    f = fmaxf(f, -120.0f);
    float t = f + 12582912.0f;          // 1.5 * 2^23 : RN to integer
    int i = __float_as_int(t);
    float r = f - (t - 12582912.0f);    // r in [-0.5, 0.5]
    float p = 1.33335581e-4f;
    p = fmaf(p, r, 1.35345402e-3f);
    p = fmaf(p, r, 9.61783718e-3f);
    p = fmaf(p, r, 5.55028137e-2f);
    p = fmaf(p, r, 2.40226507e-1f);
    p = fmaf(p, r, 6.93147181e-1f);
    p = fmaf(p, r, 1.0f);
    return __int_as_float(__float_as_int(p) + (i << 23));
}

// ---------------------------------------------------------------- zero fill
__global__ void zero_o_kernel() {
    int idx = blockIdx.x * blockDim.x + threadIdx.x;
    const int n4 = NTOK * D_MODEL / 4;
    float4 z = make_float4(0.f, 0.f, 0.f, 0.f);
    for (int i = idx; i < n4; i += gridDim.x * blockDim.x)
        ((float4*)g_o)[i] = z;
}

// ---------------------------------------------------------------- fp32 GEMM
__device__ __forceinline__ void gemm_body(const float* __restrict__ A,
                                          const float* __restrict__ W,
                                          const float* __restrict__ bias,
                                          float* __restrict__ C) {
    __shared__ float As[8][128];
    __shared__ float Ws[8][64];
    const int K = D_MODEL;
    int tid = threadIdx.x;
    int m0 = blockIdx.y * 128;
    int n0 = blockIdx.x * 64;

    float4 acc[8];
#pragma unroll
    for (int i = 0; i < 8; i++) acc[i] = make_float4(0.f, 0.f, 0.f, 0.f);

    int lrow = tid >> 1;
    int lk = (tid & 1) * 4;
    int tm = tid >> 4;
    int tn = tid & 15;

    const float* Aptr = A + (size_t)(m0 + lrow) * K + lk;
    const float* Wptr = W + (size_t)(n0 + (lrow & 63)) * K + lk;

    for (int k0 = 0; k0 < K; k0 += 8) {
        float4 av = *(const float4*)(Aptr + k0);
        float4 wv = make_float4(0.f, 0.f, 0.f, 0.f);
        if (tid < 128) wv = *(const float4*)(Wptr + k0);
        __syncthreads();
        As[lk + 0][lrow] = av.x; As[lk + 1][lrow] = av.y;
        As[lk + 2][lrow] = av.z; As[lk + 3][lrow] = av.w;
        if (tid < 128) {
            Ws[lk + 0][lrow] = wv.x; Ws[lk + 1][lrow] = wv.y;
            Ws[lk + 2][lrow] = wv.z; Ws[lk + 3][lrow] = wv.w;
        }
        __syncthreads();
#pragma unroll
        for (int k = 0; k < 8; k++) {
            float4 a0 = *(const float4*)&As[k][tm * 8];
            float4 a1 = *(const float4*)&As[k][tm * 8 + 4];
            float4 bb = *(const float4*)&Ws[k][tn * 4];
            float a[8] = {a0.x, a0.y, a0.z, a0.w, a1.x, a1.y, a1.z, a1.w};
#pragma unroll
            for (int i = 0; i < 8; i++) {
                acc[i].x += a[i] * bb.x;
                acc[i].y += a[i] * bb.y;
                acc[i].z += a[i] * bb.z;
                acc[i].w += a[i] * bb.w;
            }
        }
    }

    int n = n0 + tn * 4;
    float4 bv = *(const float4*)(bias + n);
#pragma unroll
    for (int i = 0; i < 8; i++) {
        int m = m0 + tm * 8 + i;
        float4 r = make_float4(acc[i].x + bv.x, acc[i].y + bv.y,
                               acc[i].z + bv.z, acc[i].w + bv.w);
        *(float4*)(C + (size_t)m * D_MODEL + n) = r;
    }
}

__global__ __launch_bounds__(256) void gemm_in_kernel(const float* __restrict__ x,
                                                      const float* __restrict__ w,
                                                      const float* __restrict__ b) {
    gemm_body(x, w, b, g_q);
}
__global__ __launch_bounds__(256) void gemm_out_kernel(const float* __restrict__ w,
                                                       const float* __restrict__ b,
                                                       float* __restrict__ C) {
    gemm_body(g_ln, w, b, C);
}

// ================================================================ attention
// Flash-style, mma.sync m16n8k16 bf16, 3-term split, 6 products with
// SPLIT ACCUMULATORS: hh into *_hi (few roundings at full magnitude),
// corrections (hm, mh, mm, hl, lh) into *_lo (roundings at 2^-9 magnitude).
__global__ __launch_bounds__(256) void attn_mma_kernel() {
    __shared__ __align__(128) uint8_t ksm_h[64 * 128];
    __shared__ __align__(128) uint8_t ksm_m[64 * 128];
    __shared__ __align__(128) uint8_t ksm_l[64 * 128];

    int inst = blockIdx.y;  // 56 instances: 32 (g0) + 16 (g1) + 8 (g2)
    int b, h, seg, r, off, slen;
    if (inst < 32)      { b = inst >> 4; int t = inst & 15; seg = t >> 2; h = t & 3;            r = 1; off = 0; slen = 2048; }
    else if (inst < 48) { int t = inst - 32; b = t >> 3; t &= 7; seg = t >> 2; h = 4 + (t & 3); r = 2; off = 1; slen = 4096; }
    else                { int t = inst - 48; b = t >> 2; h = 8 + (t & 3); seg = 0;              r = 4; off = 2; slen = 8192; }

    int tid = threadIdx.x;
    int warp = tid >> 5, lane = tid & 31;
    int kbase = seg * slen + off;
    int qrow0 = blockIdx.x * 128 + warp * 16;

    uint32_t kh_b = smem_u32(ksm_h);
    uint32_t km_b = smem_u32(ksm_m);
    uint32_t kl_b = smem_u32(ksm_l);

    int r0l = lane >> 2;          // 0..7
    int c2 = (lane & 3) * 2;      // 0,2,4,6

    // -------- Q fragments (unscaled; 1/8 applied to S post-mma), 3-level split
    int posq0 = kbase + (qrow0 + r0l) * r;
    int posq1 = kbase + (qrow0 + r0l + 8) * r;
    const float* qp0 = g_q + ((size_t)b * SEQ + posq0) * D_MODEL + h * HD;
    const float* qp1 = g_q + ((size_t)b * SEQ + posq1) * D_MODEL + h * HD;
    uint32_t qh[16], qm[16], ql[16];
#pragma unroll
    for (int kc = 0; kc < 4; kc++) {
        float2 v00 = *(const float2*)(qp0 + kc * 16 + c2);
        float2 v10 = *(const float2*)(qp1 + kc * 16 + c2);
        float2 v01 = *(const float2*)(qp0 + kc * 16 + c2 + 8);
        float2 v11 = *(const float2*)(qp1 + kc * 16 + c2 + 8);
        split3(v00.x, v00.y, qh[kc * 4 + 0], qm[kc * 4 + 0], ql[kc * 4 + 0]);
        split3(v10.x, v10.y, qh[kc * 4 + 1], qm[kc * 4 + 1], ql[kc * 4 + 1]);
        split3(v01.x, v01.y, qh[kc * 4 + 2], qm[kc * 4 + 2], ql[kc * 4 + 2]);
        split3(v11.x, v11.y, qh[kc * 4 + 3], qm[kc * 4 + 3], ql[kc * 4 + 3]);
    }

    float ohi[8][4], olo[8][4];
#pragma unroll
    for (int j = 0; j < 8; j++) {
        ohi[j][0] = ohi[j][1] = ohi[j][2] = ohi[j][3] = 0.f;
        olo[j][0] = olo[j][1] = olo[j][2] = olo[j][3] = 0.f;
    }
    float m0 = -1e30f, m1 = -1e30f, l0 = 0.f, l1 = 0.f;

    for (int k0 = 0; k0 < SE; k0 += 64) {
        __syncthreads();
        // -------- stage K tile (64 keys x 64 dims) as 3 bf16 levels, swizzled
#pragma unroll
        for (int it = 0; it < 4; it++) {
            int idx = tid + it * 256;
            int key = idx >> 4;
            int dg = idx & 15;
            int posk = kbase + (k0 + key) * r;
            float4 v = *(const float4*)(g_q + ((size_t)b * SEQ + posk) * D_MODEL + h * HD + dg * 4);
            uint32_t h0, m0_, l0_, h1, m1_, l1_;
            split3(v.x, v.y, h0, m0_, l0_);
            split3(v.z, v.w, h1, m1_, l1_);
            uint32_t so = SWZ((uint32_t)(key * 128 + dg * 8));
            *(uint2*)(ksm_h + so) = make_uint2(h0, h1);
            *(uint2*)(ksm_m + so) = make_uint2(m0_, m1_);
            *(uint2*)(ksm_l + so) = make_uint2(l0_, l1_);
        }
        __syncthreads();

        // -------- S = Q K^T  : split accumulators
        float shi[8][4], slo[8][4];
#pragma unroll
        for (int j = 0; j < 8; j++) {
            shi[j][0] = shi[j][1] = shi[j][2] = shi[j][3] = 0.f;
            slo[j][0] = slo[j][1] = slo[j][2] = slo[j][3] = 0.f;
        }
#pragma unroll
        for (int kc = 0; kc < 4; kc++) {
            uint32_t a0h = qh[kc * 4 + 0], a1h = qh[kc * 4 + 1],
                     a2h = qh[kc * 4 + 2], a3h = qh[kc * 4 + 3];
            uint32_t a0m = qm[kc * 4 + 0], a1m = qm[kc * 4 + 1],
                     a2m = qm[kc * 4 + 2], a3m = qm[kc * 4 + 3];
            uint32_t a0l = ql[kc * 4 + 0], a1l = ql[kc * 4 + 1],
                     a2l = ql[kc * 4 + 2], a3l = ql[kc * 4 + 3];
#pragma unroll
            for (int np = 0; np < 4; np++) {
                int key = np * 16 + (lane & 7) + ((lane >> 4) << 3);
                int dim = kc * 16 + (lane & 8);
                uint32_t so = SWZ((uint32_t)(key * 128 + dim * 2));
                uint32_t bh0, bh1, bh2, bh3, bm0, bm1, bm2, bm3, bl0, bl1, bl2, bl3;
                ldsm_x4(bh0, bh1, bh2, bh3, kh_b + so);
                ldsm_x4(bm0, bm1, bm2, bm3, km_b + so);
                ldsm_x4(bl0, bl1, bl2, bl3, kl_b + so);
                // hi: hh ; lo: hm, mh, mm, hl, lh
                mma16816(shi[np * 2 + 0], a0h, a1h, a2h, a3h, bh0, bh1);
                mma16816(slo[np * 2 + 0], a0h, a1h, a2h, a3h, bm0, bm1);
                mma16816(slo[np * 2 + 0], a0m, a1m, a2m, a3m, bh0, bh1);
                mma16816(slo[np * 2 + 0], a0m, a1m, a2m, a3m, bm0, bm1);
                mma16816(slo[np * 2 + 0], a0h, a1h, a2h, a3h, bl0, bl1);
                mma16816(slo[np * 2 + 0], a0l, a1l, a2l, a3l, bh0, bh1);
                mma16816(shi[np * 2 + 1], a0h, a1h, a2h, a3h, bh2, bh3);
                mma16816(slo[np * 2 + 1], a0h, a1h, a2h, a3h, bm2, bm3);
                mma16816(slo[np * 2 + 1], a0m, a1m, a2m, a3m, bh2, bh3);
                mma16816(slo[np * 2 + 1], a0m, a1m, a2m, a3m, bm2, bm3);
                mma16816(slo[np * 2 + 1], a0h, a1h, a2h, a3h, bl2, bl3);
                mma16816(slo[np * 2 + 1], a0l, a1l, a2l, a3l, bh2, bh3);
            }
        }
        // combine + 1/8 scale
        float s[8][4];
#pragma unroll
        for (int j = 0; j < 8; j++) {
            s[j][0] = (shi[j][0] + slo[j][0]) * 0.125f;
            s[j][1] = (shi[j][1] + slo[j][1]) * 0.125f;
            s[j][2] = (shi[j][2] + slo[j][2]) * 0.125f;
            s[j][3] = (shi[j][3] + slo[j][3]) * 0.125f;
        }

        // -------- online softmax
        float mx0 = s[0][0], mx1 = s[0][2];
#pragma unroll
        for (int j = 0; j < 8; j++) {
            mx0 = fmaxf(mx0, fmaxf(s[j][0], s[j][1]));
            mx1 = fmaxf(mx1, fmaxf(s[j][2], s[j][3]));
        }
        mx0 = fmaxf(mx0, __shfl_xor_sync(0xffffffffu, mx0, 1));
        mx0 = fmaxf(mx0, __shfl_xor_sync(0xffffffffu, mx0, 2));
        mx1 = fmaxf(mx1, __shfl_xor_sync(0xffffffffu, mx1, 1));
        mx1 = fmaxf(mx1, __shfl_xor_sync(0xffffffffu, mx1, 2));
        float mn0 = fmaxf(m0, mx0), mn1 = fmaxf(m1, mx1);
        float al0 = fexp2((m0 - mn0) * LOG2E);
        float al1 = fexp2((m1 - mn1) * LOG2E);
        m0 = mn0; m1 = mn1;
        l0 *= al0; l1 *= al1;
#pragma unroll
        for (int j = 0; j < 8; j++) {
            ohi[j][0] *= al0; ohi[j][1] *= al0;
            ohi[j][2] *= al1; ohi[j][3] *= al1;
            olo[j][0] *= al0; olo[j][1] *= al0;
            olo[j][2] *= al1; olo[j][3] *= al1;
        }
        uint32_t pah[8], pam[8], pal[8], pbh[8], pbm[8], pbl[8];
#pragma unroll
        for (int j = 0; j < 8; j++) {
            float p0 = fexp2((s[j][0] - m0) * LOG2E);
            float p1 = fexp2((s[j][1] - m0) * LOG2E);
            float p2 = fexp2((s[j][2] - m1) * LOG2E);
            float p3 = fexp2((s[j][3] - m1) * LOG2E);
            l0 += p0 + p1;
            l1 += p2 + p3;
            split3(p0, p1, pah[j], pam[j], pal[j]);
            split3(p2, p3, pbh[j], pbm[j], pbl[j]);
        }

        // -------- O += P V   (V == K tile), split accumulators
#pragma unroll
        for (int kk = 0; kk < 4; kk++) {
            uint32_t a0h = pah[kk * 2], a1h = pbh[kk * 2],
                     a2h = pah[kk * 2 + 1], a3h = pbh[kk * 2 + 1];
            uint32_t a0m = pam[kk * 2], a1m = pbm[kk * 2],
                     a2m = pam[kk * 2 + 1], a3m = pbm[kk * 2 + 1];
            uint32_t a0l = pal[kk * 2], a1l = pbl[kk * 2],
                     a2l = pal[kk * 2 + 1], a3l = pbl[kk * 2 + 1];
#pragma unroll
            for (int np = 0; np < 4; np++) {
                int key = kk * 16 + (lane & 7) + (lane & 8);
                int dim = np * 16 + ((lane >> 4) << 3);
                uint32_t so = SWZ((uint32_t)(key * 128 + dim * 2));
                uint32_t bh0, bh1, bh2, bh3, bm0, bm1, bm2, bm3, bl0, bl1, bl2, bl3;
                ldsm_x4_t(bh0, bh1, bh2, bh3, kh_b + so);
                ldsm_x4_t(bm0, bm1, bm2, bm3, km_b + so);
                ldsm_x4_t(bl0, bl1, bl2, bl3, kl_b + so);
                mma16816(ohi[np * 2 + 0], a0h, a1h, a2h, a3h, bh0, bh1);
                mma16816(olo[np * 2 + 0], a0h, a1h, a2h, a3h, bm0, bm1);
                mma16816(olo[np * 2 + 0], a0m, a1m, a2m, a3m, bh0, bh1);
                mma16816(olo[np * 2 + 0], a0m, a1m, a2m, a3m, bm0, bm1);
                mma16816(olo[np * 2 + 0], a0h, a1h, a2h, a3h, bl0, bl1);
                mma16816(olo[np * 2 + 0], a0l, a1l, a2l, a3l, bh0, bh1);
                mma16816(ohi[np * 2 + 1], a0h, a1h, a2h, a3h, bh2, bh3);
                mma16816(olo[np * 2 + 1], a0h, a1h, a2h, a3h, bm2, bm3);
                mma16816(olo[np * 2 + 1], a0m, a1m, a2m, a3m, bh2, bh3);
                mma16816(olo[np * 2 + 1], a0m, a1m, a2m, a3m, bm2, bm3);
                mma16816(olo[np * 2 + 1], a0h, a1h, a2h, a3h, bl2, bl3);
                mma16816(olo[np * 2 + 1], a0l, a1l, a2l, a3l, bh2, bh3);
            }
        }
    }

    // -------- finalize
    l0 += __shfl_xor_sync(0xffffffffu, l0, 1);
    l0 += __shfl_xor_sync(0xffffffffu, l0, 2);
    l1 += __shfl_xor_sync(0xffffffffu, l1, 1);
    l1 += __shfl_xor_sync(0xffffffffu, l1, 2);
    float inv0 = 1.0f / l0, inv1 = 1.0f / l1;
    float* op0 = g_o + ((size_t)b * SEQ + posq0) * D_MODEL + h * HD;
    float* op1 = g_o + ((size_t)b * SEQ + posq1) * D_MODEL + h * HD;
#pragma unroll
    for (int j = 0; j < 8; j++) {
        *(float2*)(op0 + j * 8 + c2) = make_float2((ohi[j][0] + olo[j][0]) * inv0,
                                                   (ohi[j][1] + olo[j][1]) * inv0);
        *(float2*)(op1 + j * 8 + c2) = make_float2((ohi[j][2] + olo[j][2]) * inv1,
                                                   (ohi[j][3] + olo[j][3]) * inv1);
    }
}

// ---------------------------------------------------------------- renorm sums
__global__ __launch_bounds__(256) void reduce1_kernel() {
    int bc = blockIdx.x;
    int b = bc / 3, cb = bc % 3;
    int c = cb * 256 + threadIdx.x;
    size_t base = (size_t)(b * SEQ + blockIdx.y * 256) * D_MODEL + c;
    float acc = 0.f;
    for (int rr = 0; rr < 256; rr++) acc += g_o[base + (size_t)rr * D_MODEL];
    g_part[blockIdx.y][b * D_MODEL + c] = acc;
}
__global__ void reduce2_kernel() {
    int idx = blockIdx.x * 256 + threadIdx.x;
    float acc = 0.f;
#pragma unroll
    for (int j = 0; j < 32; j++) acc += g_part[j][idx];
    g_sum[idx] = acc;
}

// ---------------------------------------------------------------- layernorm
__device__ __forceinline__ float blk_sum(float v, float* sh) {
    int lane = threadIdx.x & 31, w = threadIdx.x >> 5;
#pragma unroll
    for (int off = 16; off; off >>= 1) v += __shfl_xor_sync(0xffffffffu, v, off);
    if (lane == 0) sh[w] = v;
    __syncthreads();
    if (threadIdx.x == 0) {
        float t = 0.f;
#pragma unroll
        for (int i = 0; i < 8; i++) t += sh[i];
        sh[8] = t;
    }
    __syncthreads();
    return sh[8];
}

__global__ __launch_bounds__(256) void ln_kernel(const float* __restrict__ gamma,
                                                 const float* __restrict__ beta) {
    __shared__ float sh[9];
    int row = blockIdx.x;
    int b = row >> 13;
    const float* in = g_o + (size_t)row * D_MODEL;
    float v[3];
    float s = 0.f;
#pragma unroll
    for (int i = 0; i < 3; i++) {
        int c = threadIdx.x + i * 256;
        float val = in[c] / (3.0f * g_sum[b * D_MODEL + c]);
        v[i] = val;
        s += val;
    }
    float mean = blk_sum(s, sh) * (1.0f / 768.0f);
    float vs = 0.f;
#pragma unroll
    for (int i = 0; i < 3; i++) {
        float d = v[i] - mean;
        vs += d * d;
    }
    float var = blk_sum(vs, sh) * (1.0f / 768.0f);
    float rstd = rsqrtf(var + 1e-5f);
    float* outp = g_ln + (size_t)row * D_MODEL;
#pragma unroll
    for (int i = 0; i < 3; i++) {
        int c = threadIdx.x + i * 256;
        outp[c] = (v[i] - mean) * rstd * gamma[c] + beta[c];
    }
}

// ---------------------------------------------------------------- launch
extern "C" void kernel_launch(void* const* d_in, const int* in_sizes, int n_in,
                              void* d_out, int out_size) {
    const float* x      = (const float*)d_in[0];
    const float* w_in   = (const float*)d_in[1];
    const float* b_in   = (const float*)d_in[2];
    const float* w_out  = (const float*)d_in[3];
    const float* b_out  = (const float*)d_in[4];
    const float* gamma  = (const float*)d_in[5];
    const float* beta   = (const float*)d_in[6];
    float* out = (float*)d_out;

    zero_o_kernel<<<3072, 256>>>();
    gemm_in_kernel<<<dim3(12, 128), 256>>>(x, w_in, b_in);
    attn_mma_kernel<<<dim3(16, 56), 256>>>();
    reduce1_kernel<<<dim3(6, 32), 256>>>();
    reduce2_kernel<<<6, 256>>>();
    ln_kernel<<<NTOK, 256>>>(gamma, beta);
    gemm_out_kernel<<<dim3(12, 128), 256>>>(w_out, b_out, out);
}

// round 6
// speedup vs baseline: 1.2884x; 1.0417x over previous
#include <cuda_runtime.h>
#include <cuda_bf16.h>
#include <stdint.h>
#include <math.h>

#define D_MODEL 768
#define NHEADS 12
#define HD 64
#define BATCH 2
#define SEQ 8192
#define NTOK (BATCH * SEQ)
#define SE 2048
#define LOG2E 1.4426950408889634f

// Scratch (allocation-free rule: __device__ globals)
__device__ float g_o[NTOK * D_MODEL];
__device__ float g_ln[NTOK * D_MODEL];
__device__ float g_part[32][BATCH * D_MODEL];
__device__ float g_sum[BATCH * D_MODEL];
// bf16 3-level splits
__device__ uint16_t g_ah[NTOK * D_MODEL], g_am[NTOK * D_MODEL], g_al[NTOK * D_MODEL]; // GEMM A (x or ln)
__device__ uint16_t g_qh[NTOK * D_MODEL], g_qm[NTOK * D_MODEL], g_ql[NTOK * D_MODEL]; // projected q
__device__ uint16_t g_w1h[D_MODEL * D_MODEL], g_w1m[D_MODEL * D_MODEL], g_w1l[D_MODEL * D_MODEL];
__device__ uint16_t g_w2h[D_MODEL * D_MODEL], g_w2m[D_MODEL * D_MODEL], g_w2l[D_MODEL * D_MODEL];

// ================================================================ helpers
__device__ __forceinline__ uint32_t smem_u32(const void* p) {
    uint32_t a;
    asm("{ .reg .u64 t; cvta.to.shared.u64 t, %1; cvt.u32.u64 %0, t; }" : "=r"(a) : "l"(p));
    return a;
}

#define SWZ(off) ((off) ^ (((off) >> 3) & 0x70))

__device__ __forceinline__ void ldsm_x4(uint32_t& r0, uint32_t& r1, uint32_t& r2,
                                        uint32_t& r3, uint32_t addr) {
    asm volatile("ldmatrix.sync.aligned.m8n8.x4.shared.b16 {%0,%1,%2,%3}, [%4];"
                 : "=r"(r0), "=r"(r1), "=r"(r2), "=r"(r3) : "r"(addr));
}
__device__ __forceinline__ void ldsm_x4_t(uint32_t& r0, uint32_t& r1, uint32_t& r2,
                                          uint32_t& r3, uint32_t addr) {
    asm volatile("ldmatrix.sync.aligned.m8n8.x4.trans.shared.b16 {%0,%1,%2,%3}, [%4];"
                 : "=r"(r0), "=r"(r1), "=r"(r2), "=r"(r3) : "r"(addr));
}
__device__ __forceinline__ void mma16816(float* c, uint32_t a0, uint32_t a1, uint32_t a2,
                                         uint32_t a3, uint32_t b0, uint32_t b1) {
    asm volatile(
        "mma.sync.aligned.m16n8k16.row.col.f32.bf16.bf16.f32 "
        "{%0,%1,%2,%3}, {%4,%5,%6,%7}, {%8,%9}, {%0,%1,%2,%3};"
        : "+f"(c[0]), "+f"(c[1]), "+f"(c[2]), "+f"(c[3])
        : "r"(a0), "r"(a1), "r"(a2), "r"(a3), "r"(b0), "r"(b1));
}
#define CP_ASYNC16(dst, src) \
    asm volatile("cp.async.cg.shared.global [%0], [%1], 16;" :: "r"(dst), "l"(src))
#define CP_COMMIT() asm volatile("cp.async.commit_group;")

__device__ __forceinline__ uint32_t pack_bf2(__nv_bfloat16 lo, __nv_bfloat16 hi) {
    return ((uint32_t)__bfloat16_as_ushort(hi) << 16) | (uint32_t)__bfloat16_as_ushort(lo);
}
__device__ __forceinline__ void split3(float a, float b,
                                       uint32_t& h, uint32_t& m, uint32_t& l) {
    __nv_bfloat16 ah = __float2bfloat16(a), bh = __float2bfloat16(b);
    float ar = a - __bfloat162float(ah), br = b - __bfloat162float(bh);
    __nv_bfloat16 am = __float2bfloat16(ar), bm = __float2bfloat16(br);
    float ar2 = ar - __bfloat162float(am), br2 = br - __bfloat162float(bm);
    __nv_bfloat16 al = __float2bfloat16(ar2), bl = __float2bfloat16(br2);
    h = pack_bf2(ah, bh);
    m = pack_bf2(am, bm);
    l = pack_bf2(al, bl);
}

// FMA-pipe exp2 (no MUFU)
__device__ __forceinline__ float fexp2(float f) {
    f = fmaxf(f, -120.0f);
    float t = f + 12582912.0f;
    int i = __float_as_int(t);
    float r = f - (t - 12582912.0f);
    float p = 1.33335581e-4f;
    p = fmaf(p, r, 1.35345402e-3f);
    p = fmaf(p, r, 9.61783718e-3f);
    p = fmaf(p, r, 5.55028137e-2f);
    p = fmaf(p, r, 2.40226507e-1f);
    p = fmaf(p, r, 6.93147181e-1f);
    p = fmaf(p, r, 1.0f);
    return __int_as_float(__float_as_int(p) + (i << 23));
}

// ---------------------------------------------------------------- zero fill
__global__ void zero_o_kernel() {
    int idx = blockIdx.x * blockDim.x + threadIdx.x;
    const int n4 = NTOK * D_MODEL / 4;
    float4 z = make_float4(0.f, 0.f, 0.f, 0.f);
    for (int i = idx; i < n4; i += gridDim.x * blockDim.x)
        ((float4*)g_o)[i] = z;
}

// ---------------------------------------------------------------- split
// sel: 0 -> g_a*, 1 -> g_w1*, 2 -> g_w2*
__global__ __launch_bounds__(256) void split_kernel(const float* __restrict__ src,
                                                    int n4, int sel) {
    int i = blockIdx.x * blockDim.x + threadIdx.x;
    if (i >= n4) return;
    float4 v = ((const float4*)src)[i];
    uint32_t h0, m0, l0, h1, m1, l1;
    split3(v.x, v.y, h0, m0, l0);
    split3(v.z, v.w, h1, m1, l1);
    uint2* dh; uint2* dm; uint2* dl;
    if (sel == 0)      { dh = (uint2*)g_ah;  dm = (uint2*)g_am;  dl = (uint2*)g_al; }
    else if (sel == 1) { dh = (uint2*)g_w1h; dm = (uint2*)g_w1m; dl = (uint2*)g_w1l; }
    else               { dh = (uint2*)g_w2h; dm = (uint2*)g_w2m; dl = (uint2*)g_w2l; }
    dh[i] = make_uint2(h0, h1);
    dm[i] = make_uint2(m0, m1);
    dl[i] = make_uint2(l0, l1);
}

// ================================================================ mma GEMM
// C[M,768] = A[M,768] @ W[768,768]^T + bias, bf16x3 split operands,
// split accumulators (hh -> hi ; hm, mh, mm, hl, lh -> lo).
// CTA 256 threads / 8 warps, tile 128x128, K-chunks of 16, cp.async 2-stage.
#define GKC 16
#define NCH (D_MODEL / GKC)       // 48
#define G_LVL_B (128 * 48)        // 6144 B per level (rows stride 48B)
#define G_OP_B (3 * G_LVL_B)      // 18432 per operand
#define G_STAGE (2 * G_OP_B)      // 36864 per buffer
#define GEMM_SMEM_B (2 * G_STAGE) // 73728

__device__ __forceinline__ void gemm_issue(int c, int buf, uint32_t sbase, int tid,
                                           int m0, int n0,
                                           const uint16_t* Bh, const uint16_t* Bm,
                                           const uint16_t* Bl) {
    int k0 = c * GKC;
    uint32_t sb = sbase + buf * G_STAGE;
    int row = tid >> 1, half = tid & 1;
    const uint16_t* srcs[6] = {g_ah, g_am, g_al, Bh, Bm, Bl};
#pragma unroll
    for (int it = 0; it < 6; it++) {
        int grow = (it < 3 ? m0 : n0) + row;
        const uint16_t* sp = srcs[it] + (size_t)grow * D_MODEL + k0 + half * 8;
        uint32_t dst = sb + (it < 3 ? 0 : G_OP_B) + (it % 3) * G_LVL_B + row * 48 + half * 16;
        CP_ASYNC16(dst, sp);
    }
    CP_COMMIT();
}

__global__ __launch_bounds__(256, 1) void gemm_mma_kernel(const float* __restrict__ bias,
                                                          float* __restrict__ outp,
                                                          int mode) {
    extern __shared__ uint8_t gsm[];
    uint32_t sbase = smem_u32(gsm);
    int tid = threadIdx.x, warp = tid >> 5, lane = tid & 31;
    int m0 = blockIdx.y * 128, n0 = blockIdx.x * 128;

    const uint16_t* Bh = (mode == 0) ? g_w1h : g_w2h;
    const uint16_t* Bm = (mode == 0) ? g_w1m : g_w2m;
    const uint16_t* Bl = (mode == 0) ? g_w1l : g_w2l;

    float ohi[16][4], olo[16][4];
#pragma unroll
    for (int j = 0; j < 16; j++) {
        ohi[j][0] = ohi[j][1] = ohi[j][2] = ohi[j][3] = 0.f;
        olo[j][0] = olo[j][1] = olo[j][2] = olo[j][3] = 0.f;
    }

    gemm_issue(0, 0, sbase, tid, m0, n0, Bh, Bm, Bl);

    uint32_t arow = (uint32_t)((warp * 16 + (lane & 15)) * 48 + (lane >> 4) * 16);
    uint32_t brow = (uint32_t)(((lane & 7) + ((lane >> 4) << 3)) * 48 + ((lane & 8) ? 16 : 0));

    for (int c = 0; c < NCH; c++) {
        int buf = c & 1;
        if (c + 1 < NCH) {
            gemm_issue(c + 1, buf ^ 1, sbase, tid, m0, n0, Bh, Bm, Bl);
            asm volatile("cp.async.wait_group 1;");
        } else {
            asm volatile("cp.async.wait_group 0;");
        }
        __syncthreads();

        uint32_t ab = sbase + buf * G_STAGE;
        uint32_t bb = ab + G_OP_B;
        uint32_t ah0, ah1, ah2, ah3, am0, am1, am2, am3, al0, al1, al2, al3;
        ldsm_x4(ah0, ah1, ah2, ah3, ab + 0 * G_LVL_B + arow);
        ldsm_x4(am0, am1, am2, am3, ab + 1 * G_LVL_B + arow);
        ldsm_x4(al0, al1, al2, al3, ab + 2 * G_LVL_B + arow);
#pragma unroll
        for (int np = 0; np < 8; np++) {
            uint32_t baddr = bb + (uint32_t)(np * 16 * 48) + brow;
            uint32_t bh0, bh1, bh2, bh3, bm0, bm1, bm2, bm3, bl0, bl1, bl2, bl3;
            ldsm_x4(bh0, bh1, bh2, bh3, baddr + 0 * G_LVL_B);
            ldsm_x4(bm0, bm1, bm2, bm3, baddr + 1 * G_LVL_B);
            ldsm_x4(bl0, bl1, bl2, bl3, baddr + 2 * G_LVL_B);
            mma16816(ohi[np * 2 + 0], ah0, ah1, ah2, ah3, bh0, bh1);
            mma16816(olo[np * 2 + 0], ah0, ah1, ah2, ah3, bm0, bm1);
            mma16816(olo[np * 2 + 0], am0, am1, am2, am3, bh0, bh1);
            mma16816(olo[np * 2 + 0], am0, am1, am2, am3, bm0, bm1);
            mma16816(olo[np * 2 + 0], ah0, ah1, ah2, ah3, bl0, bl1);
            mma16816(olo[np * 2 + 0], al0, al1, al2, al3, bh0, bh1);
            mma16816(ohi[np * 2 + 1], ah0, ah1, ah2, ah3, bh2, bh3);
            mma16816(olo[np * 2 + 1], ah0, ah1, ah2, ah3, bm2, bm3);
            mma16816(olo[np * 2 + 1], am0, am1, am2, am3, bh2, bh3);
            mma16816(olo[np * 2 + 1], am0, am1, am2, am3, bm2, bm3);
            mma16816(olo[np * 2 + 1], ah0, ah1, ah2, ah3, bl2, bl3);
            mma16816(olo[np * 2 + 1], al0, al1, al2, al3, bh2, bh3);
        }
        __syncthreads();
    }

    // epilogue
    int r0l = lane >> 2, c2 = (lane & 3) * 2;
    int mrow0 = m0 + warp * 16 + r0l;
    int mrow1 = mrow0 + 8;
    if (mode == 0) {
        // write q splits directly
#pragma unroll
        for (int j = 0; j < 16; j++) {
            int col = n0 + j * 8 + c2;
            float2 bv = *(const float2*)(bias + col);
            float v0 = ohi[j][0] + olo[j][0] + bv.x;
            float v1 = ohi[j][1] + olo[j][1] + bv.y;
            float v2 = ohi[j][2] + olo[j][2] + bv.x;
            float v3 = ohi[j][3] + olo[j][3] + bv.y;
            uint32_t h, m, l;
            split3(v0, v1, h, m, l);
            uint32_t i0 = (uint32_t)(mrow0 * D_MODEL + col) >> 1;
            ((uint32_t*)g_qh)[i0] = h;
            ((uint32_t*)g_qm)[i0] = m;
            ((uint32_t*)g_ql)[i0] = l;
            split3(v2, v3, h, m, l);
            uint32_t i1 = (uint32_t)(mrow1 * D_MODEL + col) >> 1;
            ((uint32_t*)g_qh)[i1] = h;
            ((uint32_t*)g_qm)[i1] = m;
            ((uint32_t*)g_ql)[i1] = l;
        }
    } else {
#pragma unroll
        for (int j = 0; j < 16; j++) {
            int col = n0 + j * 8 + c2;
            float2 bv = *(const float2*)(bias + col);
            *(float2*)(outp + (size_t)mrow0 * D_MODEL + col) =
                make_float2(ohi[j][0] + olo[j][0] + bv.x, ohi[j][1] + olo[j][1] + bv.y);
            *(float2*)(outp + (size_t)mrow1 * D_MODEL + col) =
                make_float2(ohi[j][2] + olo[j][2] + bv.x, ohi[j][3] + olo[j][3] + bv.y);
        }
    }
}

// ================================================================ attention
// Flash-style bf16x3 split (pre-split operands in g_q{h,m,l}), split accumulators.
__global__ __launch_bounds__(256) void attn_mma_kernel() {
    __shared__ __align__(128) uint8_t ksm_h[64 * 128];
    __shared__ __align__(128) uint8_t ksm_m[64 * 128];
    __shared__ __align__(128) uint8_t ksm_l[64 * 128];

    int inst = blockIdx.y;
    int b, h, seg, r, off, slen;
    if (inst < 32)      { b = inst >> 4; int t = inst & 15; seg = t >> 2; h = t & 3;            r = 1; off = 0; slen = 2048; }
    else if (inst < 48) { int t = inst - 32; b = t >> 3; t &= 7; seg = t >> 2; h = 4 + (t & 3); r = 2; off = 1; slen = 4096; }
    else                { int t = inst - 48; b = t >> 2; h = 8 + (t & 3); seg = 0;              r = 4; off = 2; slen = 8192; }

    int tid = threadIdx.x;
    int warp = tid >> 5, lane = tid & 31;
    int kbase = seg * slen + off;
    int qrow0 = blockIdx.x * 128 + warp * 16;

    uint32_t kh_b = smem_u32(ksm_h);
    uint32_t km_b = smem_u32(ksm_m);
    uint32_t kl_b = smem_u32(ksm_l);

    int r0l = lane >> 2;
    int c2 = (lane & 3) * 2;

    // -------- Q fragments from pre-split arrays
    int posq0 = kbase + (qrow0 + r0l) * r;
    int posq1 = kbase + (qrow0 + r0l + 8) * r;
    uint32_t qb0 = (uint32_t)(b * SEQ + posq0) * D_MODEL + h * HD;
    uint32_t qb1 = (uint32_t)(b * SEQ + posq1) * D_MODEL + h * HD;
    uint32_t qh[16], qm[16], ql[16];
#pragma unroll
    for (int kc = 0; kc < 4; kc++) {
        uint32_t i00 = (qb0 + kc * 16 + c2) >> 1;
        uint32_t i10 = (qb1 + kc * 16 + c2) >> 1;
        uint32_t i01 = (qb0 + kc * 16 + c2 + 8) >> 1;
        uint32_t i11 = (qb1 + kc * 16 + c2 + 8) >> 1;
        qh[kc * 4 + 0] = ((const uint32_t*)g_qh)[i00];
        qm[kc * 4 + 0] = ((const uint32_t*)g_qm)[i00];
        ql[kc * 4 + 0] = ((const uint32_t*)g_ql)[i00];
        qh[kc * 4 + 1] = ((const uint32_t*)g_qh)[i10];
        qm[kc * 4 + 1] = ((const uint32_t*)g_qm)[i10];
        ql[kc * 4 + 1] = ((const uint32_t*)g_ql)[i10];
        qh[kc * 4 + 2] = ((const uint32_t*)g_qh)[i01];
        qm[kc * 4 + 2] = ((const uint32_t*)g_qm)[i01];
        ql[kc * 4 + 2] = ((const uint32_t*)g_ql)[i01];
        qh[kc * 4 + 3] = ((const uint32_t*)g_qh)[i11];
        qm[kc * 4 + 3] = ((const uint32_t*)g_qm)[i11];
        ql[kc * 4 + 3] = ((const uint32_t*)g_ql)[i11];
    }

    float ohi[8][4], olo[8][4];
#pragma unroll
    for (int j = 0; j < 8; j++) {
        ohi[j][0] = ohi[j][1] = ohi[j][2] = ohi[j][3] = 0.f;
        olo[j][0] = olo[j][1] = olo[j][2] = olo[j][3] = 0.f;
    }
    float m0 = -1e30f, m1 = -1e30f, l0 = 0.f, l1 = 0.f;

    for (int k0 = 0; k0 < SE; k0 += 64) {
        __syncthreads();
        // -------- stage K tile: pure copies from pre-split arrays
#pragma unroll
        for (int it = 0; it < 4; it++) {
            int idx = tid + it * 256;
            int key = idx >> 4;
            int dg = idx & 15;
            int posk = kbase + (k0 + key) * r;
            uint32_t gbase = ((uint32_t)(b * SEQ + posk) * D_MODEL + h * HD) >> 2;
            uint32_t so = SWZ((uint32_t)(key * 128 + dg * 8));
            *(uint2*)(ksm_h + so) = ((const uint2*)g_qh)[gbase + dg];
            *(uint2*)(ksm_m + so) = ((const uint2*)g_qm)[gbase + dg];
            *(uint2*)(ksm_l + so) = ((const uint2*)g_ql)[gbase + dg];
        }
        __syncthreads();

        // -------- S = Q K^T : split accumulators
        float shi[8][4], slo[8][4];
#pragma unroll
        for (int j = 0; j < 8; j++) {
            shi[j][0] = shi[j][1] = shi[j][2] = shi[j][3] = 0.f;
            slo[j][0] = slo[j][1] = slo[j][2] = slo[j][3] = 0.f;
        }
#pragma unroll
        for (int kc = 0; kc < 4; kc++) {
            uint32_t a0h = qh[kc * 4 + 0], a1h = qh[kc * 4 + 1],
                     a2h = qh[kc * 4 + 2], a3h = qh[kc * 4 + 3];
            uint32_t a0m = qm[kc * 4 + 0], a1m = qm[kc * 4 + 1],
                     a2m = qm[kc * 4 + 2], a3m = qm[kc * 4 + 3];
            uint32_t a0l = ql[kc * 4 + 0], a1l = ql[kc * 4 + 1],
                     a2l = ql[kc * 4 + 2], a3l = ql[kc * 4 + 3];
#pragma unroll
            for (int np = 0; np < 4; np++) {
                int key = np * 16 + (lane & 7) + ((lane >> 4) << 3);
                int dim = kc * 16 + (lane & 8);
                uint32_t so = SWZ((uint32_t)(key * 128 + dim * 2));
                uint32_t bh0, bh1, bh2, bh3, bm0, bm1, bm2, bm3, bl0, bl1, bl2, bl3;
                ldsm_x4(bh0, bh1, bh2, bh3, kh_b + so);
                ldsm_x4(bm0, bm1, bm2, bm3, km_b + so);
                ldsm_x4(bl0, bl1, bl2, bl3, kl_b + so);
                mma16816(shi[np * 2 + 0], a0h, a1h, a2h, a3h, bh0, bh1);
                mma16816(slo[np * 2 + 0], a0h, a1h, a2h, a3h, bm0, bm1);
                mma16816(slo[np * 2 + 0], a0m, a1m, a2m, a3m, bh0, bh1);
                mma16816(slo[np * 2 + 0], a0m, a1m, a2m, a3m, bm0, bm1);
                mma16816(slo[np * 2 + 0], a0h, a1h, a2h, a3h, bl0, bl1);
                mma16816(slo[np * 2 + 0], a0l, a1l, a2l, a3l, bh0, bh1);
                mma16816(shi[np * 2 + 1], a0h, a1h, a2h, a3h, bh2, bh3);
                mma16816(slo[np * 2 + 1], a0h, a1h, a2h, a3h, bm2, bm3);
                mma16816(slo[np * 2 + 1], a0m, a1m, a2m, a3m, bh2, bh3);
                mma16816(slo[np * 2 + 1], a0m, a1m, a2m, a3m, bm2, bm3);
                mma16816(slo[np * 2 + 1], a0h, a1h, a2h, a3h, bl2, bl3);
                mma16816(slo[np * 2 + 1], a0l, a1l, a2l, a3l, bh2, bh3);
            }
        }
        float s[8][4];
#pragma unroll
        for (int j = 0; j < 8; j++) {
            s[j][0] = (shi[j][0] + slo[j][0]) * 0.125f;
            s[j][1] = (shi[j][1] + slo[j][1]) * 0.125f;
            s[j][2] = (shi[j][2] + slo[j][2]) * 0.125f;
            s[j][3] = (shi[j][3] + slo[j][3]) * 0.125f;
        }

        // -------- online softmax
        float mx0 = s[0][0], mx1 = s[0][2];
#pragma unroll
        for (int j = 0; j < 8; j++) {
            mx0 = fmaxf(mx0, fmaxf(s[j][0], s[j][1]));
            mx1 = fmaxf(mx1, fmaxf(s[j][2], s[j][3]));
        }
        mx0 = fmaxf(mx0, __shfl_xor_sync(0xffffffffu, mx0, 1));
        mx0 = fmaxf(mx0, __shfl_xor_sync(0xffffffffu, mx0, 2));
        mx1 = fmaxf(mx1, __shfl_xor_sync(0xffffffffu, mx1, 1));
        mx1 = fmaxf(mx1, __shfl_xor_sync(0xffffffffu, mx1, 2));
        float mn0 = fmaxf(m0, mx0), mn1 = fmaxf(m1, mx1);
        float al0 = fexp2((m0 - mn0) * LOG2E);
        float al1 = fexp2((m1 - mn1) * LOG2E);
        m0 = mn0; m1 = mn1;
        l0 *= al0; l1 *= al1;
#pragma unroll
        for (int j = 0; j < 8; j++) {
            ohi[j][0] *= al0; ohi[j][1] *= al0;
            ohi[j][2] *= al1; ohi[j][3] *= al1;
            olo[j][0] *= al0; olo[j][1] *= al0;
            olo[j][2] *= al1; olo[j][3] *= al1;
        }
        uint32_t pah[8], pam[8], pal[8], pbh[8], pbm[8], pbl[8];
#pragma unroll
        for (int j = 0; j < 8; j++) {
            float p0 = fexp2((s[j][0] - m0) * LOG2E);
            float p1 = fexp2((s[j][1] - m0) * LOG2E);
            float p2 = fexp2((s[j][2] - m1) * LOG2E);
            float p3 = fexp2((s[j][3] - m1) * LOG2E);
            l0 += p0 + p1;
            l1 += p2 + p3;
            split3(p0, p1, pah[j], pam[j], pal[j]);
            split3(p2, p3, pbh[j], pbm[j], pbl[j]);
        }

        // -------- O += P V (V == K tile), split accumulators
#pragma unroll
        for (int kk = 0; kk < 4; kk++) {
            uint32_t a0h = pah[kk * 2], a1h = pbh[kk * 2],
                     a2h = pah[kk * 2 + 1], a3h = pbh[kk * 2 + 1];
            uint32_t a0m = pam[kk * 2], a1m = pbm[kk * 2],
                     a2m = pam[kk * 2 + 1], a3m = pbm[kk * 2 + 1];
            uint32_t a0l = pal[kk * 2], a1l = pbl[kk * 2],
                     a2l = pal[kk * 2 + 1], a3l = pbl[kk * 2 + 1];
#pragma unroll
            for (int np = 0; np < 4; np++) {
                int key = kk * 16 + (lane & 7) + (lane & 8);
                int dim = np * 16 + ((lane >> 4) << 3);
                uint32_t so = SWZ((uint32_t)(key * 128 + dim * 2));
                uint32_t bh0, bh1, bh2, bh3, bm0, bm1, bm2, bm3, bl0, bl1, bl2, bl3;
                ldsm_x4_t(bh0, bh1, bh2, bh3, kh_b + so);
                ldsm_x4_t(bm0, bm1, bm2, bm3, km_b + so);
                ldsm_x4_t(bl0, bl1, bl2, bl3, kl_b + so);
                mma16816(ohi[np * 2 + 0], a0h, a1h, a2h, a3h, bh0, bh1);
                mma16816(olo[np * 2 + 0], a0h, a1h, a2h, a3h, bm0, bm1);
                mma16816(olo[np * 2 + 0], a0m, a1m, a2m, a3m, bh0, bh1);
                mma16816(olo[np * 2 + 0], a0m, a1m, a2m, a3m, bm0, bm1);
                mma16816(olo[np * 2 + 0], a0h, a1h, a2h, a3h, bl0, bl1);
                mma16816(olo[np * 2 + 0], a0l, a1l, a2l, a3l, bh0, bh1);
                mma16816(ohi[np * 2 + 1], a0h, a1h, a2h, a3h, bh2, bh3);
                mma16816(olo[np * 2 + 1], a0h, a1h, a2h, a3h, bm2, bm3);
                mma16816(olo[np * 2 + 1], a0m, a1m, a2m, a3m, bh2, bh3);
                mma16816(olo[np * 2 + 1], a0m, a1m, a2m, a3m, bm2, bm3);
                mma16816(olo[np * 2 + 1], a0h, a1h, a2h, a3h, bl2, bl3);
                mma16816(olo[np * 2 + 1], a0l, a1l, a2l, a3l, bh2, bh3);
            }
        }
    }

    // -------- finalize
    l0 += __shfl_xor_sync(0xffffffffu, l0, 1);
    l0 += __shfl_xor_sync(0xffffffffu, l0, 2);
    l1 += __shfl_xor_sync(0xffffffffu, l1, 1);
    l1 += __shfl_xor_sync(0xffffffffu, l1, 2);
    float inv0 = 1.0f / l0, inv1 = 1.0f / l1;
    float* op0 = g_o + ((size_t)b * SEQ + posq0) * D_MODEL + h * HD;
    float* op1 = g_o + ((size_t)b * SEQ + posq1) * D_MODEL + h * HD;
#pragma unroll
    for (int j = 0; j < 8; j++) {
        *(float2*)(op0 + j * 8 + c2) = make_float2((ohi[j][0] + olo[j][0]) * inv0,
                                                   (ohi[j][1] + olo[j][1]) * inv0);
        *(float2*)(op1 + j * 8 + c2) = make_float2((ohi[j][2] + olo[j][2]) * inv1,
                                                   (ohi[j][3] + olo[j][3]) * inv1);
    }
}

// ---------------------------------------------------------------- renorm sums
__global__ __launch_bounds__(256) void reduce1_kernel() {
    int bc = blockIdx.x;
    int b = bc / 3, cb = bc % 3;
    int c = cb * 256 + threadIdx.x;
    size_t base = (size_t)(b * SEQ + blockIdx.y * 256) * D_MODEL + c;
    float acc = 0.f;
    for (int rr = 0; rr < 256; rr++) acc += g_o[base + (size_t)rr * D_MODEL];
    g_part[blockIdx.y][b * D_MODEL + c] = acc;
}
__global__ void reduce2_kernel() {
    int idx = blockIdx.x * 256 + threadIdx.x;
    float acc = 0.f;
#pragma unroll
    for (int j = 0; j < 32; j++) acc += g_part[j][idx];
    g_sum[idx] = acc;
}

// ---------------------------------------------------------------- layernorm
__device__ __forceinline__ float blk_sum(float v, float* sh) {
    int lane = threadIdx.x & 31, w = threadIdx.x >> 5;
#pragma unroll
    for (int off = 16; off; off >>= 1) v += __shfl_xor_sync(0xffffffffu, v, off);
    if (lane == 0) sh[w] = v;
    __syncthreads();
    if (threadIdx.x == 0) {
        float t = 0.f;
#pragma unroll
        for (int i = 0; i < 8; i++) t += sh[i];
        sh[8] = t;
    }
    __syncthreads();
    return sh[8];
}

__global__ __launch_bounds__(256) void ln_kernel(const float* __restrict__ gamma,
                                                 const float* __restrict__ beta) {
    __shared__ float sh[9];
    int row = blockIdx.x;
    int b = row >> 13;
    const float* in = g_o + (size_t)row * D_MODEL;
    float v[3];
    float s = 0.f;
#pragma unroll
    for (int i = 0; i < 3; i++) {
        int c = threadIdx.x + i * 256;
        float val = in[c] / (3.0f * g_sum[b * D_MODEL + c]);
        v[i] = val;
        s += val;
    }
    float mean = blk_sum(s, sh) * (1.0f / 768.0f);
    float vs = 0.f;
#pragma unroll
    for (int i = 0; i < 3; i++) {
        float d = v[i] - mean;
        vs += d * d;
    }
    float var = blk_sum(vs, sh) * (1.0f / 768.0f);
    float rstd = rsqrtf(var + 1e-5f);
    float* outp = g_ln + (size_t)row * D_MODEL;
#pragma unroll
    for (int i = 0; i < 3; i++) {
        int c = threadIdx.x + i * 256;
        outp[c] = (v[i] - mean) * rstd * gamma[c] + beta[c];
    }
}

// ---------------------------------------------------------------- launch
extern "C" void kernel_launch(void* const* d_in, const int* in_sizes, int n_in,
                              void* d_out, int out_size) {
    const float* x      = (const float*)d_in[0];
    const float* w_in   = (const float*)d_in[1];
    const float* b_in   = (const float*)d_in[2];
    const float* w_out  = (const float*)d_in[3];
    const float* b_out  = (const float*)d_in[4];
    const float* gamma  = (const float*)d_in[5];
    const float* beta   = (const float*)d_in[6];
    float* out = (float*)d_out;

    cudaFuncSetAttribute(gemm_mma_kernel, cudaFuncAttributeMaxDynamicSharedMemorySize,
                         GEMM_SMEM_B);

    float* gln;
    cudaGetSymbolAddress((void**)&gln, g_ln);

    const int nbig4 = NTOK * D_MODEL / 4;   // 3145728
    const int nw4 = D_MODEL * D_MODEL / 4;  // 147456

    zero_o_kernel<<<3072, 256>>>();
    split_kernel<<<(nbig4 + 255) / 256, 256>>>(x, nbig4, 0);
    split_kernel<<<(nw4 + 255) / 256, 256>>>(w_in, nw4, 1);
    split_kernel<<<(nw4 + 255) / 256, 256>>>(w_out, nw4, 2);
    gemm_mma_kernel<<<dim3(6, 128), 256, GEMM_SMEM_B>>>(b_in, nullptr, 0);
    attn_mma_kernel<<<dim3(16, 56), 256>>>();
    reduce1_kernel<<<dim3(6, 32), 256>>>();
    reduce2_kernel<<<6, 256>>>();
    ln_kernel<<<NTOK, 256>>>(gamma, beta);
    split_kernel<<<(nbig4 + 255) / 256, 256>>>(gln, nbig4, 0);
    gemm_mma_kernel<<<dim3(6, 128), 256, GEMM_SMEM_B>>>(b_out, out, 1);
}

// round 7
// speedup vs baseline: 1.4002x; 1.0868x over previous
#include <cuda_runtime.h>
#include <cuda_bf16.h>
#include <stdint.h>
#include <math.h>

#define D_MODEL 768
#define NHEADS 12
#define HD 64
#define BATCH 2
#define SEQ 8192
#define NTOK (BATCH * SEQ)
#define SE 2048
#define LOG2E 1.4426950408889634f

// Scratch (allocation-free rule: __device__ globals)
__device__ float g_o[NTOK * D_MODEL];
__device__ float g_part[32][BATCH * D_MODEL];
__device__ float g_sum[BATCH * D_MODEL];
// bf16 3-level splits
__device__ uint16_t g_ah[NTOK * D_MODEL], g_am[NTOK * D_MODEL], g_al[NTOK * D_MODEL]; // GEMM A (x or ln-out)
__device__ uint16_t g_qh[NTOK * D_MODEL], g_qm[NTOK * D_MODEL], g_ql[NTOK * D_MODEL]; // projected q
__device__ uint16_t g_w1h[D_MODEL * D_MODEL], g_w1m[D_MODEL * D_MODEL], g_w1l[D_MODEL * D_MODEL];
__device__ uint16_t g_w2h[D_MODEL * D_MODEL], g_w2m[D_MODEL * D_MODEL], g_w2l[D_MODEL * D_MODEL];

// ================================================================ helpers
__device__ __forceinline__ uint32_t smem_u32(const void* p) {
    uint32_t a;
    asm("{ .reg .u64 t; cvta.to.shared.u64 t, %1; cvt.u32.u64 %0, t; }" : "=r"(a) : "l"(p));
    return a;
}

#define SWZ(off) ((off) ^ (((off) >> 3) & 0x70))

__device__ __forceinline__ void ldsm_x4(uint32_t& r0, uint32_t& r1, uint32_t& r2,
                                        uint32_t& r3, uint32_t addr) {
    asm volatile("ldmatrix.sync.aligned.m8n8.x4.shared.b16 {%0,%1,%2,%3}, [%4];"
                 : "=r"(r0), "=r"(r1), "=r"(r2), "=r"(r3) : "r"(addr));
}
__device__ __forceinline__ void ldsm_x4_t(uint32_t& r0, uint32_t& r1, uint32_t& r2,
                                          uint32_t& r3, uint32_t addr) {
    asm volatile("ldmatrix.sync.aligned.m8n8.x4.trans.shared.b16 {%0,%1,%2,%3}, [%4];"
                 : "=r"(r0), "=r"(r1), "=r"(r2), "=r"(r3) : "r"(addr));
}
__device__ __forceinline__ void mma16816(float* c, uint32_t a0, uint32_t a1, uint32_t a2,
                                         uint32_t a3, uint32_t b0, uint32_t b1) {
    asm volatile(
        "mma.sync.aligned.m16n8k16.row.col.f32.bf16.bf16.f32 "
        "{%0,%1,%2,%3}, {%4,%5,%6,%7}, {%8,%9}, {%0,%1,%2,%3};"
        : "+f"(c[0]), "+f"(c[1]), "+f"(c[2]), "+f"(c[3])
        : "r"(a0), "r"(a1), "r"(a2), "r"(a3), "r"(b0), "r"(b1));
}
#define CP_ASYNC16(dst, src) \
    asm volatile("cp.async.cg.shared.global [%0], [%1], 16;" :: "r"(dst), "l"(src))
#define CP_COMMIT() asm volatile("cp.async.commit_group;")

__device__ __forceinline__ uint32_t pack_bf2(__nv_bfloat16 lo, __nv_bfloat16 hi) {
    return ((uint32_t)__bfloat16_as_ushort(hi) << 16) | (uint32_t)__bfloat16_as_ushort(lo);
}
__device__ __forceinline__ void split3(float a, float b,
                                       uint32_t& h, uint32_t& m, uint32_t& l) {
    __nv_bfloat16 ah = __float2bfloat16(a), bh = __float2bfloat16(b);
    float ar = a - __bfloat162float(ah), br = b - __bfloat162float(bh);
    __nv_bfloat16 am = __float2bfloat16(ar), bm = __float2bfloat16(br);
    float ar2 = ar - __bfloat162float(am), br2 = br - __bfloat162float(bm);
    __nv_bfloat16 al = __float2bfloat16(ar2), bl = __float2bfloat16(br2);
    h = pack_bf2(ah, bh);
    m = pack_bf2(am, bm);
    l = pack_bf2(al, bl);
}
__device__ __forceinline__ void split3s(float a, uint16_t& h, uint16_t& m, uint16_t& l) {
    __nv_bfloat16 ah = __float2bfloat16(a);
    float ar = a - __bfloat162float(ah);
    __nv_bfloat16 am = __float2bfloat16(ar);
    float ar2 = ar - __bfloat162float(am);
    __nv_bfloat16 al = __float2bfloat16(ar2);
    h = __bfloat16_as_ushort(ah);
    m = __bfloat16_as_ushort(am);
    l = __bfloat16_as_ushort(al);
}

// FMA-pipe exp2 (no MUFU)
__device__ __forceinline__ float fexp2(float f) {
    f = fmaxf(f, -120.0f);
    float t = f + 12582912.0f;
    int i = __float_as_int(t);
    float r = f - (t - 12582912.0f);
    float p = 1.33335581e-4f;
    p = fmaf(p, r, 1.35345402e-3f);
    p = fmaf(p, r, 9.61783718e-3f);
    p = fmaf(p, r, 5.55028137e-2f);
    p = fmaf(p, r, 2.40226507e-1f);
    p = fmaf(p, r, 6.93147181e-1f);
    p = fmaf(p, r, 1.0f);
    return __int_as_float(__float_as_int(p) + (i << 23));
}

// ---------------------------------------------------------------- zero fill
__global__ void zero_o_kernel() {
    int idx = blockIdx.x * blockDim.x + threadIdx.x;
    const int n4 = NTOK * D_MODEL / 4;
    float4 z = make_float4(0.f, 0.f, 0.f, 0.f);
    for (int i = idx; i < n4; i += gridDim.x * blockDim.x)
        ((float4*)g_o)[i] = z;
}

// ---------------------------------------------------------------- split
// sel: 0 -> g_a*, 1 -> g_w1*, 2 -> g_w2*
__global__ __launch_bounds__(256) void split_kernel(const float* __restrict__ src,
                                                    int n4, int sel) {
    int i = blockIdx.x * blockDim.x + threadIdx.x;
    if (i >= n4) return;
    float4 v = ((const float4*)src)[i];
    uint32_t h0, m0, l0, h1, m1, l1;
    split3(v.x, v.y, h0, m0, l0);
    split3(v.z, v.w, h1, m1, l1);
    uint2* dh; uint2* dm; uint2* dl;
    if (sel == 0)      { dh = (uint2*)g_ah;  dm = (uint2*)g_am;  dl = (uint2*)g_al; }
    else if (sel == 1) { dh = (uint2*)g_w1h; dm = (uint2*)g_w1m; dl = (uint2*)g_w1l; }
    else               { dh = (uint2*)g_w2h; dm = (uint2*)g_w2m; dl = (uint2*)g_w2l; }
    dh[i] = make_uint2(h0, h1);
    dm[i] = make_uint2(m0, m1);
    dl[i] = make_uint2(l0, l1);
}

// ================================================================ mma GEMM
#define GKC 16
#define NCH (D_MODEL / GKC)       // 48
#define G_LVL_B (128 * 48)
#define G_OP_B (3 * G_LVL_B)
#define G_STAGE (2 * G_OP_B)
#define GEMM_SMEM_B (2 * G_STAGE)

__device__ __forceinline__ void gemm_issue(int c, int buf, uint32_t sbase, int tid,
                                           int m0, int n0,
                                           const uint16_t* Bh, const uint16_t* Bm,
                                           const uint16_t* Bl) {
    int k0 = c * GKC;
    uint32_t sb = sbase + buf * G_STAGE;
    int row = tid >> 1, half = tid & 1;
    const uint16_t* srcs[6] = {g_ah, g_am, g_al, Bh, Bm, Bl};
#pragma unroll
    for (int it = 0; it < 6; it++) {
        int grow = (it < 3 ? m0 : n0) + row;
        const uint16_t* sp = srcs[it] + (size_t)grow * D_MODEL + k0 + half * 8;
        uint32_t dst = sb + (it < 3 ? 0 : G_OP_B) + (it % 3) * G_LVL_B + row * 48 + half * 16;
        CP_ASYNC16(dst, sp);
    }
    CP_COMMIT();
}

__global__ __launch_bounds__(256, 1) void gemm_mma_kernel(const float* __restrict__ bias,
                                                          float* __restrict__ outp,
                                                          int mode) {
    extern __shared__ uint8_t gsm[];
    uint32_t sbase = smem_u32(gsm);
    int tid = threadIdx.x, warp = tid >> 5, lane = tid & 31;
    int m0 = blockIdx.y * 128, n0 = blockIdx.x * 128;

    const uint16_t* Bh = (mode == 0) ? g_w1h : g_w2h;
    const uint16_t* Bm = (mode == 0) ? g_w1m : g_w2m;
    const uint16_t* Bl = (mode == 0) ? g_w1l : g_w2l;

    float ohi[16][4], olo[16][4];
#pragma unroll
    for (int j = 0; j < 16; j++) {
        ohi[j][0] = ohi[j][1] = ohi[j][2] = ohi[j][3] = 0.f;
        olo[j][0] = olo[j][1] = olo[j][2] = olo[j][3] = 0.f;
    }

    gemm_issue(0, 0, sbase, tid, m0, n0, Bh, Bm, Bl);

    uint32_t arow = (uint32_t)((warp * 16 + (lane & 15)) * 48 + (lane >> 4) * 16);
    uint32_t brow = (uint32_t)(((lane & 7) + ((lane >> 4) << 3)) * 48 + ((lane & 8) ? 16 : 0));

    for (int c = 0; c < NCH; c++) {
        int buf = c & 1;
        if (c + 1 < NCH) {
            gemm_issue(c + 1, buf ^ 1, sbase, tid, m0, n0, Bh, Bm, Bl);
            asm volatile("cp.async.wait_group 1;");
        } else {
            asm volatile("cp.async.wait_group 0;");
        }
        __syncthreads();

        uint32_t ab = sbase + buf * G_STAGE;
        uint32_t bb = ab + G_OP_B;
        uint32_t ah0, ah1, ah2, ah3, am0, am1, am2, am3, al0, al1, al2, al3;
        ldsm_x4(ah0, ah1, ah2, ah3, ab + 0 * G_LVL_B + arow);
        ldsm_x4(am0, am1, am2, am3, ab + 1 * G_LVL_B + arow);
        ldsm_x4(al0, al1, al2, al3, ab + 2 * G_LVL_B + arow);
#pragma unroll
        for (int np = 0; np < 8; np++) {
            uint32_t baddr = bb + (uint32_t)(np * 16 * 48) + brow;
            uint32_t bh0, bh1, bh2, bh3, bm0, bm1, bm2, bm3, bl0, bl1, bl2, bl3;
            ldsm_x4(bh0, bh1, bh2, bh3, baddr + 0 * G_LVL_B);
            ldsm_x4(bm0, bm1, bm2, bm3, baddr + 1 * G_LVL_B);
            ldsm_x4(bl0, bl1, bl2, bl3, baddr + 2 * G_LVL_B);
            mma16816(ohi[np * 2 + 0], ah0, ah1, ah2, ah3, bh0, bh1);
            mma16816(olo[np * 2 + 0], ah0, ah1, ah2, ah3, bm0, bm1);
            mma16816(olo[np * 2 + 0], am0, am1, am2, am3, bh0, bh1);
            mma16816(olo[np * 2 + 0], am0, am1, am2, am3, bm0, bm1);
            mma16816(olo[np * 2 + 0], ah0, ah1, ah2, ah3, bl0, bl1);
            mma16816(olo[np * 2 + 0], al0, al1, al2, al3, bh0, bh1);
            mma16816(ohi[np * 2 + 1], ah0, ah1, ah2, ah3, bh2, bh3);
            mma16816(olo[np * 2 + 1], ah0, ah1, ah2, ah3, bm2, bm3);
            mma16816(olo[np * 2 + 1], am0, am1, am2, am3, bh2, bh3);
            mma16816(olo[np * 2 + 1], am0, am1, am2, am3, bm2, bm3);
            mma16816(olo[np * 2 + 1], ah0, ah1, ah2, ah3, bl2, bl3);
            mma16816(olo[np * 2 + 1], al0, al1, al2, al3, bh2, bh3);
        }
        __syncthreads();
    }

    // epilogue
    int r0l = lane >> 2, c2 = (lane & 3) * 2;
    int mrow0 = m0 + warp * 16 + r0l;
    int mrow1 = mrow0 + 8;
    if (mode == 0) {
#pragma unroll
        for (int j = 0; j < 16; j++) {
            int col = n0 + j * 8 + c2;
            float2 bv = *(const float2*)(bias + col);
            float v0 = ohi[j][0] + olo[j][0] + bv.x;
            float v1 = ohi[j][1] + olo[j][1] + bv.y;
            float v2 = ohi[j][2] + olo[j][2] + bv.x;
            float v3 = ohi[j][3] + olo[j][3] + bv.y;
            uint32_t h, m, l;
            split3(v0, v1, h, m, l);
            uint32_t i0 = (uint32_t)(mrow0 * D_MODEL + col) >> 1;
            ((uint32_t*)g_qh)[i0] = h;
            ((uint32_t*)g_qm)[i0] = m;
            ((uint32_t*)g_ql)[i0] = l;
            split3(v2, v3, h, m, l);
            uint32_t i1 = (uint32_t)(mrow1 * D_MODEL + col) >> 1;
            ((uint32_t*)g_qh)[i1] = h;
            ((uint32_t*)g_qm)[i1] = m;
            ((uint32_t*)g_ql)[i1] = l;
        }
    } else {
#pragma unroll
        for (int j = 0; j < 16; j++) {
            int col = n0 + j * 8 + c2;
            float2 bv = *(const float2*)(bias + col);
            *(float2*)(outp + (size_t)mrow0 * D_MODEL + col) =
                make_float2(ohi[j][0] + olo[j][0] + bv.x, ohi[j][1] + olo[j][1] + bv.y);
            *(float2*)(outp + (size_t)mrow1 * D_MODEL + col) =
                make_float2(ohi[j][2] + olo[j][2] + bv.x, ohi[j][3] + olo[j][3] + bv.y);
        }
    }
}

// ================================================================ attention
// Flash-style bf16x3 split + split accumulators, cp.async double-buffered K tiles.
#define KT_LVL 8192                       // 64 keys x 128 B per level
#define KT_BUF (3 * KT_LVL)               // 24576 per buffer

__device__ __forceinline__ void attn_stage(uint32_t dstbase, int b, int kbase,
                                           int k0, int r, int h, int tid) {
#pragma unroll
    for (int it = 0; it < 6; it++) {
        int idx = tid + it * 256;          // 0..1535
        int lvl = idx >> 9;                // 0..2
        int rem = idx & 511;
        int key = rem >> 3;
        int c16 = rem & 7;
        int posk = kbase + (k0 + key) * r;
        uint32_t goff = (uint32_t)(b * SEQ + posk) * D_MODEL + h * HD + c16 * 8;
        const uint16_t* src = (lvl == 0 ? g_qh : (lvl == 1 ? g_qm : g_ql)) + goff;
        uint32_t dst = dstbase + lvl * KT_LVL + SWZ((uint32_t)(key * 128 + c16 * 16));
        CP_ASYNC16(dst, src);
    }
    CP_COMMIT();
}

__global__ __launch_bounds__(256) void attn_mma_kernel() {
    __shared__ __align__(128) uint8_t ksm[2 * KT_BUF];   // 48 KB

    int inst = blockIdx.y;
    int b, h, seg, r, off, slen;
    if (inst < 32)      { b = inst >> 4; int t = inst & 15; seg = t >> 2; h = t & 3;            r = 1; off = 0; slen = 2048; }
    else if (inst < 48) { int t = inst - 32; b = t >> 3; t &= 7; seg = t >> 2; h = 4 + (t & 3); r = 2; off = 1; slen = 4096; }
    else                { int t = inst - 48; b = t >> 2; h = 8 + (t & 3); seg = 0;              r = 4; off = 2; slen = 8192; }

    int tid = threadIdx.x;
    int warp = tid >> 5, lane = tid & 31;
    int kbase = seg * slen + off;
    int qrow0 = blockIdx.x * 128 + warp * 16;

    uint32_t smb = smem_u32(ksm);

    int r0l = lane >> 2;
    int c2 = (lane & 3) * 2;

    // -------- Q fragments from pre-split arrays
    int posq0 = kbase + (qrow0 + r0l) * r;
    int posq1 = kbase + (qrow0 + r0l + 8) * r;
    uint32_t qb0 = (uint32_t)(b * SEQ + posq0) * D_MODEL + h * HD;
    uint32_t qb1 = (uint32_t)(b * SEQ + posq1) * D_MODEL + h * HD;
    uint32_t qh[16], qm[16], ql[16];
#pragma unroll
    for (int kc = 0; kc < 4; kc++) {
        uint32_t i00 = (qb0 + kc * 16 + c2) >> 1;
        uint32_t i10 = (qb1 + kc * 16 + c2) >> 1;
        uint32_t i01 = (qb0 + kc * 16 + c2 + 8) >> 1;
        uint32_t i11 = (qb1 + kc * 16 + c2 + 8) >> 1;
        qh[kc * 4 + 0] = ((const uint32_t*)g_qh)[i00];
        qm[kc * 4 + 0] = ((const uint32_t*)g_qm)[i00];
        ql[kc * 4 + 0] = ((const uint32_t*)g_ql)[i00];
        qh[kc * 4 + 1] = ((const uint32_t*)g_qh)[i10];
        qm[kc * 4 + 1] = ((const uint32_t*)g_qm)[i10];
        ql[kc * 4 + 1] = ((const uint32_t*)g_ql)[i10];
        qh[kc * 4 + 2] = ((const uint32_t*)g_qh)[i01];
        qm[kc * 4 + 2] = ((const uint32_t*)g_qm)[i01];
        ql[kc * 4 + 2] = ((const uint32_t*)g_ql)[i01];
        qh[kc * 4 + 3] = ((const uint32_t*)g_qh)[i11];
        qm[kc * 4 + 3] = ((const uint32_t*)g_qm)[i11];
        ql[kc * 4 + 3] = ((const uint32_t*)g_ql)[i11];
    }

    float ohi[8][4], olo[8][4];
#pragma unroll
    for (int j = 0; j < 8; j++) {
        ohi[j][0] = ohi[j][1] = ohi[j][2] = ohi[j][3] = 0.f;
        olo[j][0] = olo[j][1] = olo[j][2] = olo[j][3] = 0.f;
    }
    float m0 = -1e30f, m1 = -1e30f, l0 = 0.f, l1 = 0.f;

    // prefetch tile 0
    attn_stage(smb, b, kbase, 0, r, h, tid);

    int buf = 0;
    for (int kt = 0; kt < SE / 64; kt++) {
        if (kt + 1 < SE / 64) {
            attn_stage(smb + (buf ^ 1) * KT_BUF, b, kbase, (kt + 1) * 64, r, h, tid);
            asm volatile("cp.async.wait_group 1;");
        } else {
            asm volatile("cp.async.wait_group 0;");
        }
        __syncthreads();

        uint32_t kh_b = smb + buf * KT_BUF;
        uint32_t km_b = kh_b + KT_LVL;
        uint32_t kl_b = km_b + KT_LVL;

        // -------- S = Q K^T : split accumulators
        float shi[8][4], slo[8][4];
#pragma unroll
        for (int j = 0; j < 8; j++) {
            shi[j][0] = shi[j][1] = shi[j][2] = shi[j][3] = 0.f;
            slo[j][0] = slo[j][1] = slo[j][2] = slo[j][3] = 0.f;
        }
#pragma unroll
        for (int kc = 0; kc < 4; kc++) {
            uint32_t a0h = qh[kc * 4 + 0], a1h = qh[kc * 4 + 1],
                     a2h = qh[kc * 4 + 2], a3h = qh[kc * 4 + 3];
            uint32_t a0m = qm[kc * 4 + 0], a1m = qm[kc * 4 + 1],
                     a2m = qm[kc * 4 + 2], a3m = qm[kc * 4 + 3];
            uint32_t a0l = ql[kc * 4 + 0], a1l = ql[kc * 4 + 1],
                     a2l = ql[kc * 4 + 2], a3l = ql[kc * 4 + 3];
#pragma unroll
            for (int np = 0; np < 4; np++) {
                int key = np * 16 + (lane & 7) + ((lane >> 4) << 3);
                int dim = kc * 16 + (lane & 8);
                uint32_t so = SWZ((uint32_t)(key * 128 + dim * 2));
                uint32_t bh0, bh1, bh2, bh3, bm0, bm1, bm2, bm3, bl0, bl1, bl2, bl3;
                ldsm_x4(bh0, bh1, bh2, bh3, kh_b + so);
                ldsm_x4(bm0, bm1, bm2, bm3, km_b + so);
                ldsm_x4(bl0, bl1, bl2, bl3, kl_b + so);
                mma16816(shi[np * 2 + 0], a0h, a1h, a2h, a3h, bh0, bh1);
                mma16816(slo[np * 2 + 0], a0h, a1h, a2h, a3h, bm0, bm1);
                mma16816(slo[np * 2 + 0], a0m, a1m, a2m, a3m, bh0, bh1);
                mma16816(slo[np * 2 + 0], a0m, a1m, a2m, a3m, bm0, bm1);
                mma16816(slo[np * 2 + 0], a0h, a1h, a2h, a3h, bl0, bl1);
                mma16816(slo[np * 2 + 0], a0l, a1l, a2l, a3l, bh0, bh1);
                mma16816(shi[np * 2 + 1], a0h, a1h, a2h, a3h, bh2, bh3);
                mma16816(slo[np * 2 + 1], a0h, a1h, a2h, a3h, bm2, bm3);
                mma16816(slo[np * 2 + 1], a0m, a1m, a2m, a3m, bh2, bh3);
                mma16816(slo[np * 2 + 1], a0m, a1m, a2m, a3m, bm2, bm3);
                mma16816(slo[np * 2 + 1], a0h, a1h, a2h, a3h, bl2, bl3);
                mma16816(slo[np * 2 + 1], a0l, a1l, a2l, a3l, bh2, bh3);
            }
        }
        float s[8][4];
#pragma unroll
        for (int j = 0; j < 8; j++) {
            s[j][0] = (shi[j][0] + slo[j][0]) * 0.125f;
            s[j][1] = (shi[j][1] + slo[j][1]) * 0.125f;
            s[j][2] = (shi[j][2] + slo[j][2]) * 0.125f;
            s[j][3] = (shi[j][3] + slo[j][3]) * 0.125f;
        }

        // -------- online softmax
        float mx0 = s[0][0], mx1 = s[0][2];
#pragma unroll
        for (int j = 0; j < 8; j++) {
            mx0 = fmaxf(mx0, fmaxf(s[j][0], s[j][1]));
            mx1 = fmaxf(mx1, fmaxf(s[j][2], s[j][3]));
        }
        mx0 = fmaxf(mx0, __shfl_xor_sync(0xffffffffu, mx0, 1));
        mx0 = fmaxf(mx0, __shfl_xor_sync(0xffffffffu, mx0, 2));
        mx1 = fmaxf(mx1, __shfl_xor_sync(0xffffffffu, mx1, 1));
        mx1 = fmaxf(mx1, __shfl_xor_sync(0xffffffffu, mx1, 2));
        float mn0 = fmaxf(m0, mx0), mn1 = fmaxf(m1, mx1);
        float al0 = fexp2((m0 - mn0) * LOG2E);
        float al1 = fexp2((m1 - mn1) * LOG2E);
        m0 = mn0; m1 = mn1;
        l0 *= al0; l1 *= al1;
#pragma unroll
        for (int j = 0; j < 8; j++) {
            ohi[j][0] *= al0; ohi[j][1] *= al0;
            ohi[j][2] *= al1; ohi[j][3] *= al1;
            olo[j][0] *= al0; olo[j][1] *= al0;
            olo[j][2] *= al1; olo[j][3] *= al1;
        }
        uint32_t pah[8], pam[8], pal[8], pbh[8], pbm[8], pbl[8];
#pragma unroll
        for (int j = 0; j < 8; j++) {
            float p0 = fexp2((s[j][0] - m0) * LOG2E);
            float p1 = fexp2((s[j][1] - m0) * LOG2E);
            float p2 = fexp2((s[j][2] - m1) * LOG2E);
            float p3 = fexp2((s[j][3] - m1) * LOG2E);
            l0 += p0 + p1;
            l1 += p2 + p3;
            split3(p0, p1, pah[j], pam[j], pal[j]);
            split3(p2, p3, pbh[j], pbm[j], pbl[j]);
        }

        // -------- O += P V (V == K tile), split accumulators
#pragma unroll
        for (int kk = 0; kk < 4; kk++) {
            uint32_t a0h = pah[kk * 2], a1h = pbh[kk * 2],
                     a2h = pah[kk * 2 + 1], a3h = pbh[kk * 2 + 1];
            uint32_t a0m = pam[kk * 2], a1m = pbm[kk * 2],
                     a2m = pam[kk * 2 + 1], a3m = pbm[kk * 2 + 1];
            uint32_t a0l = pal[kk * 2], a1l = pbl[kk * 2],
                     a2l = pal[kk * 2 + 1], a3l = pbl[kk * 2 + 1];
#pragma unroll
            for (int np = 0; np < 4; np++) {
                int key = kk * 16 + (lane & 7) + (lane & 8);
                int dim = np * 16 + ((lane >> 4) << 3);
                uint32_t so = SWZ((uint32_t)(key * 128 + dim * 2));
                uint32_t bh0, bh1, bh2, bh3, bm0, bm1, bm2, bm3, bl0, bl1, bl2, bl3;
                ldsm_x4_t(bh0, bh1, bh2, bh3, kh_b + so);
                ldsm_x4_t(bm0, bm1, bm2, bm3, km_b + so);
                ldsm_x4_t(bl0, bl1, bl2, bl3, kl_b + so);
                mma16816(ohi[np * 2 + 0], a0h, a1h, a2h, a3h, bh0, bh1);
                mma16816(olo[np * 2 + 0], a0h, a1h, a2h, a3h, bm0, bm1);
                mma16816(olo[np * 2 + 0], a0m, a1m, a2m, a3m, bh0, bh1);
                mma16816(olo[np * 2 + 0], a0m, a1m, a2m, a3m, bm0, bm1);
                mma16816(olo[np * 2 + 0], a0h, a1h, a2h, a3h, bl0, bl1);
                mma16816(olo[np * 2 + 0], a0l, a1l, a2l, a3l, bh0, bh1);
                mma16816(ohi[np * 2 + 1], a0h, a1h, a2h, a3h, bh2, bh3);
                mma16816(olo[np * 2 + 1], a0h, a1h, a2h, a3h, bm2, bm3);
                mma16816(olo[np * 2 + 1], a0m, a1m, a2m, a3m, bh2, bh3);
                mma16816(olo[np * 2 + 1], a0m, a1m, a2m, a3m, bm2, bm3);
                mma16816(olo[np * 2 + 1], a0h, a1h, a2h, a3h, bl2, bl3);
                mma16816(olo[np * 2 + 1], a0l, a1l, a2l, a3l, bh2, bh3);
            }
        }
        __syncthreads();   // all reads of buf done before next iter's issue overwrites
        buf ^= 1;
    }

    // -------- finalize
    l0 += __shfl_xor_sync(0xffffffffu, l0, 1);
    l0 += __shfl_xor_sync(0xffffffffu, l0, 2);
    l1 += __shfl_xor_sync(0xffffffffu, l1, 1);
    l1 += __shfl_xor_sync(0xffffffffu, l1, 2);
    float inv0 = 1.0f / l0, inv1 = 1.0f / l1;
    float* op0 = g_o + ((size_t)b * SEQ + posq0) * D_MODEL + h * HD;
    float* op1 = g_o + ((size_t)b * SEQ + posq1) * D_MODEL + h * HD;
#pragma unroll
    for (int j = 0; j < 8; j++) {
        *(float2*)(op0 + j * 8 + c2) = make_float2((ohi[j][0] + olo[j][0]) * inv0,
                                                   (ohi[j][1] + olo[j][1]) * inv0);
        *(float2*)(op1 + j * 8 + c2) = make_float2((ohi[j][2] + olo[j][2]) * inv1,
                                                   (ohi[j][3] + olo[j][3]) * inv1);
    }
}

// ---------------------------------------------------------------- renorm sums
__global__ __launch_bounds__(256) void reduce1_kernel() {
    int bc = blockIdx.x;
    int b = bc / 3, cb = bc % 3;
    int c = cb * 256 + threadIdx.x;
    size_t base = (size_t)(b * SEQ + blockIdx.y * 256) * D_MODEL + c;
    float acc = 0.f;
    for (int rr = 0; rr < 256; rr++) acc += g_o[base + (size_t)rr * D_MODEL];
    g_part[blockIdx.y][b * D_MODEL + c] = acc;
}
__global__ void reduce2_kernel() {
    int idx = blockIdx.x * 256 + threadIdx.x;
    float acc = 0.f;
#pragma unroll
    for (int j = 0; j < 32; j++) acc += g_part[j][idx];
    g_sum[idx] = acc;
}

// ---------------------------------------------------------------- layernorm (writes A splits directly)
__device__ __forceinline__ float blk_sum(float v, float* sh) {
    int lane = threadIdx.x & 31, w = threadIdx.x >> 5;
#pragma unroll
    for (int off = 16; off; off >>= 1) v += __shfl_xor_sync(0xffffffffu, v, off);
    if (lane == 0) sh[w] = v;
    __syncthreads();
    if (threadIdx.x == 0) {
        float t = 0.f;
#pragma unroll
        for (int i = 0; i < 8; i++) t += sh[i];
        sh[8] = t;
    }
    __syncthreads();
    return sh[8];
}

__global__ __launch_bounds__(256) void ln_kernel(const float* __restrict__ gamma,
                                                 const float* __restrict__ beta) {
    __shared__ float sh[9];
    int row = blockIdx.x;
    int b = row >> 13;
    const float* in = g_o + (size_t)row * D_MODEL;
    float v[3];
    float s = 0.f;
#pragma unroll
    for (int i = 0; i < 3; i++) {
        int c = threadIdx.x + i * 256;
        float val = in[c] / (3.0f * g_sum[b * D_MODEL + c]);
        v[i] = val;
        s += val;
    }
    float mean = blk_sum(s, sh) * (1.0f / 768.0f);
    float vs = 0.f;
#pragma unroll
    for (int i = 0; i < 3; i++) {
        float d = v[i] - mean;
        vs += d * d;
    }
    float var = blk_sum(vs, sh) * (1.0f / 768.0f);
    float rstd = rsqrtf(var + 1e-5f);
#pragma unroll
    for (int i = 0; i < 3; i++) {
        int c = threadIdx.x + i * 256;
        float outv = (v[i] - mean) * rstd * gamma[c] + beta[c];
        uint16_t hh, mm, ll;
        split3s(outv, hh, mm, ll);
        size_t idx = (size_t)row * D_MODEL + c;
        g_ah[idx] = hh;
        g_am[idx] = mm;
        g_al[idx] = ll;
    }
}

// ---------------------------------------------------------------- launch
extern "C" void kernel_launch(void* const* d_in, const int* in_sizes, int n_in,
                              void* d_out, int out_size) {
    const float* x      = (const float*)d_in[0];
    const float* w_in   = (const float*)d_in[1];
    const float* b_in   = (const float*)d_in[2];
    const float* w_out  = (const float*)d_in[3];
    const float* b_out  = (const float*)d_in[4];
    const float* gamma  = (const float*)d_in[5];
    const float* beta   = (const float*)d_in[6];
    float* out = (float*)d_out;

    cudaFuncSetAttribute(gemm_mma_kernel, cudaFuncAttributeMaxDynamicSharedMemorySize,
                         GEMM_SMEM_B);

    const int nbig4 = NTOK * D_MODEL / 4;
    const int nw4 = D_MODEL * D_MODEL / 4;

    zero_o_kernel<<<3072, 256>>>();
    split_kernel<<<(nbig4 + 255) / 256, 256>>>(x, nbig4, 0);
    split_kernel<<<(nw4 + 255) / 256, 256>>>(w_in, nw4, 1);
    split_kernel<<<(nw4 + 255) / 256, 256>>>(w_out, nw4, 2);
    gemm_mma_kernel<<<dim3(6, 128), 256, GEMM_SMEM_B>>>(b_in, nullptr, 0);
    attn_mma_kernel<<<dim3(16, 56), 256>>>();
    reduce1_kernel<<<dim3(6, 32), 256>>>();
    reduce2_kernel<<<6, 256>>>();
    ln_kernel<<<NTOK, 256>>>(gamma, beta);
    gemm_mma_kernel<<<dim3(6, 128), 256, GEMM_SMEM_B>>>(b_out, out, 1);
}

// round 9
// speedup vs baseline: 1.5907x; 1.1361x over previous
#include <cuda_runtime.h>
#include <cuda_bf16.h>
#include <cuda_fp16.h>
#include <stdint.h>
#include <math.h>

#define D_MODEL 768
#define NHEADS 12
#define HD 64
#define BATCH 2
#define SEQ 8192
#define NTOK (BATCH * SEQ)
#define SE 2048
#define LOG2E 1.4426950408889634f

// Scratch (allocation-free rule: __device__ globals)
__device__ float g_o[NTOK * D_MODEL];
__device__ float g_part[32][BATCH * D_MODEL];
__device__ float g_sum[BATCH * D_MODEL];
// g_a*: bf16x3 of x for gemm1; later fp16x2 of ln-out for gemm2 (g_am unused then)
__device__ uint16_t g_ah[NTOK * D_MODEL], g_am[NTOK * D_MODEL], g_al[NTOK * D_MODEL];
// projected q: bf16x3 (renorm-amplified path -> full fidelity)
__device__ uint16_t g_qh[NTOK * D_MODEL], g_qm[NTOK * D_MODEL], g_ql[NTOK * D_MODEL];
// weights: w1 bf16x3 (amplified), w2 fp16x2 (un-amplified)
__device__ uint16_t g_w1h[D_MODEL * D_MODEL], g_w1m[D_MODEL * D_MODEL], g_w1l[D_MODEL * D_MODEL];
__device__ uint16_t g_w2h[D_MODEL * D_MODEL], g_w2l[D_MODEL * D_MODEL];

// ================================================================ helpers
__device__ __forceinline__ uint32_t smem_u32(const void* p) {
    uint32_t a;
    asm("{ .reg .u64 t; cvta.to.shared.u64 t, %1; cvt.u32.u64 %0, t; }" : "=r"(a) : "l"(p));
    return a;
}

#define SWZ(off) ((off) ^ (((off) >> 3) & 0x70))

__device__ __forceinline__ void ldsm_x4(uint32_t& r0, uint32_t& r1, uint32_t& r2,
                                        uint32_t& r3, uint32_t addr) {
    asm volatile("ldmatrix.sync.aligned.m8n8.x4.shared.b16 {%0,%1,%2,%3}, [%4];"
                 : "=r"(r0), "=r"(r1), "=r"(r2), "=r"(r3) : "r"(addr));
}
__device__ __forceinline__ void ldsm_x4_t(uint32_t& r0, uint32_t& r1, uint32_t& r2,
                                          uint32_t& r3, uint32_t addr) {
    asm volatile("ldmatrix.sync.aligned.m8n8.x4.trans.shared.b16 {%0,%1,%2,%3}, [%4];"
                 : "=r"(r0), "=r"(r1), "=r"(r2), "=r"(r3) : "r"(addr));
}
// bf16 mma
__device__ __forceinline__ void mma16816(float* c, uint32_t a0, uint32_t a1, uint32_t a2,
                                         uint32_t a3, uint32_t b0, uint32_t b1) {
    asm volatile(
        "mma.sync.aligned.m16n8k16.row.col.f32.bf16.bf16.f32 "
        "{%0,%1,%2,%3}, {%4,%5,%6,%7}, {%8,%9}, {%0,%1,%2,%3};"
        : "+f"(c[0]), "+f"(c[1]), "+f"(c[2]), "+f"(c[3])
        : "r"(a0), "r"(a1), "r"(a2), "r"(a3), "r"(b0), "r"(b1));
}
// fp16 mma
__device__ __forceinline__ void mmah(float* c, uint32_t a0, uint32_t a1, uint32_t a2,
                                     uint32_t a3, uint32_t b0, uint32_t b1) {
    asm volatile(
        "mma.sync.aligned.m16n8k16.row.col.f32.f16.f16.f32 "
        "{%0,%1,%2,%3}, {%4,%5,%6,%7}, {%8,%9}, {%0,%1,%2,%3};"
        : "+f"(c[0]), "+f"(c[1]), "+f"(c[2]), "+f"(c[3])
        : "r"(a0), "r"(a1), "r"(a2), "r"(a3), "r"(b0), "r"(b1));
}
#define CP_ASYNC16(dst, src) \
    asm volatile("cp.async.cg.shared.global [%0], [%1], 16;" :: "r"(dst), "l"(src))
#define CP_COMMIT() asm volatile("cp.async.commit_group;")

__device__ __forceinline__ uint32_t pack_bf2(__nv_bfloat16 lo, __nv_bfloat16 hi) {
    return ((uint32_t)__bfloat16_as_ushort(hi) << 16) | (uint32_t)__bfloat16_as_ushort(lo);
}
__device__ __forceinline__ void split3(float a, float b,
                                       uint32_t& h, uint32_t& m, uint32_t& l) {
    __nv_bfloat16 ah = __float2bfloat16(a), bh = __float2bfloat16(b);
    float ar = a - __bfloat162float(ah), br = b - __bfloat162float(bh);
    __nv_bfloat16 am = __float2bfloat16(ar), bm = __float2bfloat16(br);
    float ar2 = ar - __bfloat162float(am), br2 = br - __bfloat162float(bm);
    __nv_bfloat16 al = __float2bfloat16(ar2), bl = __float2bfloat16(br2);
    h = pack_bf2(ah, bh);
    m = pack_bf2(am, bm);
    l = pack_bf2(al, bl);
}
__device__ __forceinline__ uint32_t pack_h2(__half lo, __half hi) {
    return ((uint32_t)__half_as_ushort(hi) << 16) | (uint32_t)__half_as_ushort(lo);
}
__device__ __forceinline__ void split2(float a, float b, uint32_t& h, uint32_t& l) {
    __half ha = __float2half_rn(a), hb = __float2half_rn(b);
    __half la = __float2half_rn(a - __half2float(ha));
    __half lb = __float2half_rn(b - __half2float(hb));
    h = pack_h2(ha, hb);
    l = pack_h2(la, lb);
}
__device__ __forceinline__ void split2s(float a, uint16_t& h, uint16_t& l) {
    __half ha = __float2half_rn(a);
    __half la = __float2half_rn(a - __half2float(ha));
    h = __half_as_ushort(ha);
    l = __half_as_ushort(la);
}

// FMA-pipe exp2 (no MUFU)
__device__ __forceinline__ float fexp2(float f) {
    f = fmaxf(f, -120.0f);
    float t = f + 12582912.0f;
    int i = __float_as_int(t);
    float r = f - (t - 12582912.0f);
    float p = 1.33335581e-4f;
    p = fmaf(p, r, 1.35345402e-3f);
    p = fmaf(p, r, 9.61783718e-3f);
    p = fmaf(p, r, 5.55028137e-2f);
    p = fmaf(p, r, 2.40226507e-1f);
    p = fmaf(p, r, 6.93147181e-1f);
    p = fmaf(p, r, 1.0f);
    return __int_as_float(__float_as_int(p) + (i << 23));
}

// ---------------------------------------------------------------- zero fill
__global__ void zero_o_kernel() {
    int idx = blockIdx.x * blockDim.x + threadIdx.x;
    const int n4 = NTOK * D_MODEL / 4;
    float4 z = make_float4(0.f, 0.f, 0.f, 0.f);
    for (int i = idx; i < n4; i += gridDim.x * blockDim.x)
        ((float4*)g_o)[i] = z;
}

// ---------------------------------------------------------------- splits
__global__ __launch_bounds__(256) void split_kernel(const float* __restrict__ src,
                                                    int n4, int sel) {
    int i = blockIdx.x * blockDim.x + threadIdx.x;
    if (i >= n4) return;
    float4 v = ((const float4*)src)[i];
    uint32_t h0, m0, l0, h1, m1, l1;
    split3(v.x, v.y, h0, m0, l0);
    split3(v.z, v.w, h1, m1, l1);
    uint2* dh; uint2* dm; uint2* dl;
    if (sel == 0) { dh = (uint2*)g_ah;  dm = (uint2*)g_am;  dl = (uint2*)g_al; }
    else          { dh = (uint2*)g_w1h; dm = (uint2*)g_w1m; dl = (uint2*)g_w1l; }
    dh[i] = make_uint2(h0, h1);
    dm[i] = make_uint2(m0, m1);
    dl[i] = make_uint2(l0, l1);
}
__global__ __launch_bounds__(256) void split2_kernel(const float* __restrict__ src, int n4) {
    int i = blockIdx.x * blockDim.x + threadIdx.x;
    if (i >= n4) return;
    float4 v = ((const float4*)src)[i];
    uint32_t h0, l0, h1, l1;
    split2(v.x, v.y, h0, l0);
    split2(v.z, v.w, h1, l1);
    ((uint2*)g_w2h)[i] = make_uint2(h0, h1);
    ((uint2*)g_w2l)[i] = make_uint2(l0, l1);
}

// ================================================================ GEMM1 (bf16x3, 6 products) -> q bf16x3
#define GKC 16
#define NCH (D_MODEL / GKC)       // 48
#define G_LVL_B (128 * 48)
#define G_OP_B (3 * G_LVL_B)
#define G_STAGE (2 * G_OP_B)
#define GEMM_SMEM_B (2 * G_STAGE)

__device__ __forceinline__ void gemm_issue(int c, int buf, uint32_t sbase, int tid,
                                           int m0, int n0) {
    int k0 = c * GKC;
    uint32_t sb = sbase + buf * G_STAGE;
    int row = tid >> 1, half = tid & 1;
    const uint16_t* srcs[6] = {g_ah, g_am, g_al, g_w1h, g_w1m, g_w1l};
#pragma unroll
    for (int it = 0; it < 6; it++) {
        int grow = (it < 3 ? m0 : n0) + row;
        const uint16_t* sp = srcs[it] + (size_t)grow * D_MODEL + k0 + half * 8;
        uint32_t dst = sb + (it < 3 ? 0 : G_OP_B) + (it % 3) * G_LVL_B + row * 48 + half * 16;
        CP_ASYNC16(dst, sp);
    }
    CP_COMMIT();
}

__global__ __launch_bounds__(256, 1) void gemm_mma_kernel(const float* __restrict__ bias) {
    extern __shared__ uint8_t gsm[];
    uint32_t sbase = smem_u32(gsm);
    int tid = threadIdx.x, warp = tid >> 5, lane = tid & 31;
    int m0 = blockIdx.y * 128, n0 = blockIdx.x * 128;

    float ohi[16][4], olo[16][4];
#pragma unroll
    for (int j = 0; j < 16; j++) {
        ohi[j][0] = ohi[j][1] = ohi[j][2] = ohi[j][3] = 0.f;
        olo[j][0] = olo[j][1] = olo[j][2] = olo[j][3] = 0.f;
    }

    gemm_issue(0, 0, sbase, tid, m0, n0);

    uint32_t arow = (uint32_t)((warp * 16 + (lane & 15)) * 48 + (lane >> 4) * 16);
    uint32_t brow = (uint32_t)(((lane & 7) + ((lane >> 4) << 3)) * 48 + ((lane & 8) ? 16 : 0));

    for (int c = 0; c < NCH; c++) {
        int buf = c & 1;
        if (c + 1 < NCH) {
            gemm_issue(c + 1, buf ^ 1, sbase, tid, m0, n0);
            asm volatile("cp.async.wait_group 1;");
        } else {
            asm volatile("cp.async.wait_group 0;");
        }
        __syncthreads();

        uint32_t ab = sbase + buf * G_STAGE;
        uint32_t bb = ab + G_OP_B;
        uint32_t ah0, ah1, ah2, ah3, am0, am1, am2, am3, al0, al1, al2, al3;
        ldsm_x4(ah0, ah1, ah2, ah3, ab + 0 * G_LVL_B + arow);
        ldsm_x4(am0, am1, am2, am3, ab + 1 * G_LVL_B + arow);
        ldsm_x4(al0, al1, al2, al3, ab + 2 * G_LVL_B + arow);
#pragma unroll
        for (int np = 0; np < 8; np++) {
            uint32_t baddr = bb + (uint32_t)(np * 16 * 48) + brow;
            uint32_t bh0, bh1, bh2, bh3, bm0, bm1, bm2, bm3, bl0, bl1, bl2, bl3;
            ldsm_x4(bh0, bh1, bh2, bh3, baddr + 0 * G_LVL_B);
            ldsm_x4(bm0, bm1, bm2, bm3, baddr + 1 * G_LVL_B);
            ldsm_x4(bl0, bl1, bl2, bl3, baddr + 2 * G_LVL_B);
            mma16816(ohi[np * 2 + 0], ah0, ah1, ah2, ah3, bh0, bh1);
            mma16816(olo[np * 2 + 0], ah0, ah1, ah2, ah3, bm0, bm1);
            mma16816(olo[np * 2 + 0], am0, am1, am2, am3, bh0, bh1);
            mma16816(olo[np * 2 + 0], am0, am1, am2, am3, bm0, bm1);
            mma16816(olo[np * 2 + 0], ah0, ah1, ah2, ah3, bl0, bl1);
            mma16816(olo[np * 2 + 0], al0, al1, al2, al3, bh0, bh1);
            mma16816(ohi[np * 2 + 1], ah0, ah1, ah2, ah3, bh2, bh3);
            mma16816(olo[np * 2 + 1], ah0, ah1, ah2, ah3, bm2, bm3);
            mma16816(olo[np * 2 + 1], am0, am1, am2, am3, bh2, bh3);
            mma16816(olo[np * 2 + 1], am0, am1, am2, am3, bm2, bm3);
            mma16816(olo[np * 2 + 1], ah0, ah1, ah2, ah3, bl2, bl3);
            mma16816(olo[np * 2 + 1], al0, al1, al2, al3, bh2, bh3);
        }
        __syncthreads();
    }

    // epilogue: write q as bf16x3 splits (amplified path: full fidelity)
    int r0l = lane >> 2, c2 = (lane & 3) * 2;
    int mrow0 = m0 + warp * 16 + r0l;
    int mrow1 = mrow0 + 8;
#pragma unroll
    for (int j = 0; j < 16; j++) {
        int col = n0 + j * 8 + c2;
        float2 bv = *(const float2*)(bias + col);
        float v0 = ohi[j][0] + olo[j][0] + bv.x;
        float v1 = ohi[j][1] + olo[j][1] + bv.y;
        float v2 = ohi[j][2] + olo[j][2] + bv.x;
        float v3 = ohi[j][3] + olo[j][3] + bv.y;
        uint32_t h, m, l;
        split3(v0, v1, h, m, l);
        uint32_t i0 = (uint32_t)(mrow0 * D_MODEL + col) >> 1;
        ((uint32_t*)g_qh)[i0] = h;
        ((uint32_t*)g_qm)[i0] = m;
        ((uint32_t*)g_ql)[i0] = l;
        split3(v2, v3, h, m, l);
        uint32_t i1 = (uint32_t)(mrow1 * D_MODEL + col) >> 1;
        ((uint32_t*)g_qh)[i1] = h;
        ((uint32_t*)g_qm)[i1] = m;
        ((uint32_t*)g_ql)[i1] = l;
    }
}

// ================================================================ GEMM2 (fp16x2, 3 products) - NOT renorm-amplified
#define F_LVL_B (128 * 48)
#define F_OP_B (2 * F_LVL_B)
#define F_STAGE (2 * F_OP_B)
#define GEMM2_SMEM_B (2 * F_STAGE)

__device__ __forceinline__ void gemm2_issue(int c, int buf, uint32_t sbase, int tid,
                                            int m0, int n0) {
    int k0 = c * GKC;
    uint32_t sb = sbase + buf * F_STAGE;
    int row = tid >> 1, half = tid & 1;
    const uint16_t* srcs[4] = {g_ah, g_al, g_w2h, g_w2l};
#pragma unroll
    for (int it = 0; it < 4; it++) {
        int grow = (it < 2 ? m0 : n0) + row;
        const uint16_t* sp = srcs[it] + (size_t)grow * D_MODEL + k0 + half * 8;
        uint32_t dst = sb + (it < 2 ? 0 : F_OP_B) + (it & 1) * F_LVL_B + row * 48 + half * 16;
        CP_ASYNC16(dst, sp);
    }
    CP_COMMIT();
}

__global__ __launch_bounds__(256, 1) void gemm2_f16_kernel(const float* __restrict__ bias,
                                                           float* __restrict__ outp) {
    extern __shared__ uint8_t gsm[];
    uint32_t sbase = smem_u32(gsm);
    int tid = threadIdx.x, warp = tid >> 5, lane = tid & 31;
    int m0 = blockIdx.y * 128, n0 = blockIdx.x * 128;

    float ohi[16][4], olo[16][4];
#pragma unroll
    for (int j = 0; j < 16; j++) {
        ohi[j][0] = ohi[j][1] = ohi[j][2] = ohi[j][3] = 0.f;
        olo[j][0] = olo[j][1] = olo[j][2] = olo[j][3] = 0.f;
    }

    gemm2_issue(0, 0, sbase, tid, m0, n0);

    uint32_t arow = (uint32_t)((warp * 16 + (lane & 15)) * 48 + (lane >> 4) * 16);
    uint32_t brow = (uint32_t)(((lane & 7) + ((lane >> 4) << 3)) * 48 + ((lane & 8) ? 16 : 0));

    for (int c = 0; c < NCH; c++) {
        int buf = c & 1;
        if (c + 1 < NCH) {
            gemm2_issue(c + 1, buf ^ 1, sbase, tid, m0, n0);
            asm volatile("cp.async.wait_group 1;");
        } else {
            asm volatile("cp.async.wait_group 0;");
        }
        __syncthreads();

        uint32_t ab = sbase + buf * F_STAGE;
        uint32_t bb = ab + F_OP_B;
        uint32_t ah0, ah1, ah2, ah3, al0, al1, al2, al3;
        ldsm_x4(ah0, ah1, ah2, ah3, ab + 0 * F_LVL_B + arow);
        ldsm_x4(al0, al1, al2, al3, ab + 1 * F_LVL_B + arow);
#pragma unroll
        for (int np = 0; np < 8; np++) {
            uint32_t baddr = bb + (uint32_t)(np * 16 * 48) + brow;
            uint32_t bh0, bh1, bh2, bh3, bl0, bl1, bl2, bl3;
            ldsm_x4(bh0, bh1, bh2, bh3, baddr + 0 * F_LVL_B);
            ldsm_x4(bl0, bl1, bl2, bl3, baddr + 1 * F_LVL_B);
            mmah(ohi[np * 2 + 0], ah0, ah1, ah2, ah3, bh0, bh1);
            mmah(olo[np * 2 + 0], ah0, ah1, ah2, ah3, bl0, bl1);
            mmah(olo[np * 2 + 0], al0, al1, al2, al3, bh0, bh1);
            mmah(ohi[np * 2 + 1], ah0, ah1, ah2, ah3, bh2, bh3);
            mmah(olo[np * 2 + 1], ah0, ah1, ah2, ah3, bl2, bl3);
            mmah(olo[np * 2 + 1], al0, al1, al2, al3, bh2, bh3);
        }
        __syncthreads();
    }

    int r0l = lane >> 2, c2 = (lane & 3) * 2;
    int mrow0 = m0 + warp * 16 + r0l;
    int mrow1 = mrow0 + 8;
#pragma unroll
    for (int j = 0; j < 16; j++) {
        int col = n0 + j * 8 + c2;
        float2 bv = *(const float2*)(bias + col);
        *(float2*)(outp + (size_t)mrow0 * D_MODEL + col) =
            make_float2(ohi[j][0] + olo[j][0] + bv.x, ohi[j][1] + olo[j][1] + bv.y);
        *(float2*)(outp + (size_t)mrow1 * D_MODEL + col) =
            make_float2(ohi[j][2] + olo[j][2] + bv.x, ohi[j][3] + olo[j][3] + bv.y);
    }
}

// ================================================================ attention (bf16x3, 6 products, FIXED-MAX softmax)
#define KT_LVL 8192
#define KT_BUF (3 * KT_LVL)

// p = exp(s/8 - 16) = exp2(ssum * (0.125*log2e) + (-16*log2e))
#define P_SCL 0.18033688011111793f
#define P_OFF -23.083120654223414f

__device__ __forceinline__ void attn_stage(uint32_t dstbase, int b, int kbase,
                                           int k0, int r, int h, int tid) {
#pragma unroll
    for (int it = 0; it < 6; it++) {
        int idx = tid + it * 256;
        int lvl = idx >> 9;
        int rem = idx & 511;
        int key = rem >> 3;
        int c16 = rem & 7;
        int posk = kbase + (k0 + key) * r;
        uint32_t goff = (uint32_t)(b * SEQ + posk) * D_MODEL + h * HD + c16 * 8;
        const uint16_t* src = (lvl == 0 ? g_qh : (lvl == 1 ? g_qm : g_ql)) + goff;
        uint32_t dst = dstbase + lvl * KT_LVL + SWZ((uint32_t)(key * 128 + c16 * 16));
        CP_ASYNC16(dst, src);
    }
    CP_COMMIT();
}

__global__ __launch_bounds__(256) void attn_mma_kernel() {
    __shared__ __align__(128) uint8_t ksm[2 * KT_BUF];   // 48 KB

    int inst = blockIdx.y;
    int b, h, seg, r, off, slen;
    if (inst < 32)      { b = inst >> 4; int t = inst & 15; seg = t >> 2; h = t & 3;            r = 1; off = 0; slen = 2048; }
    else if (inst < 48) { int t = inst - 32; b = t >> 3; t &= 7; seg = t >> 2; h = 4 + (t & 3); r = 2; off = 1; slen = 4096; }
    else                { int t = inst - 48; b = t >> 2; h = 8 + (t & 3); seg = 0;              r = 4; off = 2; slen = 8192; }

    int tid = threadIdx.x;
    int warp = tid >> 5, lane = tid & 31;
    int kbase = seg * slen + off;
    int qrow0 = blockIdx.x * 128 + warp * 16;

    uint32_t smb = smem_u32(ksm);

    int r0l = lane >> 2;
    int c2 = (lane & 3) * 2;

    // -------- Q fragments (bf16x3 levels)
    int posq0 = kbase + (qrow0 + r0l) * r;
    int posq1 = kbase + (qrow0 + r0l + 8) * r;
    uint32_t qb0 = (uint32_t)(b * SEQ + posq0) * D_MODEL + h * HD;
    uint32_t qb1 = (uint32_t)(b * SEQ + posq1) * D_MODEL + h * HD;
    uint32_t qh[16], qm[16], ql[16];
#pragma unroll
    for (int kc = 0; kc < 4; kc++) {
        uint32_t i00 = (qb0 + kc * 16 + c2) >> 1;
        uint32_t i10 = (qb1 + kc * 16 + c2) >> 1;
        uint32_t i01 = (qb0 + kc * 16 + c2 + 8) >> 1;
        uint32_t i11 = (qb1 + kc * 16 + c2 + 8) >> 1;
        qh[kc * 4 + 0] = ((const uint32_t*)g_qh)[i00];
        qm[kc * 4 + 0] = ((const uint32_t*)g_qm)[i00];
        ql[kc * 4 + 0] = ((const uint32_t*)g_ql)[i00];
        qh[kc * 4 + 1] = ((const uint32_t*)g_qh)[i10];
        qm[kc * 4 + 1] = ((const uint32_t*)g_qm)[i10];
        ql[kc * 4 + 1] = ((const uint32_t*)g_ql)[i10];
        qh[kc * 4 + 2] = ((const uint32_t*)g_qh)[i01];
        qm[kc * 4 + 2] = ((const uint32_t*)g_qm)[i01];
        ql[kc * 4 + 2] = ((const uint32_t*)g_ql)[i01];
        qh[kc * 4 + 3] = ((const uint32_t*)g_qh)[i11];
        qm[kc * 4 + 3] = ((const uint32_t*)g_qm)[i11];
        ql[kc * 4 + 3] = ((const uint32_t*)g_ql)[i11];
    }

    float ohi[8][4], olo[8][4];
#pragma unroll
    for (int j = 0; j < 8; j++) {
        ohi[j][0] = ohi[j][1] = ohi[j][2] = ohi[j][3] = 0.f;
        olo[j][0] = olo[j][1] = olo[j][2] = olo[j][3] = 0.f;
    }
    float l0 = 0.f, l1 = 0.f;

    attn_stage(smb, b, kbase, 0, r, h, tid);

    int buf = 0;
    for (int kt = 0; kt < SE / 64; kt++) {
        if (kt + 1 < SE / 64) {
            attn_stage(smb + (buf ^ 1) * KT_BUF, b, kbase, (kt + 1) * 64, r, h, tid);
            asm volatile("cp.async.wait_group 1;");
        } else {
            asm volatile("cp.async.wait_group 0;");
        }
        __syncthreads();

        uint32_t kh_b = smb + buf * KT_BUF;
        uint32_t km_b = kh_b + KT_LVL;
        uint32_t kl_b = km_b + KT_LVL;

        // -------- S = Q K^T : split accumulators
        float shi[8][4], slo[8][4];
#pragma unroll
        for (int j = 0; j < 8; j++) {
            shi[j][0] = shi[j][1] = shi[j][2] = shi[j][3] = 0.f;
            slo[j][0] = slo[j][1] = slo[j][2] = slo[j][3] = 0.f;
        }
#pragma unroll
        for (int kc = 0; kc < 4; kc++) {
            uint32_t a0h = qh[kc * 4 + 0], a1h = qh[kc * 4 + 1],
                     a2h = qh[kc * 4 + 2], a3h = qh[kc * 4 + 3];
            uint32_t a0m = qm[kc * 4 + 0], a1m = qm[kc * 4 + 1],
                     a2m = qm[kc * 4 + 2], a3m = qm[kc * 4 + 3];
            uint32_t a0l = ql[kc * 4 + 0], a1l = ql[kc * 4 + 1],
                     a2l = ql[kc * 4 + 2], a3l = ql[kc * 4 + 3];
#pragma unroll
            for (int np = 0; np < 4; np++) {
                int key = np * 16 + (lane & 7) + ((lane >> 4) << 3);
                int dim = kc * 16 + (lane & 8);
                uint32_t so = SWZ((uint32_t)(key * 128 + dim * 2));
                uint32_t bh0, bh1, bh2, bh3, bm0, bm1, bm2, bm3, bl0, bl1, bl2, bl3;
                ldsm_x4(bh0, bh1, bh2, bh3, kh_b + so);
                ldsm_x4(bm0, bm1, bm2, bm3, km_b + so);
                ldsm_x4(bl0, bl1, bl2, bl3, kl_b + so);
                mma16816(shi[np * 2 + 0], a0h, a1h, a2h, a3h, bh0, bh1);
                mma16816(slo[np * 2 + 0], a0h, a1h, a2h, a3h, bm0, bm1);
                mma16816(slo[np * 2 + 0], a0m, a1m, a2m, a3m, bh0, bh1);
                mma16816(slo[np * 2 + 0], a0m, a1m, a2m, a3m, bm0, bm1);
                mma16816(slo[np * 2 + 0], a0h, a1h, a2h, a3h, bl0, bl1);
                mma16816(slo[np * 2 + 0], a0l, a1l, a2l, a3l, bh0, bh1);
                mma16816(shi[np * 2 + 1], a0h, a1h, a2h, a3h, bh2, bh3);
                mma16816(slo[np * 2 + 1], a0h, a1h, a2h, a3h, bm2, bm3);
                mma16816(slo[np * 2 + 1], a0m, a1m, a2m, a3m, bh2, bh3);
                mma16816(slo[np * 2 + 1], a0m, a1m, a2m, a3m, bm2, bm3);
                mma16816(slo[np * 2 + 1], a0h, a1h, a2h, a3h, bl2, bl3);
                mma16816(slo[np * 2 + 1], a0l, a1l, a2l, a3l, bh2, bh3);
            }
        }

        // -------- fixed-max softmax: p = exp2(ssum*P_SCL + P_OFF)
        uint32_t pah[8], pam[8], pal[8], pbh[8], pbm[8], pbl[8];
#pragma unroll
        for (int j = 0; j < 8; j++) {
            float p0 = fexp2(fmaf(shi[j][0] + slo[j][0], P_SCL, P_OFF));
            float p1 = fexp2(fmaf(shi[j][1] + slo[j][1], P_SCL, P_OFF));
            float p2 = fexp2(fmaf(shi[j][2] + slo[j][2], P_SCL, P_OFF));
            float p3 = fexp2(fmaf(shi[j][3] + slo[j][3], P_SCL, P_OFF));
            l0 += p0 + p1;
            l1 += p2 + p3;
            split3(p0, p1, pah[j], pam[j], pal[j]);
            split3(p2, p3, pbh[j], pbm[j], pbl[j]);
        }

        // -------- O += P V (V == K tile), split accumulators
#pragma unroll
        for (int kk = 0; kk < 4; kk++) {
            uint32_t a0h = pah[kk * 2], a1h = pbh[kk * 2],
                     a2h = pah[kk * 2 + 1], a3h = pbh[kk * 2 + 1];
            uint32_t a0m = pam[kk * 2], a1m = pbm[kk * 2],
                     a2m = pam[kk * 2 + 1], a3m = pbm[kk * 2 + 1];
            uint32_t a0l = pal[kk * 2], a1l = pbl[kk * 2],
                     a2l = pal[kk * 2 + 1], a3l = pbl[kk * 2 + 1];
#pragma unroll
            for (int np = 0; np < 4; np++) {
                int key = kk * 16 + (lane & 7) + (lane & 8);
                int dim = np * 16 + ((lane >> 4) << 3);
                uint32_t so = SWZ((uint32_t)(key * 128 + dim * 2));
                uint32_t bh0, bh1, bh2, bh3, bm0, bm1, bm2, bm3, bl0, bl1, bl2, bl3;
                ldsm_x4_t(bh0, bh1, bh2, bh3, kh_b + so);
                ldsm_x4_t(bm0, bm1, bm2, bm3, km_b + so);
                ldsm_x4_t(bl0, bl1, bl2, bl3, kl_b + so);
                mma16816(ohi[np * 2 + 0], a0h, a1h, a2h, a3h, bh0, bh1);
                mma16816(olo[np * 2 + 0], a0h, a1h, a2h, a3h, bm0, bm1);
                mma16816(olo[np * 2 + 0], a0m, a1m, a2m, a3m, bh0, bh1);
                mma16816(olo[np * 2 + 0], a0m, a1m, a2m, a3m, bm0, bm1);
                mma16816(olo[np * 2 + 0], a0h, a1h, a2h, a3h, bl0, bl1);
                mma16816(olo[np * 2 + 0], a0l, a1l, a2l, a3l, bh0, bh1);
                mma16816(ohi[np * 2 + 1], a0h, a1h, a2h, a3h, bh2, bh3);
                mma16816(olo[np * 2 + 1], a0h, a1h, a2h, a3h, bm2, bm3);
                mma16816(olo[np * 2 + 1], a0m, a1m, a2m, a3m, bh2, bh3);
                mma16816(olo[np * 2 + 1], a0m, a1m, a2m, a3m, bm2, bm3);
                mma16816(olo[np * 2 + 1], a0h, a1h, a2h, a3h, bl2, bl3);
                mma16816(olo[np * 2 + 1], a0l, a1l, a2l, a3l, bh2, bh3);
            }
        }
        __syncthreads();
        buf ^= 1;
    }

    // -------- finalize
    l0 += __shfl_xor_sync(0xffffffffu, l0, 1);
    l0 += __shfl_xor_sync(0xffffffffu, l0, 2);
    l1 += __shfl_xor_sync(0xffffffffu, l1, 1);
    l1 += __shfl_xor_sync(0xffffffffu, l1, 2);
    float inv0 = 1.0f / l0, inv1 = 1.0f / l1;
    float* op0 = g_o + ((size_t)b * SEQ + posq0) * D_MODEL + h * HD;
    float* op1 = g_o + ((size_t)b * SEQ + posq1) * D_MODEL + h * HD;
#pragma unroll
    for (int j = 0; j < 8; j++) {
        *(float2*)(op0 + j * 8 + c2) = make_float2((ohi[j][0] + olo[j][0]) * inv0,
                                                   (ohi[j][1] + olo[j][1]) * inv0);
        *(float2*)(op1 + j * 8 + c2) = make_float2((ohi[j][2] + olo[j][2]) * inv1,
                                                   (ohi[j][3] + olo[j][3]) * inv1);
    }
}

// ---------------------------------------------------------------- renorm sums
__global__ __launch_bounds__(256) void reduce1_kernel() {
    int bc = blockIdx.x;
    int b = bc / 3, cb = bc % 3;
    int c = cb * 256 + threadIdx.x;
    size_t base = (size_t)(b * SEQ + blockIdx.y * 256) * D_MODEL + c;
    float acc = 0.f;
    for (int rr = 0; rr < 256; rr++) acc += g_o[base + (size_t)rr * D_MODEL];
    g_part[blockIdx.y][b * D_MODEL + c] = acc;
}
__global__ void reduce2_kernel() {
    int idx = blockIdx.x * 256 + threadIdx.x;
    float acc = 0.f;
#pragma unroll
    for (int j = 0; j < 32; j++) acc += g_part[j][idx];
    g_sum[idx] = acc;
}

// ---------------------------------------------------------------- layernorm (writes fp16x2 A splits for gemm2)
__device__ __forceinline__ float blk_sum(float v, float* sh) {
    int lane = threadIdx.x & 31, w = threadIdx.x >> 5;
#pragma unroll
    for (int off = 16; off; off >>= 1) v += __shfl_xor_sync(0xffffffffu, v, off);
    if (lane == 0) sh[w] = v;
    __syncthreads();
    if (threadIdx.x == 0) {
        float t = 0.f;
#pragma unroll
        for (int i = 0; i < 8; i++) t += sh[i];
        sh[8] = t;
    }
    __syncthreads();
    return sh[8];
}

__global__ __launch_bounds__(256) void ln_kernel(const float* __restrict__ gamma,
                                                 const float* __restrict__ beta) {
    __shared__ float sh[9];
    int row = blockIdx.x;
    int b = row >> 13;
    const float* in = g_o + (size_t)row * D_MODEL;
    float v[3];
    float s = 0.f;
#pragma unroll
    for (int i = 0; i < 3; i++) {
        int c = threadIdx.x + i * 256;
        float val = in[c] / (3.0f * g_sum[b * D_MODEL + c]);
        v[i] = val;
        s += val;
    }
    float mean = blk_sum(s, sh) * (1.0f / 768.0f);
    float vs = 0.f;
#pragma unroll
    for (int i = 0; i < 3; i++) {
        float d = v[i] - mean;
        vs += d * d;
    }
    float var = blk_sum(vs, sh) * (1.0f / 768.0f);
    float rstd = rsqrtf(var + 1e-5f);
#pragma unroll
    for (int i = 0; i < 3; i++) {
        int c = threadIdx.x + i * 256;
        float outv = (v[i] - mean) * rstd * gamma[c] + beta[c];
        uint16_t hh, ll;
        split2s(outv, hh, ll);
        size_t idx = (size_t)row * D_MODEL + c;
        g_ah[idx] = hh;
        g_al[idx] = ll;
    }
}

// ---------------------------------------------------------------- launch
extern "C" void kernel_launch(void* const* d_in, const int* in_sizes, int n_in,
                              void* d_out, int out_size) {
    const float* x      = (const float*)d_in[0];
    const float* w_in   = (const float*)d_in[1];
    const float* b_in   = (const float*)d_in[2];
    const float* w_out  = (const float*)d_in[3];
    const float* b_out  = (const float*)d_in[4];
    const float* gamma  = (const float*)d_in[5];
    const float* beta   = (const float*)d_in[6];
    float* out = (float*)d_out;

    cudaFuncSetAttribute(gemm_mma_kernel, cudaFuncAttributeMaxDynamicSharedMemorySize,
                         GEMM_SMEM_B);
    cudaFuncSetAttribute(gemm2_f16_kernel, cudaFuncAttributeMaxDynamicSharedMemorySize,
                         GEMM2_SMEM_B);

    const int nbig4 = NTOK * D_MODEL / 4;
    const int nw4 = D_MODEL * D_MODEL / 4;

    zero_o_kernel<<<3072, 256>>>();
    split_kernel<<<(nbig4 + 255) / 256, 256>>>(x, nbig4, 0);
    split_kernel<<<(nw4 + 255) / 256, 256>>>(w_in, nw4, 1);
    split2_kernel<<<(nw4 + 255) / 256, 256>>>(w_out, nw4);
    gemm_mma_kernel<<<dim3(6, 128), 256, GEMM_SMEM_B>>>(b_in);
    attn_mma_kernel<<<dim3(16, 56), 256>>>();
    reduce1_kernel<<<dim3(6, 32), 256>>>();
    reduce2_kernel<<<6, 256>>>();
    ln_kernel<<<NTOK, 256>>>(gamma, beta);
    gemm2_f16_kernel<<<dim3(6, 128), 256, GEMM2_SMEM_B>>>(b_out, out);
}

// round 10
// speedup vs baseline: 1.6972x; 1.0669x over previous
#include <cuda_runtime.h>
#include <cuda_bf16.h>
#include <cuda_fp16.h>
#include <stdint.h>
#include <math.h>

#define D_MODEL 768
#define NHEADS 12
#define HD 64
#define BATCH 2
#define SEQ 8192
#define NTOK (BATCH * SEQ)
#define SE 2048
#define LOG2E 1.4426950408889634f

// Scratch (allocation-free rule: __device__ globals)
__device__ float g_o[NTOK * D_MODEL];
__device__ float g_part[32][BATCH * D_MODEL];
__device__ float g_sum[BATCH * D_MODEL];
// g_a*: bf16x3 of x for gemm1; later fp16x2 of ln-out for gemm2 (g_am unused then)
__device__ uint16_t g_ah[NTOK * D_MODEL], g_am[NTOK * D_MODEL], g_al[NTOK * D_MODEL];
// projected q: bf16x3 (V side of PV; renorm-amplified path)
__device__ uint16_t g_qh[NTOK * D_MODEL], g_qm[NTOK * D_MODEL], g_ql[NTOK * D_MODEL];
// projected q: fp16x2 (QK side)
__device__ uint16_t g_fh[NTOK * D_MODEL], g_fl[NTOK * D_MODEL];
// weights: w1 bf16x3 (amplified), w2 fp16x2 (un-amplified)
__device__ uint16_t g_w1h[D_MODEL * D_MODEL], g_w1m[D_MODEL * D_MODEL], g_w1l[D_MODEL * D_MODEL];
__device__ uint16_t g_w2h[D_MODEL * D_MODEL], g_w2l[D_MODEL * D_MODEL];

// ================================================================ helpers
__device__ __forceinline__ uint32_t smem_u32(const void* p) {
    uint32_t a;
    asm("{ .reg .u64 t; cvta.to.shared.u64 t, %1; cvt.u32.u64 %0, t; }" : "=r"(a) : "l"(p));
    return a;
}

#define SWZ(off) ((off) ^ (((off) >> 3) & 0x70))

__device__ __forceinline__ void ldsm_x4(uint32_t& r0, uint32_t& r1, uint32_t& r2,
                                        uint32_t& r3, uint32_t addr) {
    asm volatile("ldmatrix.sync.aligned.m8n8.x4.shared.b16 {%0,%1,%2,%3}, [%4];"
                 : "=r"(r0), "=r"(r1), "=r"(r2), "=r"(r3) : "r"(addr));
}
__device__ __forceinline__ void ldsm_x4_t(uint32_t& r0, uint32_t& r1, uint32_t& r2,
                                          uint32_t& r3, uint32_t addr) {
    asm volatile("ldmatrix.sync.aligned.m8n8.x4.trans.shared.b16 {%0,%1,%2,%3}, [%4];"
                 : "=r"(r0), "=r"(r1), "=r"(r2), "=r"(r3) : "r"(addr));
}
// bf16 mma
__device__ __forceinline__ void mma16816(float* c, uint32_t a0, uint32_t a1, uint32_t a2,
                                         uint32_t a3, uint32_t b0, uint32_t b1) {
    asm volatile(
        "mma.sync.aligned.m16n8k16.row.col.f32.bf16.bf16.f32 "
        "{%0,%1,%2,%3}, {%4,%5,%6,%7}, {%8,%9}, {%0,%1,%2,%3};"
        : "+f"(c[0]), "+f"(c[1]), "+f"(c[2]), "+f"(c[3])
        : "r"(a0), "r"(a1), "r"(a2), "r"(a3), "r"(b0), "r"(b1));
}
// fp16 mma
__device__ __forceinline__ void mmah(float* c, uint32_t a0, uint32_t a1, uint32_t a2,
                                     uint32_t a3, uint32_t b0, uint32_t b1) {
    asm volatile(
        "mma.sync.aligned.m16n8k16.row.col.f32.f16.f16.f32 "
        "{%0,%1,%2,%3}, {%4,%5,%6,%7}, {%8,%9}, {%0,%1,%2,%3};"
        : "+f"(c[0]), "+f"(c[1]), "+f"(c[2]), "+f"(c[3])
        : "r"(a0), "r"(a1), "r"(a2), "r"(a3), "r"(b0), "r"(b1));
}
#define CP_ASYNC16(dst, src) \
    asm volatile("cp.async.cg.shared.global [%0], [%1], 16;" :: "r"(dst), "l"(src))
#define CP_COMMIT() asm volatile("cp.async.commit_group;")

__device__ __forceinline__ uint32_t pack_bf2(__nv_bfloat16 lo, __nv_bfloat16 hi) {
    return ((uint32_t)__bfloat16_as_ushort(hi) << 16) | (uint32_t)__bfloat16_as_ushort(lo);
}
__device__ __forceinline__ void split3(float a, float b,
                                       uint32_t& h, uint32_t& m, uint32_t& l) {
    __nv_bfloat16 ah = __float2bfloat16(a), bh = __float2bfloat16(b);
    float ar = a - __bfloat162float(ah), br = b - __bfloat162float(bh);
    __nv_bfloat16 am = __float2bfloat16(ar), bm = __float2bfloat16(br);
    float ar2 = ar - __bfloat162float(am), br2 = br - __bfloat162float(bm);
    __nv_bfloat16 al = __float2bfloat16(ar2), bl = __float2bfloat16(br2);
    h = pack_bf2(ah, bh);
    m = pack_bf2(am, bm);
    l = pack_bf2(al, bl);
}
__device__ __forceinline__ uint32_t pack_h2(__half lo, __half hi) {
    return ((uint32_t)__half_as_ushort(hi) << 16) | (uint32_t)__half_as_ushort(lo);
}
__device__ __forceinline__ void split2(float a, float b, uint32_t& h, uint32_t& l) {
    __half ha = __float2half_rn(a), hb = __float2half_rn(b);
    __half la = __float2half_rn(a - __half2float(ha));
    __half lb = __float2half_rn(b - __half2float(hb));
    h = pack_h2(ha, hb);
    l = pack_h2(la, lb);
}
__device__ __forceinline__ void split2s(float a, uint16_t& h, uint16_t& l) {
    __half ha = __float2half_rn(a);
    __half la = __float2half_rn(a - __half2float(ha));
    h = __half_as_ushort(ha);
    l = __half_as_ushort(la);
}

// FMA-pipe exp2 (no MUFU)
__device__ __forceinline__ float fexp2(float f) {
    f = fmaxf(f, -120.0f);
    float t = f + 12582912.0f;
    int i = __float_as_int(t);
    float r = f - (t - 12582912.0f);
    float p = 1.33335581e-4f;
    p = fmaf(p, r, 1.35345402e-3f);
    p = fmaf(p, r, 9.61783718e-3f);
    p = fmaf(p, r, 5.55028137e-2f);
    p = fmaf(p, r, 2.40226507e-1f);
    p = fmaf(p, r, 6.93147181e-1f);
    p = fmaf(p, r, 1.0f);
    return __int_as_float(__float_as_int(p) + (i << 23));
}

// ---------------------------------------------------------------- zero fill
__global__ void zero_o_kernel() {
    int idx = blockIdx.x * blockDim.x + threadIdx.x;
    const int n4 = NTOK * D_MODEL / 4;
    float4 z = make_float4(0.f, 0.f, 0.f, 0.f);
    for (int i = idx; i < n4; i += gridDim.x * blockDim.x)
        ((float4*)g_o)[i] = z;
}

// ---------------------------------------------------------------- splits
__global__ __launch_bounds__(256) void split_kernel(const float* __restrict__ src,
                                                    int n4, int sel) {
    int i = blockIdx.x * blockDim.x + threadIdx.x;
    if (i >= n4) return;
    float4 v = ((const float4*)src)[i];
    uint32_t h0, m0, l0, h1, m1, l1;
    split3(v.x, v.y, h0, m0, l0);
    split3(v.z, v.w, h1, m1, l1);
    uint2* dh; uint2* dm; uint2* dl;
    if (sel == 0) { dh = (uint2*)g_ah;  dm = (uint2*)g_am;  dl = (uint2*)g_al; }
    else          { dh = (uint2*)g_w1h; dm = (uint2*)g_w1m; dl = (uint2*)g_w1l; }
    dh[i] = make_uint2(h0, h1);
    dm[i] = make_uint2(m0, m1);
    dl[i] = make_uint2(l0, l1);
}
__global__ __launch_bounds__(256) void split2_kernel(const float* __restrict__ src, int n4) {
    int i = blockIdx.x * blockDim.x + threadIdx.x;
    if (i >= n4) return;
    float4 v = ((const float4*)src)[i];
    uint32_t h0, l0, h1, l1;
    split2(v.x, v.y, h0, l0);
    split2(v.z, v.w, h1, l1);
    ((uint2*)g_w2h)[i] = make_uint2(h0, h1);
    ((uint2*)g_w2l)[i] = make_uint2(l0, l1);
}

// ================================================================ GEMM1 (bf16x3, 6 products) -> q bf16x3 + fp16x2
#define GKC 16
#define NCH (D_MODEL / GKC)       // 48
#define G_LVL_B (128 * 48)
#define G_OP_B (3 * G_LVL_B)
#define G_STAGE (2 * G_OP_B)
#define GEMM_SMEM_B (2 * G_STAGE)

__device__ __forceinline__ void gemm_issue(int c, int buf, uint32_t sbase, int tid,
                                           int m0, int n0) {
    int k0 = c * GKC;
    uint32_t sb = sbase + buf * G_STAGE;
    int row = tid >> 1, half = tid & 1;
    const uint16_t* srcs[6] = {g_ah, g_am, g_al, g_w1h, g_w1m, g_w1l};
#pragma unroll
    for (int it = 0; it < 6; it++) {
        int grow = (it < 3 ? m0 : n0) + row;
        const uint16_t* sp = srcs[it] + (size_t)grow * D_MODEL + k0 + half * 8;
        uint32_t dst = sb + (it < 3 ? 0 : G_OP_B) + (it % 3) * G_LVL_B + row * 48 + half * 16;
        CP_ASYNC16(dst, sp);
    }
    CP_COMMIT();
}

__global__ __launch_bounds__(256, 1) void gemm_mma_kernel(const float* __restrict__ bias) {
    extern __shared__ uint8_t gsm[];
    uint32_t sbase = smem_u32(gsm);
    int tid = threadIdx.x, warp = tid >> 5, lane = tid & 31;
    int m0 = blockIdx.y * 128, n0 = blockIdx.x * 128;

    float ohi[16][4], olo[16][4];
#pragma unroll
    for (int j = 0; j < 16; j++) {
        ohi[j][0] = ohi[j][1] = ohi[j][2] = ohi[j][3] = 0.f;
        olo[j][0] = olo[j][1] = olo[j][2] = olo[j][3] = 0.f;
    }

    gemm_issue(0, 0, sbase, tid, m0, n0);

    uint32_t arow = (uint32_t)((warp * 16 + (lane & 15)) * 48 + (lane >> 4) * 16);
    uint32_t brow = (uint32_t)(((lane & 7) + ((lane >> 4) << 3)) * 48 + ((lane & 8) ? 16 : 0));

    for (int c = 0; c < NCH; c++) {
        int buf = c & 1;
        if (c + 1 < NCH) {
            gemm_issue(c + 1, buf ^ 1, sbase, tid, m0, n0);
            asm volatile("cp.async.wait_group 1;");
        } else {
            asm volatile("cp.async.wait_group 0;");
        }
        __syncthreads();

        uint32_t ab = sbase + buf * G_STAGE;
        uint32_t bb = ab + G_OP_B;
        uint32_t ah0, ah1, ah2, ah3, am0, am1, am2, am3, al0, al1, al2, al3;
        ldsm_x4(ah0, ah1, ah2, ah3, ab + 0 * G_LVL_B + arow);
        ldsm_x4(am0, am1, am2, am3, ab + 1 * G_LVL_B + arow);
        ldsm_x4(al0, al1, al2, al3, ab + 2 * G_LVL_B + arow);
#pragma unroll
        for (int np = 0; np < 8; np++) {
            uint32_t baddr = bb + (uint32_t)(np * 16 * 48) + brow;
            uint32_t bh0, bh1, bh2, bh3, bm0, bm1, bm2, bm3, bl0, bl1, bl2, bl3;
            ldsm_x4(bh0, bh1, bh2, bh3, baddr + 0 * G_LVL_B);
            ldsm_x4(bm0, bm1, bm2, bm3, baddr + 1 * G_LVL_B);
            ldsm_x4(bl0, bl1, bl2, bl3, baddr + 2 * G_LVL_B);
            mma16816(ohi[np * 2 + 0], ah0, ah1, ah2, ah3, bh0, bh1);
            mma16816(olo[np * 2 + 0], ah0, ah1, ah2, ah3, bm0, bm1);
            mma16816(olo[np * 2 + 0], am0, am1, am2, am3, bh0, bh1);
            mma16816(olo[np * 2 + 0], am0, am1, am2, am3, bm0, bm1);
            mma16816(olo[np * 2 + 0], ah0, ah1, ah2, ah3, bl0, bl1);
            mma16816(olo[np * 2 + 0], al0, al1, al2, al3, bh0, bh1);
            mma16816(ohi[np * 2 + 1], ah0, ah1, ah2, ah3, bh2, bh3);
            mma16816(olo[np * 2 + 1], ah0, ah1, ah2, ah3, bm2, bm3);
            mma16816(olo[np * 2 + 1], am0, am1, am2, am3, bh2, bh3);
            mma16816(olo[np * 2 + 1], am0, am1, am2, am3, bm2, bm3);
            mma16816(olo[np * 2 + 1], ah0, ah1, ah2, ah3, bl2, bl3);
            mma16816(olo[np * 2 + 1], al0, al1, al2, al3, bh2, bh3);
        }
        __syncthreads();
    }

    // epilogue: write q as bf16x3 (PV/V side) AND fp16x2 (QK side)
    int r0l = lane >> 2, c2 = (lane & 3) * 2;
    int mrow0 = m0 + warp * 16 + r0l;
    int mrow1 = mrow0 + 8;
#pragma unroll
    for (int j = 0; j < 16; j++) {
        int col = n0 + j * 8 + c2;
        float2 bv = *(const float2*)(bias + col);
        float v0 = ohi[j][0] + olo[j][0] + bv.x;
        float v1 = ohi[j][1] + olo[j][1] + bv.y;
        float v2 = ohi[j][2] + olo[j][2] + bv.x;
        float v3 = ohi[j][3] + olo[j][3] + bv.y;
        uint32_t h, m, l;
        uint32_t fh, fl;
        split3(v0, v1, h, m, l);
        split2(v0, v1, fh, fl);
        uint32_t i0 = (uint32_t)(mrow0 * D_MODEL + col) >> 1;
        ((uint32_t*)g_qh)[i0] = h;
        ((uint32_t*)g_qm)[i0] = m;
        ((uint32_t*)g_ql)[i0] = l;
        ((uint32_t*)g_fh)[i0] = fh;
        ((uint32_t*)g_fl)[i0] = fl;
        split3(v2, v3, h, m, l);
        split2(v2, v3, fh, fl);
        uint32_t i1 = (uint32_t)(mrow1 * D_MODEL + col) >> 1;
        ((uint32_t*)g_qh)[i1] = h;
        ((uint32_t*)g_qm)[i1] = m;
        ((uint32_t*)g_ql)[i1] = l;
        ((uint32_t*)g_fh)[i1] = fh;
        ((uint32_t*)g_fl)[i1] = fl;
    }
}

// ================================================================ GEMM2 (fp16x2, 3 products)
#define F_LVL_B (128 * 48)
#define F_OP_B (2 * F_LVL_B)
#define F_STAGE (2 * F_OP_B)
#define GEMM2_SMEM_B (2 * F_STAGE)

__device__ __forceinline__ void gemm2_issue(int c, int buf, uint32_t sbase, int tid,
                                            int m0, int n0) {
    int k0 = c * GKC;
    uint32_t sb = sbase + buf * F_STAGE;
    int row = tid >> 1, half = tid & 1;
    const uint16_t* srcs[4] = {g_ah, g_al, g_w2h, g_w2l};
#pragma unroll
    for (int it = 0; it < 4; it++) {
        int grow = (it < 2 ? m0 : n0) + row;
        const uint16_t* sp = srcs[it] + (size_t)grow * D_MODEL + k0 + half * 8;
        uint32_t dst = sb + (it < 2 ? 0 : F_OP_B) + (it & 1) * F_LVL_B + row * 48 + half * 16;
        CP_ASYNC16(dst, sp);
    }
    CP_COMMIT();
}

__global__ __launch_bounds__(256, 1) void gemm2_f16_kernel(const float* __restrict__ bias,
                                                           float* __restrict__ outp) {
    extern __shared__ uint8_t gsm[];
    uint32_t sbase = smem_u32(gsm);
    int tid = threadIdx.x, warp = tid >> 5, lane = tid & 31;
    int m0 = blockIdx.y * 128, n0 = blockIdx.x * 128;

    float ohi[16][4], olo[16][4];
#pragma unroll
    for (int j = 0; j < 16; j++) {
        ohi[j][0] = ohi[j][1] = ohi[j][2] = ohi[j][3] = 0.f;
        olo[j][0] = olo[j][1] = olo[j][2] = olo[j][3] = 0.f;
    }

    gemm2_issue(0, 0, sbase, tid, m0, n0);

    uint32_t arow = (uint32_t)((warp * 16 + (lane & 15)) * 48 + (lane >> 4) * 16);
    uint32_t brow = (uint32_t)(((lane & 7) + ((lane >> 4) << 3)) * 48 + ((lane & 8) ? 16 : 0));

    for (int c = 0; c < NCH; c++) {
        int buf = c & 1;
        if (c + 1 < NCH) {
            gemm2_issue(c + 1, buf ^ 1, sbase, tid, m0, n0);
            asm volatile("cp.async.wait_group 1;");
        } else {
            asm volatile("cp.async.wait_group 0;");
        }
        __syncthreads();

        uint32_t ab = sbase + buf * F_STAGE;
        uint32_t bb = ab + F_OP_B;
        uint32_t ah0, ah1, ah2, ah3, al0, al1, al2, al3;
        ldsm_x4(ah0, ah1, ah2, ah3, ab + 0 * F_LVL_B + arow);
        ldsm_x4(al0, al1, al2, al3, ab + 1 * F_LVL_B + arow);
#pragma unroll
        for (int np = 0; np < 8; np++) {
            uint32_t baddr = bb + (uint32_t)(np * 16 * 48) + brow;
            uint32_t bh0, bh1, bh2, bh3, bl0, bl1, bl2, bl3;
            ldsm_x4(bh0, bh1, bh2, bh3, baddr + 0 * F_LVL_B);
            ldsm_x4(bl0, bl1, bl2, bl3, baddr + 1 * F_LVL_B);
            mmah(ohi[np * 2 + 0], ah0, ah1, ah2, ah3, bh0, bh1);
            mmah(olo[np * 2 + 0], ah0, ah1, ah2, ah3, bl0, bl1);
            mmah(olo[np * 2 + 0], al0, al1, al2, al3, bh0, bh1);
            mmah(ohi[np * 2 + 1], ah0, ah1, ah2, ah3, bh2, bh3);
            mmah(olo[np * 2 + 1], ah0, ah1, ah2, ah3, bl2, bl3);
            mmah(olo[np * 2 + 1], al0, al1, al2, al3, bh2, bh3);
        }
        __syncthreads();
    }

    int r0l = lane >> 2, c2 = (lane & 3) * 2;
    int mrow0 = m0 + warp * 16 + r0l;
    int mrow1 = mrow0 + 8;
#pragma unroll
    for (int j = 0; j < 16; j++) {
        int col = n0 + j * 8 + c2;
        float2 bv = *(const float2*)(bias + col);
        *(float2*)(outp + (size_t)mrow0 * D_MODEL + col) =
            make_float2(ohi[j][0] + olo[j][0] + bv.x, ohi[j][1] + olo[j][1] + bv.y);
        *(float2*)(outp + (size_t)mrow1 * D_MODEL + col) =
            make_float2(ohi[j][2] + olo[j][2] + bv.x, ohi[j][3] + olo[j][3] + bv.y);
    }
}

// ================================================================ attention
// QK: fp16x2 (3 products). PV: bf16x3 (6 products). Fixed-max softmax.
#define KT_LVL 8192
#define KT_BUF (5 * KT_LVL)     // 2 fp16 levels + 3 bf16 levels = 40960 B
#define ATTN_SMEM (2 * KT_BUF)  // 81920 B

#define P_SCL 0.18033688011111793f
#define P_OFF -23.083120654223414f

__device__ __forceinline__ void attn_stage(uint32_t dstbase, int b, int kbase,
                                           int k0, int r, int h, int tid) {
#pragma unroll
    for (int it = 0; it < 10; it++) {
        int idx = tid + it * 256;          // 0..2559
        int lvl = idx >> 9;                // 0..4
        int rem = idx & 511;
        int key = rem >> 3;
        int c16 = rem & 7;
        int posk = kbase + (k0 + key) * r;
        uint32_t goff = (uint32_t)(b * SEQ + posk) * D_MODEL + h * HD + c16 * 8;
        const uint16_t* src;
        switch (lvl) {
            case 0: src = g_fh + goff; break;
            case 1: src = g_fl + goff; break;
            case 2: src = g_qh + goff; break;
            case 3: src = g_qm + goff; break;
            default: src = g_ql + goff; break;
        }
        uint32_t dst = dstbase + lvl * KT_LVL + SWZ((uint32_t)(key * 128 + c16 * 16));
        CP_ASYNC16(dst, src);
    }
    CP_COMMIT();
}

__global__ __launch_bounds__(256, 1) void attn_mma_kernel() {
    extern __shared__ uint8_t ksm[];

    int inst = blockIdx.y;
    int b, h, seg, r, off, slen;
    if (inst < 32)      { b = inst >> 4; int t = inst & 15; seg = t >> 2; h = t & 3;            r = 1; off = 0; slen = 2048; }
    else if (inst < 48) { int t = inst - 32; b = t >> 3; t &= 7; seg = t >> 2; h = 4 + (t & 3); r = 2; off = 1; slen = 4096; }
    else                { int t = inst - 48; b = t >> 2; h = 8 + (t & 3); seg = 0;              r = 4; off = 2; slen = 8192; }

    int tid = threadIdx.x;
    int warp = tid >> 5, lane = tid & 31;
    int kbase = seg * slen + off;
    int qrow0 = blockIdx.x * 128 + warp * 16;

    uint32_t smb = smem_u32(ksm);

    int r0l = lane >> 2;
    int c2 = (lane & 3) * 2;

    // -------- Q fragments (fp16x2 levels)
    int posq0 = kbase + (qrow0 + r0l) * r;
    int posq1 = kbase + (qrow0 + r0l + 8) * r;
    uint32_t qb0 = (uint32_t)(b * SEQ + posq0) * D_MODEL + h * HD;
    uint32_t qb1 = (uint32_t)(b * SEQ + posq1) * D_MODEL + h * HD;
    uint32_t qh[16], ql[16];
#pragma unroll
    for (int kc = 0; kc < 4; kc++) {
        uint32_t i00 = (qb0 + kc * 16 + c2) >> 1;
        uint32_t i10 = (qb1 + kc * 16 + c2) >> 1;
        uint32_t i01 = (qb0 + kc * 16 + c2 + 8) >> 1;
        uint32_t i11 = (qb1 + kc * 16 + c2 + 8) >> 1;
        qh[kc * 4 + 0] = ((const uint32_t*)g_fh)[i00];
        ql[kc * 4 + 0] = ((const uint32_t*)g_fl)[i00];
        qh[kc * 4 + 1] = ((const uint32_t*)g_fh)[i10];
        ql[kc * 4 + 1] = ((const uint32_t*)g_fl)[i10];
        qh[kc * 4 + 2] = ((const uint32_t*)g_fh)[i01];
        ql[kc * 4 + 2] = ((const uint32_t*)g_fl)[i01];
        qh[kc * 4 + 3] = ((const uint32_t*)g_fh)[i11];
        ql[kc * 4 + 3] = ((const uint32_t*)g_fl)[i11];
    }

    float ohi[8][4], olo[8][4];
#pragma unroll
    for (int j = 0; j < 8; j++) {
        ohi[j][0] = ohi[j][1] = ohi[j][2] = ohi[j][3] = 0.f;
        olo[j][0] = olo[j][1] = olo[j][2] = olo[j][3] = 0.f;
    }
    float l0 = 0.f, l1 = 0.f;

    attn_stage(smb, b, kbase, 0, r, h, tid);

    int buf = 0;
    for (int kt = 0; kt < SE / 64; kt++) {
        if (kt + 1 < SE / 64) {
            attn_stage(smb + (buf ^ 1) * KT_BUF, b, kbase, (kt + 1) * 64, r, h, tid);
            asm volatile("cp.async.wait_group 1;");
        } else {
            asm volatile("cp.async.wait_group 0;");
        }
        __syncthreads();

        uint32_t kh_b = smb + buf * KT_BUF;          // fp16 h
        uint32_t kl_b = kh_b + KT_LVL;               // fp16 l
        uint32_t vh_b = kh_b + 2 * KT_LVL;           // bf16 h
        uint32_t vm_b = kh_b + 3 * KT_LVL;           // bf16 m
        uint32_t vl_b = kh_b + 4 * KT_LVL;           // bf16 l

        // -------- S = Q K^T : fp16x2, split accumulators (hh -> hi ; hl, lh -> lo)
        float shi[8][4], slo[8][4];
#pragma unroll
        for (int j = 0; j < 8; j++) {
            shi[j][0] = shi[j][1] = shi[j][2] = shi[j][3] = 0.f;
            slo[j][0] = slo[j][1] = slo[j][2] = slo[j][3] = 0.f;
        }
#pragma unroll
        for (int kc = 0; kc < 4; kc++) {
            uint32_t a0h = qh[kc * 4 + 0], a1h = qh[kc * 4 + 1],
                     a2h = qh[kc * 4 + 2], a3h = qh[kc * 4 + 3];
            uint32_t a0l = ql[kc * 4 + 0], a1l = ql[kc * 4 + 1],
                     a2l = ql[kc * 4 + 2], a3l = ql[kc * 4 + 3];
#pragma unroll
            for (int np = 0; np < 4; np++) {
                int key = np * 16 + (lane & 7) + ((lane >> 4) << 3);
                int dim = kc * 16 + (lane & 8);
                uint32_t so = SWZ((uint32_t)(key * 128 + dim * 2));
                uint32_t bh0, bh1, bh2, bh3, bl0, bl1, bl2, bl3;
                ldsm_x4(bh0, bh1, bh2, bh3, kh_b + so);
                ldsm_x4(bl0, bl1, bl2, bl3, kl_b + so);
                mmah(shi[np * 2 + 0], a0h, a1h, a2h, a3h, bh0, bh1);
                mmah(slo[np * 2 + 0], a0h, a1h, a2h, a3h, bl0, bl1);
                mmah(slo[np * 2 + 0], a0l, a1l, a2l, a3l, bh0, bh1);
                mmah(shi[np * 2 + 1], a0h, a1h, a2h, a3h, bh2, bh3);
                mmah(slo[np * 2 + 1], a0h, a1h, a2h, a3h, bl2, bl3);
                mmah(slo[np * 2 + 1], a0l, a1l, a2l, a3l, bh2, bh3);
            }
        }

        // -------- fixed-max softmax: p = exp2(ssum*P_SCL + P_OFF), bf16x3 split
        uint32_t pah[8], pam[8], pal[8], pbh[8], pbm[8], pbl[8];
#pragma unroll
        for (int j = 0; j < 8; j++) {
            float p0 = fexp2(fmaf(shi[j][0] + slo[j][0], P_SCL, P_OFF));
            float p1 = fexp2(fmaf(shi[j][1] + slo[j][1], P_SCL, P_OFF));
            float p2 = fexp2(fmaf(shi[j][2] + slo[j][2], P_SCL, P_OFF));
            float p3 = fexp2(fmaf(shi[j][3] + slo[j][3], P_SCL, P_OFF));
            l0 += p0 + p1;
            l1 += p2 + p3;
            split3(p0, p1, pah[j], pam[j], pal[j]);
            split3(p2, p3, pbh[j], pbm[j], pbl[j]);
        }

        // -------- O += P V : bf16x3, split accumulators
#pragma unroll
        for (int kk = 0; kk < 4; kk++) {
            uint32_t a0h = pah[kk * 2], a1h = pbh[kk * 2],
                     a2h = pah[kk * 2 + 1], a3h = pbh[kk * 2 + 1];
            uint32_t a0m = pam[kk * 2], a1m = pbm[kk * 2],
                     a2m = pam[kk * 2 + 1], a3m = pbm[kk * 2 + 1];
            uint32_t a0l = pal[kk * 2], a1l = pbl[kk * 2],
                     a2l = pal[kk * 2 + 1], a3l = pbl[kk * 2 + 1];
#pragma unroll
            for (int np = 0; np < 4; np++) {
                int key = kk * 16 + (lane & 7) + (lane & 8);
                int dim = np * 16 + ((lane >> 4) << 3);
                uint32_t so = SWZ((uint32_t)(key * 128 + dim * 2));
                uint32_t bh0, bh1, bh2, bh3, bm0, bm1, bm2, bm3, bl0, bl1, bl2, bl3;
                ldsm_x4_t(bh0, bh1, bh2, bh3, vh_b + so);
                ldsm_x4_t(bm0, bm1, bm2, bm3, vm_b + so);
                ldsm_x4_t(bl0, bl1, bl2, bl3, vl_b + so);
                mma16816(ohi[np * 2 + 0], a0h, a1h, a2h, a3h, bh0, bh1);
                mma16816(olo[np * 2 + 0], a0h, a1h, a2h, a3h, bm0, bm1);
                mma16816(olo[np * 2 + 0], a0m, a1m, a2m, a3m, bh0, bh1);
                mma16816(olo[np * 2 + 0], a0m, a1m, a2m, a3m, bm0, bm1);
                mma16816(olo[np * 2 + 0], a0h, a1h, a2h, a3h, bl0, bl1);
                mma16816(olo[np * 2 + 0], a0l, a1l, a2l, a3l, bh0, bh1);
                mma16816(ohi[np * 2 + 1], a0h, a1h, a2h, a3h, bh2, bh3);
                mma16816(olo[np * 2 + 1], a0h, a1h, a2h, a3h, bm2, bm3);
                mma16816(olo[np * 2 + 1], a0m, a1m, a2m, a3m, bh2, bh3);
                mma16816(olo[np * 2 + 1], a0m, a1m, a2m, a3m, bm2, bm3);
                mma16816(olo[np * 2 + 1], a0h, a1h, a2h, a3h, bl2, bl3);
                mma16816(olo[np * 2 + 1], a0l, a1l, a2l, a3l, bh2, bh3);
            }
        }
        __syncthreads();
        buf ^= 1;
    }

    // -------- finalize
    l0 += __shfl_xor_sync(0xffffffffu, l0, 1);
    l0 += __shfl_xor_sync(0xffffffffu, l0, 2);
    l1 += __shfl_xor_sync(0xffffffffu, l1, 1);
    l1 += __shfl_xor_sync(0xffffffffu, l1, 2);
    float inv0 = 1.0f / l0, inv1 = 1.0f / l1;
    float* op0 = g_o + ((size_t)b * SEQ + posq0) * D_MODEL + h * HD;
    float* op1 = g_o + ((size_t)b * SEQ + posq1) * D_MODEL + h * HD;
#pragma unroll
    for (int j = 0; j < 8; j++) {
        *(float2*)(op0 + j * 8 + c2) = make_float2((ohi[j][0] + olo[j][0]) * inv0,
                                                   (ohi[j][1] + olo[j][1]) * inv0);
        *(float2*)(op1 + j * 8 + c2) = make_float2((ohi[j][2] + olo[j][2]) * inv1,
                                                   (ohi[j][3] + olo[j][3]) * inv1);
    }
}

// ---------------------------------------------------------------- renorm sums
__global__ __launch_bounds__(256) void reduce1_kernel() {
    int bc = blockIdx.x;
    int b = bc / 3, cb = bc % 3;
    int c = cb * 256 + threadIdx.x;
    size_t base = (size_t)(b * SEQ + blockIdx.y * 256) * D_MODEL + c;
    float acc = 0.f;
    for (int rr = 0; rr < 256; rr++) acc += g_o[base + (size_t)rr * D_MODEL];
    g_part[blockIdx.y][b * D_MODEL + c] = acc;
}
__global__ void reduce2_kernel() {
    int idx = blockIdx.x * 256 + threadIdx.x;
    float acc = 0.f;
#pragma unroll
    for (int j = 0; j < 32; j++) acc += g_part[j][idx];
    g_sum[idx] = acc;
}

// ---------------------------------------------------------------- layernorm (writes fp16x2 A splits for gemm2)
__device__ __forceinline__ float blk_sum(float v, float* sh) {
    int lane = threadIdx.x & 31, w = threadIdx.x >> 5;
#pragma unroll
    for (int off = 16; off; off >>= 1) v += __shfl_xor_sync(0xffffffffu, v, off);
    if (lane == 0) sh[w] = v;
    __syncthreads();
    if (threadIdx.x == 0) {
        float t = 0.f;
#pragma unroll
        for (int i = 0; i < 8; i++) t += sh[i];
        sh[8] = t;
    }
    __syncthreads();
    return sh[8];
}

__global__ __launch_bounds__(256) void ln_kernel(const float* __restrict__ gamma,
                                                 const float* __restrict__ beta) {
    __shared__ float sh[9];
    int row = blockIdx.x;
    int b = row >> 13;
    const float* in = g_o + (size_t)row * D_MODEL;
    float v[3];
    float s = 0.f;
#pragma unroll
    for (int i = 0; i < 3; i++) {
        int c = threadIdx.x + i * 256;
        float val = in[c] / (3.0f * g_sum[b * D_MODEL + c]);
        v[i] = val;
        s += val;
    }
    float mean = blk_sum(s, sh) * (1.0f / 768.0f);
    float vs = 0.f;
#pragma unroll
    for (int i = 0; i < 3; i++) {
        float d = v[i] - mean;
        vs += d * d;
    }
    float var = blk_sum(vs, sh) * (1.0f / 768.0f);
    float rstd = rsqrtf(var + 1e-5f);
#pragma unroll
    for (int i = 0; i < 3; i++) {
        int c = threadIdx.x + i * 256;
        float outv = (v[i] - mean) * rstd * gamma[c] + beta[c];
        uint16_t hh, ll;
        split2s(outv, hh, ll);
        size_t idx = (size_t)row * D_MODEL + c;
        g_ah[idx] = hh;
        g_al[idx] = ll;
    }
}

// ---------------------------------------------------------------- launch
extern "C" void kernel_launch(void* const* d_in, const int* in_sizes, int n_in,
                              void* d_out, int out_size) {
    const float* x      = (const float*)d_in[0];
    const float* w_in   = (const float*)d_in[1];
    const float* b_in   = (const float*)d_in[2];
    const float* w_out  = (const float*)d_in[3];
    const float* b_out  = (const float*)d_in[4];
    const float* gamma  = (const float*)d_in[5];
    const float* beta   = (const float*)d_in[6];
    float* out = (float*)d_out;

    cudaFuncSetAttribute(gemm_mma_kernel, cudaFuncAttributeMaxDynamicSharedMemorySize,
                         GEMM_SMEM_B);
    cudaFuncSetAttribute(gemm2_f16_kernel, cudaFuncAttributeMaxDynamicSharedMemorySize,
                         GEMM2_SMEM_B);
    cudaFuncSetAttribute(attn_mma_kernel, cudaFuncAttributeMaxDynamicSharedMemorySize,
                         ATTN_SMEM);

    const int nbig4 = NTOK * D_MODEL / 4;
    const int nw4 = D_MODEL * D_MODEL / 4;

    zero_o_kernel<<<3072, 256>>>();
    split_kernel<<<(nbig4 + 255) / 256, 256>>>(x, nbig4, 0);
    split_kernel<<<(nw4 + 255) / 256, 256>>>(w_in, nw4, 1);
    split2_kernel<<<(nw4 + 255) / 256, 256>>>(w_out, nw4);
    gemm_mma_kernel<<<dim3(6, 128), 256, GEMM_SMEM_B>>>(b_in);
    attn_mma_kernel<<<dim3(16, 56), 256, ATTN_SMEM>>>();
    reduce1_kernel<<<dim3(6, 32), 256>>>();
    reduce2_kernel<<<6, 256>>>();
    ln_kernel<<<NTOK, 256>>>(gamma, beta);
    gemm2_f16_kernel<<<dim3(6, 128), 256, GEMM2_SMEM_B>>>(b_out, out);
}

// round 12
// speedup vs baseline: 1.7183x; 1.0124x over previous
#include <cuda_runtime.h>
#include <cuda_bf16.h>
#include <cuda_fp16.h>
#include <stdint.h>
#include <math.h>

#define D_MODEL 768
#define NHEADS 12
#define HD 64
#define BATCH 2
#define SEQ 8192
#define NTOK (BATCH * SEQ)
#define SE 2048
#define LOG2E 1.4426950408889634f

// Scratch (allocation-free rule: __device__ globals)
__device__ float g_o[NTOK * D_MODEL];
__device__ float g_part[32][BATCH * D_MODEL];
__device__ float g_sum[BATCH * D_MODEL];
// g_a*: bf16x3 of x for gemm1; later fp16x2 of ln-out for gemm2 (g_am unused then)
__device__ uint16_t g_ah[NTOK * D_MODEL], g_am[NTOK * D_MODEL], g_al[NTOK * D_MODEL];
// projected q: bf16x3 (V side of PV; renorm-amplified O-path)
__device__ uint16_t g_qh[NTOK * D_MODEL], g_qm[NTOK * D_MODEL], g_ql[NTOK * D_MODEL];
// projected q: fp16x2 (QK S-path)
__device__ uint16_t g_fh[NTOK * D_MODEL], g_fl[NTOK * D_MODEL];
// weights: w1 bf16x3 (amplified), w2 fp16x2 (un-amplified)
__device__ uint16_t g_w1h[D_MODEL * D_MODEL], g_w1m[D_MODEL * D_MODEL], g_w1l[D_MODEL * D_MODEL];
__device__ uint16_t g_w2h[D_MODEL * D_MODEL], g_w2l[D_MODEL * D_MODEL];

// ================================================================ helpers
__device__ __forceinline__ uint32_t smem_u32(const void* p) {
    uint32_t a;
    asm("{ .reg .u64 t; cvta.to.shared.u64 t, %1; cvt.u32.u64 %0, t; }" : "=r"(a) : "l"(p));
    return a;
}

#define SWZ(off) ((off) ^ (((off) >> 3) & 0x70))

__device__ __forceinline__ void ldsm_x4(uint32_t& r0, uint32_t& r1, uint32_t& r2,
                                        uint32_t& r3, uint32_t addr) {
    asm volatile("ldmatrix.sync.aligned.m8n8.x4.shared.b16 {%0,%1,%2,%3}, [%4];"
                 : "=r"(r0), "=r"(r1), "=r"(r2), "=r"(r3) : "r"(addr));
}
__device__ __forceinline__ void ldsm_x4_t(uint32_t& r0, uint32_t& r1, uint32_t& r2,
                                          uint32_t& r3, uint32_t addr) {
    asm volatile("ldmatrix.sync.aligned.m8n8.x4.trans.shared.b16 {%0,%1,%2,%3}, [%4];"
                 : "=r"(r0), "=r"(r1), "=r"(r2), "=r"(r3) : "r"(addr));
}
// bf16 mma
__device__ __forceinline__ void mma16816(float* c, uint32_t a0, uint32_t a1, uint32_t a2,
                                         uint32_t a3, uint32_t b0, uint32_t b1) {
    asm volatile(
        "mma.sync.aligned.m16n8k16.row.col.f32.bf16.bf16.f32 "
        "{%0,%1,%2,%3}, {%4,%5,%6,%7}, {%8,%9}, {%0,%1,%2,%3};"
        : "+f"(c[0]), "+f"(c[1]), "+f"(c[2]), "+f"(c[3])
        : "r"(a0), "r"(a1), "r"(a2), "r"(a3), "r"(b0), "r"(b1));
}
// fp16 mma
__device__ __forceinline__ void mmah(float* c, uint32_t a0, uint32_t a1, uint32_t a2,
                                     uint32_t a3, uint32_t b0, uint32_t b1) {
    asm volatile(
        "mma.sync.aligned.m16n8k16.row.col.f32.f16.f16.f32 "
        "{%0,%1,%2,%3}, {%4,%5,%6,%7}, {%8,%9}, {%0,%1,%2,%3};"
        : "+f"(c[0]), "+f"(c[1]), "+f"(c[2]), "+f"(c[3])
        : "r"(a0), "r"(a1), "r"(a2), "r"(a3), "r"(b0), "r"(b1));
}
#define CP_ASYNC16(dst, src) \
    asm volatile("cp.async.cg.shared.global [%0], [%1], 16;" :: "r"(dst), "l"(src))
#define CP_COMMIT() asm volatile("cp.async.commit_group;")

__device__ __forceinline__ uint32_t pack_bf2(__nv_bfloat16 lo, __nv_bfloat16 hi) {
    return ((uint32_t)__bfloat16_as_ushort(hi) << 16) | (uint32_t)__bfloat16_as_ushort(lo);
}
__device__ __forceinline__ void split3(float a, float b,
                                       uint32_t& h, uint32_t& m, uint32_t& l) {
    __nv_bfloat16 ah = __float2bfloat16(a), bh = __float2bfloat16(b);
    float ar = a - __bfloat162float(ah), br = b - __bfloat162float(bh);
    __nv_bfloat16 am = __float2bfloat16(ar), bm = __float2bfloat16(br);
    float ar2 = ar - __bfloat162float(am), br2 = br - __bfloat162float(bm);
    __nv_bfloat16 al = __float2bfloat16(ar2), bl = __float2bfloat16(br2);
    h = pack_bf2(ah, bh);
    m = pack_bf2(am, bm);
    l = pack_bf2(al, bl);
}
__device__ __forceinline__ uint32_t pack_h2(__half lo, __half hi) {
    return ((uint32_t)__half_as_ushort(hi) << 16) | (uint32_t)__half_as_ushort(lo);
}
__device__ __forceinline__ void split2(float a, float b, uint32_t& h, uint32_t& l) {
    __half ha = __float2half_rn(a), hb = __float2half_rn(b);
    __half la = __float2half_rn(a - __half2float(ha));
    __half lb = __float2half_rn(b - __half2float(hb));
    h = pack_h2(ha, hb);
    l = pack_h2(la, lb);
}
__device__ __forceinline__ void split2s(float a, uint16_t& h, uint16_t& l) {
    __half ha = __float2half_rn(a);
    __half la = __float2half_rn(a - __half2float(ha));
    h = __half_as_ushort(ha);
    l = __half_as_ushort(la);
}

// FMA-pipe exp2 (no MUFU)
__device__ __forceinline__ float fexp2(float f) {
    f = fmaxf(f, -120.0f);
    float t = f + 12582912.0f;
    int i = __float_as_int(t);
    float r = f - (t - 12582912.0f);
    float p = 1.33335581e-4f;
    p = fmaf(p, r, 1.35345402e-3f);
    p = fmaf(p, r, 9.61783718e-3f);
    p = fmaf(p, r, 5.55028137e-2f);
    p = fmaf(p, r, 2.40226507e-1f);
    p = fmaf(p, r, 6.93147181e-1f);
    p = fmaf(p, r, 1.0f);
    return __int_as_float(__float_as_int(p) + (i << 23));
}

// ---------------------------------------------------------------- zero fill
__global__ void zero_o_kernel() {
    int idx = blockIdx.x * blockDim.x + threadIdx.x;
    const int n4 = NTOK * D_MODEL / 4;
    float4 z = make_float4(0.f, 0.f, 0.f, 0.f);
    for (int i = idx; i < n4; i += gridDim.x * blockDim.x)
        ((float4*)g_o)[i] = z;
}

// ---------------------------------------------------------------- splits
__global__ __launch_bounds__(256) void split_kernel(const float* __restrict__ src,
                                                    int n4, int sel) {
    int i = blockIdx.x * blockDim.x + threadIdx.x;
    if (i >= n4) return;
    float4 v = ((const float4*)src)[i];
    uint32_t h0, m0, l0, h1, m1, l1;
    split3(v.x, v.y, h0, m0, l0);
    split3(v.z, v.w, h1, m1, l1);
    uint2* dh; uint2* dm; uint2* dl;
    if (sel == 0) { dh = (uint2*)g_ah;  dm = (uint2*)g_am;  dl = (uint2*)g_al; }
    else          { dh = (uint2*)g_w1h; dm = (uint2*)g_w1m; dl = (uint2*)g_w1l; }
    dh[i] = make_uint2(h0, h1);
    dm[i] = make_uint2(m0, m1);
    dl[i] = make_uint2(l0, l1);
}
__global__ __launch_bounds__(256) void split2_kernel(const float* __restrict__ src, int n4) {
    int i = blockIdx.x * blockDim.x + threadIdx.x;
    if (i >= n4) return;
    float4 v = ((const float4*)src)[i];
    uint32_t h0, l0, h1, l1;
    split2(v.x, v.y, h0, l0);
    split2(v.z, v.w, h1, l1);
    ((uint2*)g_w2h)[i] = make_uint2(h0, h1);
    ((uint2*)g_w2l)[i] = make_uint2(l0, l1);
}

// ================================================================ GEMM1 (bf16x3, 6 products) -> q bf16x3 + fp16x2
#define GKC 16
#define NCH (D_MODEL / GKC)       // 48
#define G_LVL_B (128 * 48)
#define G_OP_B (3 * G_LVL_B)
#define G_STAGE (2 * G_OP_B)
#define GEMM_SMEM_B (2 * G_STAGE)

__device__ __forceinline__ void gemm_issue(int c, int buf, uint32_t sbase, int tid,
                                           int m0, int n0) {
    int k0 = c * GKC;
    uint32_t sb = sbase + buf * G_STAGE;
    int row = tid >> 1, half = tid & 1;
    const uint16_t* srcs[6] = {g_ah, g_am, g_al, g_w1h, g_w1m, g_w1l};
#pragma unroll
    for (int it = 0; it < 6; it++) {
        int grow = (it < 3 ? m0 : n0) + row;
        const uint16_t* sp = srcs[it] + (size_t)grow * D_MODEL + k0 + half * 8;
        uint32_t dst = sb + (it < 3 ? 0 : G_OP_B) + (it % 3) * G_LVL_B + row * 48 + half * 16;
        CP_ASYNC16(dst, sp);
    }
    CP_COMMIT();
}

__global__ __launch_bounds__(256, 1) void gemm_mma_kernel(const float* __restrict__ bias) {
    extern __shared__ uint8_t gsm[];
    uint32_t sbase = smem_u32(gsm);
    int tid = threadIdx.x, warp = tid >> 5, lane = tid & 31;
    int m0 = blockIdx.y * 128, n0 = blockIdx.x * 128;

    float ohi[16][4], olo[16][4];
#pragma unroll
    for (int j = 0; j < 16; j++) {
        ohi[j][0] = ohi[j][1] = ohi[j][2] = ohi[j][3] = 0.f;
        olo[j][0] = olo[j][1] = olo[j][2] = olo[j][3] = 0.f;
    }

    gemm_issue(0, 0, sbase, tid, m0, n0);

    uint32_t arow = (uint32_t)((warp * 16 + (lane & 15)) * 48 + (lane >> 4) * 16);
    uint32_t brow = (uint32_t)(((lane & 7) + ((lane >> 4) << 3)) * 48 + ((lane & 8) ? 16 : 0));

    for (int c = 0; c < NCH; c++) {
        int buf = c & 1;
        if (c + 1 < NCH) {
            gemm_issue(c + 1, buf ^ 1, sbase, tid, m0, n0);
            asm volatile("cp.async.wait_group 1;");
        } else {
            asm volatile("cp.async.wait_group 0;");
        }
        __syncthreads();

        uint32_t ab = sbase + buf * G_STAGE;
        uint32_t bb = ab + G_OP_B;
        uint32_t ah0, ah1, ah2, ah3, am0, am1, am2, am3, al0, al1, al2, al3;
        ldsm_x4(ah0, ah1, ah2, ah3, ab + 0 * G_LVL_B + arow);
        ldsm_x4(am0, am1, am2, am3, ab + 1 * G_LVL_B + arow);
        ldsm_x4(al0, al1, al2, al3, ab + 2 * G_LVL_B + arow);
#pragma unroll
        for (int np = 0; np < 8; np++) {
            uint32_t baddr = bb + (uint32_t)(np * 16 * 48) + brow;
            uint32_t bh0, bh1, bh2, bh3, bm0, bm1, bm2, bm3, bl0, bl1, bl2, bl3;
            ldsm_x4(bh0, bh1, bh2, bh3, baddr + 0 * G_LVL_B);
            ldsm_x4(bm0, bm1, bm2, bm3, baddr + 1 * G_LVL_B);
            ldsm_x4(bl0, bl1, bl2, bl3, baddr + 2 * G_LVL_B);
            // interleave the two accumulator chains for ILP
            mma16816(ohi[np * 2 + 0], ah0, ah1, ah2, ah3, bh0, bh1);
            mma16816(ohi[np * 2 + 1], ah0, ah1, ah2, ah3, bh2, bh3);
            mma16816(olo[np * 2 + 0], ah0, ah1, ah2, ah3, bm0, bm1);
            mma16816(olo[np * 2 + 1], ah0, ah1, ah2, ah3, bm2, bm3);
            mma16816(olo[np * 2 + 0], am0, am1, am2, am3, bh0, bh1);
            mma16816(olo[np * 2 + 1], am0, am1, am2, am3, bh2, bh3);
            mma16816(olo[np * 2 + 0], am0, am1, am2, am3, bm0, bm1);
            mma16816(olo[np * 2 + 1], am0, am1, am2, am3, bm2, bm3);
            mma16816(olo[np * 2 + 0], ah0, ah1, ah2, ah3, bl0, bl1);
            mma16816(olo[np * 2 + 1], ah0, ah1, ah2, ah3, bl2, bl3);
            mma16816(olo[np * 2 + 0], al0, al1, al2, al3, bh0, bh1);
            mma16816(olo[np * 2 + 1], al0, al1, al2, al3, bh2, bh3);
        }
        __syncthreads();
    }

    // epilogue: write q as bf16x3 (V side) AND fp16x2 (QK side)
    int r0l = lane >> 2, c2 = (lane & 3) * 2;
    int mrow0 = m0 + warp * 16 + r0l;
    int mrow1 = mrow0 + 8;
#pragma unroll
    for (int j = 0; j < 16; j++) {
        int col = n0 + j * 8 + c2;
        float2 bv = *(const float2*)(bias + col);
        float v0 = ohi[j][0] + olo[j][0] + bv.x;
        float v1 = ohi[j][1] + olo[j][1] + bv.y;
        float v2 = ohi[j][2] + olo[j][2] + bv.x;
        float v3 = ohi[j][3] + olo[j][3] + bv.y;
        uint32_t h, m, l;
        uint32_t fh, fl;
        split3(v0, v1, h, m, l);
        split2(v0, v1, fh, fl);
        uint32_t i0 = (uint32_t)(mrow0 * D_MODEL + col) >> 1;
        ((uint32_t*)g_qh)[i0] = h;
        ((uint32_t*)g_qm)[i0] = m;
        ((uint32_t*)g_ql)[i0] = l;
        ((uint32_t*)g_fh)[i0] = fh;
        ((uint32_t*)g_fl)[i0] = fl;
        split3(v2, v3, h, m, l);
        split2(v2, v3, fh, fl);
        uint32_t i1 = (uint32_t)(mrow1 * D_MODEL + col) >> 1;
        ((uint32_t*)g_qh)[i1] = h;
        ((uint32_t*)g_qm)[i1] = m;
        ((uint32_t*)g_ql)[i1] = l;
        ((uint32_t*)g_fh)[i1] = fh;
        ((uint32_t*)g_fl)[i1] = fl;
    }
}

// ================================================================ GEMM2 (fp16x2, 3 products)
#define F_LVL_B (128 * 48)
#define F_OP_B (2 * F_LVL_B)
#define F_STAGE (2 * F_OP_B)
#define GEMM2_SMEM_B (2 * F_STAGE)

__device__ __forceinline__ void gemm2_issue(int c, int buf, uint32_t sbase, int tid,
                                            int m0, int n0) {
    int k0 = c * GKC;
    uint32_t sb = sbase + buf * F_STAGE;
    int row = tid >> 1, half = tid & 1;
    const uint16_t* srcs[4] = {g_ah, g_al, g_w2h, g_w2l};
#pragma unroll
    for (int it = 0; it < 4; it++) {
        int grow = (it < 2 ? m0 : n0) + row;
        const uint16_t* sp = srcs[it] + (size_t)grow * D_MODEL + k0 + half * 8;
        uint32_t dst = sb + (it < 2 ? 0 : F_OP_B) + (it & 1) * F_LVL_B + row * 48 + half * 16;
        CP_ASYNC16(dst, sp);
    }
    CP_COMMIT();
}

__global__ __launch_bounds__(256, 1) void gemm2_f16_kernel(const float* __restrict__ bias,
                                                           float* __restrict__ outp) {
    extern __shared__ uint8_t gsm[];
    uint32_t sbase = smem_u32(gsm);
    int tid = threadIdx.x, warp = tid >> 5, lane = tid & 31;
    int m0 = blockIdx.y * 128, n0 = blockIdx.x * 128;

    float ohi[16][4], olo[16][4];
#pragma unroll
    for (int j = 0; j < 16; j++) {
        ohi[j][0] = ohi[j][1] = ohi[j][2] = ohi[j][3] = 0.f;
        olo[j][0] = olo[j][1] = olo[j][2] = olo[j][3] = 0.f;
    }

    gemm2_issue(0, 0, sbase, tid, m0, n0);

    uint32_t arow = (uint32_t)((warp * 16 + (lane & 15)) * 48 + (lane >> 4) * 16);
    uint32_t brow = (uint32_t)(((lane & 7) + ((lane >> 4) << 3)) * 48 + ((lane & 8) ? 16 : 0));

    for (int c = 0; c < NCH; c++) {
        int buf = c & 1;
        if (c + 1 < NCH) {
            gemm2_issue(c + 1, buf ^ 1, sbase, tid, m0, n0);
            asm volatile("cp.async.wait_group 1;");
        } else {
            asm volatile("cp.async.wait_group 0;");
        }
        __syncthreads();

        uint32_t ab = sbase + buf * F_STAGE;
        uint32_t bb = ab + F_OP_B;
        uint32_t ah0, ah1, ah2, ah3, al0, al1, al2, al3;
        ldsm_x4(ah0, ah1, ah2, ah3, ab + 0 * F_LVL_B + arow);
        ldsm_x4(al0, al1, al2, al3, ab + 1 * F_LVL_B + arow);
#pragma unroll
        for (int np = 0; np < 8; np++) {
            uint32_t baddr = bb + (uint32_t)(np * 16 * 48) + brow;
            uint32_t bh0, bh1, bh2, bh3, bl0, bl1, bl2, bl3;
            ldsm_x4(bh0, bh1, bh2, bh3, baddr + 0 * F_LVL_B);
            ldsm_x4(bl0, bl1, bl2, bl3, baddr + 1 * F_LVL_B);
            mmah(ohi[np * 2 + 0], ah0, ah1, ah2, ah3, bh0, bh1);
            mmah(ohi[np * 2 + 1], ah0, ah1, ah2, ah3, bh2, bh3);
            mmah(olo[np * 2 + 0], ah0, ah1, ah2, ah3, bl0, bl1);
            mmah(olo[np * 2 + 1], ah0, ah1, ah2, ah3, bl2, bl3);
            mmah(olo[np * 2 + 0], al0, al1, al2, al3, bh0, bh1);
            mmah(olo[np * 2 + 1], al0, al1, al2, al3, bh2, bh3);
        }
        __syncthreads();
    }

    int r0l = lane >> 2, c2 = (lane & 3) * 2;
    int mrow0 = m0 + warp * 16 + r0l;
    int mrow1 = mrow0 + 8;
#pragma unroll
    for (int j = 0; j < 16; j++) {
        int col = n0 + j * 8 + c2;
        float2 bv = *(const float2*)(bias + col);
        *(float2*)(outp + (size_t)mrow0 * D_MODEL + col) =
            make_float2(ohi[j][0] + olo[j][0] + bv.x, ohi[j][1] + olo[j][1] + bv.y);
        *(float2*)(outp + (size_t)mrow1 * D_MODEL + col) =
            make_float2(ohi[j][2] + olo[j][2] + bv.x, ohi[j][3] + olo[j][3] + bv.y);
    }
}

// ================================================================ attention
// QK: fp16x2 (3 products). PV: bf16x3 (6 products). Fixed-max softmax.
// 64-query CTAs (128 threads), 2 CTAs/SM for dependency-latency hiding.
#define KT_LVL 8192
#define KT_BUF (5 * KT_LVL)     // 2 fp16 levels + 3 bf16 levels = 40960 B
#define ATTN_SMEM (2 * KT_BUF)  // 81920 B

#define P_SCL 0.18033688011111793f
#define P_OFF -23.083120654223414f

__device__ __forceinline__ void attn_stage(uint32_t dstbase, int b, int kbase,
                                           int k0, int r, int h, int tid) {
#pragma unroll
    for (int it = 0; it < 20; it++) {
        int idx = tid + it * 128;          // 0..2559
        int lvl = idx >> 9;                // 0..4
        int rem = idx & 511;
        int key = rem >> 3;
        int c16 = rem & 7;
        int posk = kbase + (k0 + key) * r;
        uint32_t goff = (uint32_t)(b * SEQ + posk) * D_MODEL + h * HD + c16 * 8;
        const uint16_t* src;
        switch (lvl) {
            case 0: src = g_fh + goff; break;
            case 1: src = g_fl + goff; break;
            case 2: src = g_qh + goff; break;
            case 3: src = g_qm + goff; break;
            default: src = g_ql + goff; break;
        }
        uint32_t dst = dstbase + lvl * KT_LVL + SWZ((uint32_t)(key * 128 + c16 * 16));
        CP_ASYNC16(dst, src);
    }
    CP_COMMIT();
}

__global__ __launch_bounds__(128, 2) void attn_mma_kernel() {
    extern __shared__ uint8_t ksm[];

    int inst = blockIdx.y;
    int b, h, seg, r, off, slen;
    if (inst < 32)      { b = inst >> 4; int t = inst & 15; seg = t >> 2; h = t & 3;            r = 1; off = 0; slen = 2048; }
    else if (inst < 48) { int t = inst - 32; b = t >> 3; t &= 7; seg = t >> 2; h = 4 + (t & 3); r = 2; off = 1; slen = 4096; }
    else                { int t = inst - 48; b = t >> 2; h = 8 + (t & 3); seg = 0;              r = 4; off = 2; slen = 8192; }

    int tid = threadIdx.x;
    int warp = tid >> 5, lane = tid & 31;
    int kbase = seg * slen + off;
    int qrow0 = blockIdx.x * 64 + warp * 16;

    uint32_t smb = smem_u32(ksm);

    int r0l = lane >> 2;
    int c2 = (lane & 3) * 2;

    // -------- Q fragments (fp16x2 levels)
    int posq0 = kbase + (qrow0 + r0l) * r;
    int posq1 = kbase + (qrow0 + r0l + 8) * r;
    uint32_t qb0 = (uint32_t)(b * SEQ + posq0) * D_MODEL + h * HD;
    uint32_t qb1 = (uint32_t)(b * SEQ + posq1) * D_MODEL + h * HD;
    uint32_t qh[16], ql[16];
#pragma unroll
    for (int kc = 0; kc < 4; kc++) {
        uint32_t i00 = (qb0 + kc * 16 + c2) >> 1;
        uint32_t i10 = (qb1 + kc * 16 + c2) >> 1;
        uint32_t i01 = (qb0 + kc * 16 + c2 + 8) >> 1;
        uint32_t i11 = (qb1 + kc * 16 + c2 + 8) >> 1;
        qh[kc * 4 + 0] = ((const uint32_t*)g_fh)[i00];
        ql[kc * 4 + 0] = ((const uint32_t*)g_fl)[i00];
        qh[kc * 4 + 1] = ((const uint32_t*)g_fh)[i10];
        ql[kc * 4 + 1] = ((const uint32_t*)g_fl)[i10];
        qh[kc * 4 + 2] = ((const uint32_t*)g_fh)[i01];
        ql[kc * 4 + 2] = ((const uint32_t*)g_fl)[i01];
        qh[kc * 4 + 3] = ((const uint32_t*)g_fh)[i11];
        ql[kc * 4 + 3] = ((const uint32_t*)g_fl)[i11];
    }

    float ohi[8][4], olo[8][4];
#pragma unroll
    for (int j = 0; j < 8; j++) {
        ohi[j][0] = ohi[j][1] = ohi[j][2] = ohi[j][3] = 0.f;
        olo[j][0] = olo[j][1] = olo[j][2] = olo[j][3] = 0.f;
    }
    float l0 = 0.f, l1 = 0.f;

    attn_stage(smb, b, kbase, 0, r, h, tid);

    int buf = 0;
    for (int kt = 0; kt < SE / 64; kt++) {
        if (kt + 1 < SE / 64) {
            attn_stage(smb + (buf ^ 1) * KT_BUF, b, kbase, (kt + 1) * 64, r, h, tid);
            asm volatile("cp.async.wait_group 1;");
        } else {
            asm volatile("cp.async.wait_group 0;");
        }
        __syncthreads();

        uint32_t kh_b = smb + buf * KT_BUF;          // fp16 h
        uint32_t kl_b = kh_b + KT_LVL;               // fp16 l
        uint32_t vh_b = kh_b + 2 * KT_LVL;           // bf16 h
        uint32_t vm_b = kh_b + 3 * KT_LVL;           // bf16 m
        uint32_t vl_b = kh_b + 4 * KT_LVL;           // bf16 l

        // -------- S = Q K^T : fp16x2, split accumulators
        float shi[8][4], slo[8][4];
#pragma unroll
        for (int j = 0; j < 8; j++) {
            shi[j][0] = shi[j][1] = shi[j][2] = shi[j][3] = 0.f;
            slo[j][0] = slo[j][1] = slo[j][2] = slo[j][3] = 0.f;
        }
#pragma unroll
        for (int kc = 0; kc < 4; kc++) {
            uint32_t a0h = qh[kc * 4 + 0], a1h = qh[kc * 4 + 1],
                     a2h = qh[kc * 4 + 2], a3h = qh[kc * 4 + 3];
            uint32_t a0l = ql[kc * 4 + 0], a1l = ql[kc * 4 + 1],
                     a2l = ql[kc * 4 + 2], a3l = ql[kc * 4 + 3];
#pragma unroll
            for (int np = 0; np < 4; np++) {
                int key = np * 16 + (lane & 7) + ((lane >> 4) << 3);
                int dim = kc * 16 + (lane & 8);
                uint32_t so = SWZ((uint32_t)(key * 128 + dim * 2));
                uint32_t bh0, bh1, bh2, bh3, bl0, bl1, bl2, bl3;
                ldsm_x4(bh0, bh1, bh2, bh3, kh_b + so);
                ldsm_x4(bl0, bl1, bl2, bl3, kl_b + so);
                mmah(shi[np * 2 + 0], a0h, a1h, a2h, a3h, bh0, bh1);
                mmah(shi[np * 2 + 1], a0h, a1h, a2h, a3h, bh2, bh3);
                mmah(slo[np * 2 + 0], a0h, a1h, a2h, a3h, bl0, bl1);
                mmah(slo[np * 2 + 1], a0h, a1h, a2h, a3h, bl2, bl3);
                mmah(slo[np * 2 + 0], a0l, a1l, a2l, a3l, bh0, bh1);
                mmah(slo[np * 2 + 1], a0l, a1l, a2l, a3l, bh2, bh3);
            }
        }

        // -------- fixed-max softmax: p = exp2(ssum*P_SCL + P_OFF), bf16x3 split
        uint32_t pah[8], pam[8], pal[8], pbh[8], pbm[8], pbl[8];
#pragma unroll
        for (int j = 0; j < 8; j++) {
            float p0 = fexp2(fmaf(shi[j][0] + slo[j][0], P_SCL, P_OFF));
            float p1 = fexp2(fmaf(shi[j][1] + slo[j][1], P_SCL, P_OFF));
            float p2 = fexp2(fmaf(shi[j][2] + slo[j][2], P_SCL, P_OFF));
            float p3 = fexp2(fmaf(shi[j][3] + slo[j][3], P_SCL, P_OFF));
            l0 += p0 + p1;
            l1 += p2 + p3;
            split3(p0, p1, pah[j], pam[j], pal[j]);
            split3(p2, p3, pbh[j], pbm[j], pbl[j]);
        }

        // -------- O += P V : bf16x3, split accumulators (interleaved chains)
#pragma unroll
        for (int kk = 0; kk < 4; kk++) {
            uint32_t a0h = pah[kk * 2], a1h = pbh[kk * 2],
                     a2h = pah[kk * 2 + 1], a3h = pbh[kk * 2 + 1];
            uint32_t a0m = pam[kk * 2], a1m = pbm[kk * 2],
                     a2m = pam[kk * 2 + 1], a3m = pbm[kk * 2 + 1];
            uint32_t a0l = pal[kk * 2], a1l = pbl[kk * 2],
                     a2l = pal[kk * 2 + 1], a3l = pbl[kk * 2 + 1];
#pragma unroll
            for (int np = 0; np < 4; np++) {
                int key = kk * 16 + (lane & 7) + (lane & 8);
                int dim = np * 16 + ((lane >> 4) << 3);
                uint32_t so = SWZ((uint32_t)(key * 128 + dim * 2));
                uint32_t bh0, bh1, bh2, bh3, bm0, bm1, bm2, bm3, bl0, bl1, bl2, bl3;
                ldsm_x4_t(bh0, bh1, bh2, bh3, vh_b + so);
                ldsm_x4_t(bm0, bm1, bm2, bm3, vm_b + so);
                ldsm_x4_t(bl0, bl1, bl2, bl3, vl_b + so);
                mma16816(ohi[np * 2 + 0], a0h, a1h, a2h, a3h, bh0, bh1);
                mma16816(ohi[np * 2 + 1], a0h, a1h, a2h, a3h, bh2, bh3);
                mma16816(olo[np * 2 + 0], a0h, a1h, a2h, a3h, bm0, bm1);
                mma16816(olo[np * 2 + 1], a0h, a1h, a2h, a3h, bm2, bm3);
                mma16816(olo[np * 2 + 0], a0m, a1m, a2m, a3m, bh0, bh1);
                mma16816(olo[np * 2 + 1], a0m, a1m, a2m, a3m, bh2, bh3);
                mma16816(olo[np * 2 + 0], a0m, a1m, a2m, a3m, bm0, bm1);
                mma16816(olo[np * 2 + 1], a0m, a1m, a2m, a3m, bm2, bm3);
                mma16816(olo[np * 2 + 0], a0h, a1h, a2h, a3h, bl0, bl1);
                mma16816(olo[np * 2 + 1], a0h, a1h, a2h, a3h, bl2, bl3);
                mma16816(olo[np * 2 + 0], a0l, a1l, a2l, a3l, bh0, bh1);
                mma16816(olo[np * 2 + 1], a0l, a1l, a2l, a3l, bh2, bh3);
            }
        }
        __syncthreads();
        buf ^= 1;
    }

    // -------- finalize
    l0 += __shfl_xor_sync(0xffffffffu, l0, 1);
    l0 += __shfl_xor_sync(0xffffffffu, l0, 2);
    l1 += __shfl_xor_sync(0xffffffffu, l1, 1);
    l1 += __shfl_xor_sync(0xffffffffu, l1, 2);
    float inv0 = 1.0f / l0, inv1 = 1.0f / l1;
    float* op0 = g_o + ((size_t)b * SEQ + posq0) * D_MODEL + h * HD;
    float* op1 = g_o + ((size_t)b * SEQ + posq1) * D_MODEL + h * HD;
#pragma unroll
    for (int j = 0; j < 8; j++) {
        *(float2*)(op0 + j * 8 + c2) = make_float2((ohi[j][0] + olo[j][0]) * inv0,
                                                   (ohi[j][1] + olo[j][1]) * inv0);
        *(float2*)(op1 + j * 8 + c2) = make_float2((ohi[j][2] + olo[j][2]) * inv1,
                                                   (ohi[j][3] + olo[j][3]) * inv1);
    }
}

// ---------------------------------------------------------------- renorm sums
__global__ __launch_bounds__(256) void reduce1_kernel() {
    int bc = blockIdx.x;
    int b = bc / 3, cb = bc % 3;
    int c = cb * 256 + threadIdx.x;
    size_t base = (size_t)(b * SEQ + blockIdx.y * 256) * D_MODEL + c;
    float acc = 0.f;
    for (int rr = 0; rr < 256; rr++) acc += g_o[base + (size_t)rr * D_MODEL];
    g_part[blockIdx.y][b * D_MODEL + c] = acc;
}
__global__ void reduce2_kernel() {
    int idx = blockIdx.x * 256 + threadIdx.x;
    float acc = 0.f;
#pragma unroll
    for (int j = 0; j < 32; j++) acc += g_part[j][idx];
    g_sum[idx] = acc;
}

// ---------------------------------------------------------------- layernorm (writes fp16x2 A splits for gemm2)
__device__ __forceinline__ float blk_sum(float v, float* sh) {
    int lane = threadIdx.x & 31, w = threadIdx.x >> 5;
#pragma unroll
    for (int off = 16; off; off >>= 1) v += __shfl_xor_sync(0xffffffffu, v, off);
    if (lane == 0) sh[w] = v;
    __syncthreads();
    if (threadIdx.x == 0) {
        float t = 0.f;
#pragma unroll
        for (int i = 0; i < 8; i++) t += sh[i];
        sh[8] = t;
    }
    __syncthreads();
    return sh[8];
}

__global__ __launch_bounds__(256) void ln_kernel(const float* __restrict__ gamma,
                                                 const float* __restrict__ beta) {
    __shared__ float sh[9];
    int row = blockIdx.x;
    int b = row >> 13;
    const float* in = g_o + (size_t)row * D_MODEL;
    float v[3];
    float s = 0.f;
#pragma unroll
    for (int i = 0; i < 3; i++) {
        int c = threadIdx.x + i * 256;
        float val = in[c] / (3.0f * g_sum[b * D_MODEL + c]);
        v[i] = val;
        s += val;
    }
    float mean = blk_sum(s, sh) * (1.0f / 768.0f);
    float vs = 0.f;
#pragma unroll
    for (int i = 0; i < 3; i++) {
        float d = v[i] - mean;
        vs += d * d;
    }
    float var = blk_sum(vs, sh) * (1.0f / 768.0f);
    float rstd = rsqrtf(var + 1e-5f);
#pragma unroll
    for (int i = 0; i < 3; i++) {
        int c = threadIdx.x + i * 256;
        float outv = (v[i] - mean) * rstd * gamma[c] + beta[c];
        uint16_t hh, ll;
        split2s(outv, hh, ll);
        size_t idx = (size_t)row * D_MODEL + c;
        g_ah[idx] = hh;
        g_al[idx] = ll;
    }
}

// ---------------------------------------------------------------- launch
extern "C" void kernel_launch(void* const* d_in, const int* in_sizes, int n_in,
                              void* d_out, int out_size) {
    const float* x      = (const float*)d_in[0];
    const float* w_in   = (const float*)d_in[1];
    const float* b_in   = (const float*)d_in[2];
    const float* w_out  = (const float*)d_in[3];
    const float* b_out  = (const float*)d_in[4];
    const float* gamma  = (const float*)d_in[5];
    const float* beta   = (const float*)d_in[6];
    float* out = (float*)d_out;

    cudaFuncSetAttribute(gemm_mma_kernel, cudaFuncAttributeMaxDynamicSharedMemorySize,
                         GEMM_SMEM_B);
    cudaFuncSetAttribute(gemm2_f16_kernel, cudaFuncAttributeMaxDynamicSharedMemorySize,
                         GEMM2_SMEM_B);
    cudaFuncSetAttribute(attn_mma_kernel, cudaFuncAttributeMaxDynamicSharedMemorySize,
                         ATTN_SMEM);

    const int nbig4 = NTOK * D_MODEL / 4;
    const int nw4 = D_MODEL * D_MODEL / 4;

    zero_o_kernel<<<3072, 256>>>();
    split_kernel<<<(nbig4 + 255) / 256, 256>>>(x, nbig4, 0);
    split_kernel<<<(nw4 + 255) / 256, 256>>>(w_in, nw4, 1);
    split2_kernel<<<(nw4 + 255) / 256, 256>>>(w_out, nw4);
    gemm_mma_kernel<<<dim3(6, 128), 256, GEMM_SMEM_B>>>(b_in);
    attn_mma_kernel<<<dim3(32, 56), 128, ATTN_SMEM>>>();
    reduce1_kernel<<<dim3(6, 32), 256>>>();
    reduce2_kernel<<<6, 256>>>();
    ln_kernel<<<NTOK, 256>>>(gamma, beta);
    gemm2_f16_kernel<<<dim3(6, 128), 256, GEMM2_SMEM_B>>>(b_out, out);
}

// round 13
// speedup vs baseline: 1.8063x; 1.0512x over previous
#include <cuda_runtime.h>
#include <cuda_bf16.h>
#include <cuda_fp16.h>
#include <stdint.h>
#include <math.h>

#define D_MODEL 768
#define NHEADS 12
#define HD 64
#define BATCH 2
#define SEQ 8192
#define NTOK (BATCH * SEQ)
#define SE 2048
#define LOG2E 1.4426950408889634f

// Scratch (allocation-free rule: __device__ globals)
__device__ float g_o[NTOK * D_MODEL];
__device__ float g_part[32][BATCH * D_MODEL];
__device__ float g_sum[BATCH * D_MODEL];
// g_a*: bf16x3 of x for gemm1; g_ah later holds fp16 of ln-out for gemm2
__device__ uint16_t g_ah[NTOK * D_MODEL], g_am[NTOK * D_MODEL], g_al[NTOK * D_MODEL];
// projected q: bf16x3 (V side of PV; renorm-amplified O-path)
__device__ uint16_t g_qh[NTOK * D_MODEL], g_qm[NTOK * D_MODEL], g_ql[NTOK * D_MODEL];
// projected q: fp16x2 (QK S-path)
__device__ uint16_t g_fh[NTOK * D_MODEL], g_fl[NTOK * D_MODEL];
// weights: w1 bf16x3 (amplified), w2 fp16x2 (un-amplified)
__device__ uint16_t g_w1h[D_MODEL * D_MODEL], g_w1m[D_MODEL * D_MODEL], g_w1l[D_MODEL * D_MODEL];
__device__ uint16_t g_w2h[D_MODEL * D_MODEL], g_w2l[D_MODEL * D_MODEL];

// ================================================================ helpers
__device__ __forceinline__ uint32_t smem_u32(const void* p) {
    uint32_t a;
    asm("{ .reg .u64 t; cvta.to.shared.u64 t, %1; cvt.u32.u64 %0, t; }" : "=r"(a) : "l"(p));
    return a;
}

#define SWZ(off) ((off) ^ (((off) >> 3) & 0x70))

__device__ __forceinline__ void ldsm_x4(uint32_t& r0, uint32_t& r1, uint32_t& r2,
                                        uint32_t& r3, uint32_t addr) {
    asm volatile("ldmatrix.sync.aligned.m8n8.x4.shared.b16 {%0,%1,%2,%3}, [%4];"
                 : "=r"(r0), "=r"(r1), "=r"(r2), "=r"(r3) : "r"(addr));
}
__device__ __forceinline__ void ldsm_x4_t(uint32_t& r0, uint32_t& r1, uint32_t& r2,
                                          uint32_t& r3, uint32_t addr) {
    asm volatile("ldmatrix.sync.aligned.m8n8.x4.trans.shared.b16 {%0,%1,%2,%3}, [%4];"
                 : "=r"(r0), "=r"(r1), "=r"(r2), "=r"(r3) : "r"(addr));
}
// bf16 mma
__device__ __forceinline__ void mma16816(float* c, uint32_t a0, uint32_t a1, uint32_t a2,
                                         uint32_t a3, uint32_t b0, uint32_t b1) {
    asm volatile(
        "mma.sync.aligned.m16n8k16.row.col.f32.bf16.bf16.f32 "
        "{%0,%1,%2,%3}, {%4,%5,%6,%7}, {%8,%9}, {%0,%1,%2,%3};"
        : "+f"(c[0]), "+f"(c[1]), "+f"(c[2]), "+f"(c[3])
        : "r"(a0), "r"(a1), "r"(a2), "r"(a3), "r"(b0), "r"(b1));
}
// fp16 mma
__device__ __forceinline__ void mmah(float* c, uint32_t a0, uint32_t a1, uint32_t a2,
                                     uint32_t a3, uint32_t b0, uint32_t b1) {
    asm volatile(
        "mma.sync.aligned.m16n8k16.row.col.f32.f16.f16.f32 "
        "{%0,%1,%2,%3}, {%4,%5,%6,%7}, {%8,%9}, {%0,%1,%2,%3};"
        : "+f"(c[0]), "+f"(c[1]), "+f"(c[2]), "+f"(c[3])
        : "r"(a0), "r"(a1), "r"(a2), "r"(a3), "r"(b0), "r"(b1));
}
#define CP_ASYNC16(dst, src) \
    asm volatile("cp.async.cg.shared.global [%0], [%1], 16;" :: "r"(dst), "l"(src))
#define CP_COMMIT() asm volatile("cp.async.commit_group;")

__device__ __forceinline__ uint32_t pack_bf2(__nv_bfloat16 lo, __nv_bfloat16 hi) {
    return ((uint32_t)__bfloat16_as_ushort(hi) << 16) | (uint32_t)__bfloat16_as_ushort(lo);
}
__device__ __forceinline__ void split3(float a, float b,
                                       uint32_t& h, uint32_t& m, uint32_t& l) {
    __nv_bfloat16 ah = __float2bfloat16(a), bh = __float2bfloat16(b);
    float ar = a - __bfloat162float(ah), br = b - __bfloat162float(bh);
    __nv_bfloat16 am = __float2bfloat16(ar), bm = __float2bfloat16(br);
    float ar2 = ar - __bfloat162float(am), br2 = br - __bfloat162float(bm);
    __nv_bfloat16 al = __float2bfloat16(ar2), bl = __float2bfloat16(br2);
    h = pack_bf2(ah, bh);
    m = pack_bf2(am, bm);
    l = pack_bf2(al, bl);
}
__device__ __forceinline__ uint32_t pack_h2(__half lo, __half hi) {
    return ((uint32_t)__half_as_ushort(hi) << 16) | (uint32_t)__half_as_ushort(lo);
}
__device__ __forceinline__ void split2(float a, float b, uint32_t& h, uint32_t& l) {
    __half ha = __float2half_rn(a), hb = __float2half_rn(b);
    __half la = __float2half_rn(a - __half2float(ha));
    __half lb = __float2half_rn(b - __half2float(hb));
    h = pack_h2(ha, hb);
    l = pack_h2(la, lb);
}

// FMA-pipe exp2 (no MUFU)
__device__ __forceinline__ float fexp2(float f) {
    f = fmaxf(f, -120.0f);
    float t = f + 12582912.0f;
    int i = __float_as_int(t);
    float r = f - (t - 12582912.0f);
    float p = 1.33335581e-4f;
    p = fmaf(p, r, 1.35345402e-3f);
    p = fmaf(p, r, 9.61783718e-3f);
    p = fmaf(p, r, 5.55028137e-2f);
    p = fmaf(p, r, 2.40226507e-1f);
    p = fmaf(p, r, 6.93147181e-1f);
    p = fmaf(p, r, 1.0f);
    return __int_as_float(__float_as_int(p) + (i << 23));
}

// ---------------------------------------------------------------- zero fill
// Only channels [256,768) need zeroing: channels 0-255 (heads 0-3, r=1 group)
// are written at every position by the attention kernel.
__global__ void zero_o_kernel() {
    int idx = blockIdx.x * blockDim.x + threadIdx.x;
    const int per_tok = 512 / 4;  // 128 float4 per token
    const int n4 = NTOK * per_tok;
    float4 z = make_float4(0.f, 0.f, 0.f, 0.f);
    for (int i = idx; i < n4; i += gridDim.x * blockDim.x) {
        int tok = i / per_tok;
        int c4 = i % per_tok;
        ((float4*)(g_o + (size_t)tok * D_MODEL + 256))[c4] = z;
    }
}

// ---------------------------------------------------------------- splits
__global__ __launch_bounds__(256) void split_kernel(const float* __restrict__ src,
                                                    int n4, int sel) {
    int i = blockIdx.x * blockDim.x + threadIdx.x;
    if (i >= n4) return;
    float4 v = ((const float4*)src)[i];
    uint32_t h0, m0, l0, h1, m1, l1;
    split3(v.x, v.y, h0, m0, l0);
    split3(v.z, v.w, h1, m1, l1);
    uint2* dh; uint2* dm; uint2* dl;
    if (sel == 0) { dh = (uint2*)g_ah;  dm = (uint2*)g_am;  dl = (uint2*)g_al; }
    else          { dh = (uint2*)g_w1h; dm = (uint2*)g_w1m; dl = (uint2*)g_w1l; }
    dh[i] = make_uint2(h0, h1);
    dm[i] = make_uint2(m0, m1);
    dl[i] = make_uint2(l0, l1);
}
__global__ __launch_bounds__(256) void split2_kernel(const float* __restrict__ src, int n4) {
    int i = blockIdx.x * blockDim.x + threadIdx.x;
    if (i >= n4) return;
    float4 v = ((const float4*)src)[i];
    uint32_t h0, l0, h1, l1;
    split2(v.x, v.y, h0, l0);
    split2(v.z, v.w, h1, l1);
    ((uint2*)g_w2h)[i] = make_uint2(h0, h1);
    ((uint2*)g_w2l)[i] = make_uint2(l0, l1);
}

// ================================================================ GEMM1 (bf16x3, 6 products) -> q bf16x3 + fp16x2
#define GKC 16
#define NCH (D_MODEL / GKC)       // 48
#define G_LVL_B (128 * 48)
#define G_OP_B (3 * G_LVL_B)
#define G_STAGE (2 * G_OP_B)
#define GEMM_SMEM_B (2 * G_STAGE)

__device__ __forceinline__ void gemm_issue(int c, int buf, uint32_t sbase, int tid,
                                           int m0, int n0) {
    int k0 = c * GKC;
    uint32_t sb = sbase + buf * G_STAGE;
    int row = tid >> 1, half = tid & 1;
    const uint16_t* srcs[6] = {g_ah, g_am, g_al, g_w1h, g_w1m, g_w1l};
#pragma unroll
    for (int it = 0; it < 6; it++) {
        int grow = (it < 3 ? m0 : n0) + row;
        const uint16_t* sp = srcs[it] + (size_t)grow * D_MODEL + k0 + half * 8;
        uint32_t dst = sb + (it < 3 ? 0 : G_OP_B) + (it % 3) * G_LVL_B + row * 48 + half * 16;
        CP_ASYNC16(dst, sp);
    }
    CP_COMMIT();
}

__global__ __launch_bounds__(256, 1) void gemm_mma_kernel(const float* __restrict__ bias) {
    extern __shared__ uint8_t gsm[];
    uint32_t sbase = smem_u32(gsm);
    int tid = threadIdx.x, warp = tid >> 5, lane = tid & 31;
    int m0 = blockIdx.y * 128, n0 = blockIdx.x * 128;

    float ohi[16][4], olo[16][4];
#pragma unroll
    for (int j = 0; j < 16; j++) {
        ohi[j][0] = ohi[j][1] = ohi[j][2] = ohi[j][3] = 0.f;
        olo[j][0] = olo[j][1] = olo[j][2] = olo[j][3] = 0.f;
    }

    gemm_issue(0, 0, sbase, tid, m0, n0);

    uint32_t arow = (uint32_t)((warp * 16 + (lane & 15)) * 48 + (lane >> 4) * 16);
    uint32_t brow = (uint32_t)(((lane & 7) + ((lane >> 4) << 3)) * 48 + ((lane & 8) ? 16 : 0));

    for (int c = 0; c < NCH; c++) {
        int buf = c & 1;
        if (c + 1 < NCH) {
            gemm_issue(c + 1, buf ^ 1, sbase, tid, m0, n0);
            asm volatile("cp.async.wait_group 1;");
        } else {
            asm volatile("cp.async.wait_group 0;");
        }
        __syncthreads();

        uint32_t ab = sbase + buf * G_STAGE;
        uint32_t bb = ab + G_OP_B;
        uint32_t ah0, ah1, ah2, ah3, am0, am1, am2, am3, al0, al1, al2, al3;
        ldsm_x4(ah0, ah1, ah2, ah3, ab + 0 * G_LVL_B + arow);
        ldsm_x4(am0, am1, am2, am3, ab + 1 * G_LVL_B + arow);
        ldsm_x4(al0, al1, al2, al3, ab + 2 * G_LVL_B + arow);
#pragma unroll
        for (int np = 0; np < 8; np++) {
            uint32_t baddr = bb + (uint32_t)(np * 16 * 48) + brow;
            uint32_t bh0, bh1, bh2, bh3, bm0, bm1, bm2, bm3, bl0, bl1, bl2, bl3;
            ldsm_x4(bh0, bh1, bh2, bh3, baddr + 0 * G_LVL_B);
            ldsm_x4(bm0, bm1, bm2, bm3, baddr + 1 * G_LVL_B);
            ldsm_x4(bl0, bl1, bl2, bl3, baddr + 2 * G_LVL_B);
            mma16816(ohi[np * 2 + 0], ah0, ah1, ah2, ah3, bh0, bh1);
            mma16816(ohi[np * 2 + 1], ah0, ah1, ah2, ah3, bh2, bh3);
            mma16816(olo[np * 2 + 0], ah0, ah1, ah2, ah3, bm0, bm1);
            mma16816(olo[np * 2 + 1], ah0, ah1, ah2, ah3, bm2, bm3);
            mma16816(olo[np * 2 + 0], am0, am1, am2, am3, bh0, bh1);
            mma16816(olo[np * 2 + 1], am0, am1, am2, am3, bh2, bh3);
            mma16816(olo[np * 2 + 0], am0, am1, am2, am3, bm0, bm1);
            mma16816(olo[np * 2 + 1], am0, am1, am2, am3, bm2, bm3);
            mma16816(olo[np * 2 + 0], ah0, ah1, ah2, ah3, bl0, bl1);
            mma16816(olo[np * 2 + 1], ah0, ah1, ah2, ah3, bl2, bl3);
            mma16816(olo[np * 2 + 0], al0, al1, al2, al3, bh0, bh1);
            mma16816(olo[np * 2 + 1], al0, al1, al2, al3, bh2, bh3);
        }
        __syncthreads();
    }

    // epilogue: write q as bf16x3 (V side) AND fp16x2 (QK side)
    int r0l = lane >> 2, c2 = (lane & 3) * 2;
    int mrow0 = m0 + warp * 16 + r0l;
    int mrow1 = mrow0 + 8;
#pragma unroll
    for (int j = 0; j < 16; j++) {
        int col = n0 + j * 8 + c2;
        float2 bv = *(const float2*)(bias + col);
        float v0 = ohi[j][0] + olo[j][0] + bv.x;
        float v1 = ohi[j][1] + olo[j][1] + bv.y;
        float v2 = ohi[j][2] + olo[j][2] + bv.x;
        float v3 = ohi[j][3] + olo[j][3] + bv.y;
        uint32_t h, m, l;
        uint32_t fh, fl;
        split3(v0, v1, h, m, l);
        split2(v0, v1, fh, fl);
        uint32_t i0 = (uint32_t)(mrow0 * D_MODEL + col) >> 1;
        ((uint32_t*)g_qh)[i0] = h;
        ((uint32_t*)g_qm)[i0] = m;
        ((uint32_t*)g_ql)[i0] = l;
        ((uint32_t*)g_fh)[i0] = fh;
        ((uint32_t*)g_fl)[i0] = fl;
        split3(v2, v3, h, m, l);
        split2(v2, v3, fh, fl);
        uint32_t i1 = (uint32_t)(mrow1 * D_MODEL + col) >> 1;
        ((uint32_t*)g_qh)[i1] = h;
        ((uint32_t*)g_qm)[i1] = m;
        ((uint32_t*)g_ql)[i1] = l;
        ((uint32_t*)g_fh)[i1] = fh;
        ((uint32_t*)g_fl)[i1] = fl;
    }
}

// ================================================================ GEMM2 (2 products: A_h*W_h + A_h*W_l; A single fp16)
#define F_LVL_B (128 * 48)
#define F_STAGE (3 * F_LVL_B)        // A h | W h | W l
#define GEMM2_SMEM_B (2 * F_STAGE)

__device__ __forceinline__ void gemm2_issue(int c, int buf, uint32_t sbase, int tid,
                                            int m0, int n0) {
    int k0 = c * GKC;
    uint32_t sb = sbase + buf * F_STAGE;
    int row = tid >> 1, half = tid & 1;
    const uint16_t* srcs[3] = {g_ah, g_w2h, g_w2l};
#pragma unroll
    for (int it = 0; it < 3; it++) {
        int grow = (it < 1 ? m0 : n0) + row;
        const uint16_t* sp = srcs[it] + (size_t)grow * D_MODEL + k0 + half * 8;
        uint32_t dst = sb + it * F_LVL_B + row * 48 + half * 16;
        CP_ASYNC16(dst, sp);
    }
    CP_COMMIT();
}

__global__ __launch_bounds__(256, 1) void gemm2_f16_kernel(const float* __restrict__ bias,
                                                           float* __restrict__ outp) {
    extern __shared__ uint8_t gsm[];
    uint32_t sbase = smem_u32(gsm);
    int tid = threadIdx.x, warp = tid >> 5, lane = tid & 31;
    int m0 = blockIdx.y * 128, n0 = blockIdx.x * 128;

    float ohi[16][4], olo[16][4];
#pragma unroll
    for (int j = 0; j < 16; j++) {
        ohi[j][0] = ohi[j][1] = ohi[j][2] = ohi[j][3] = 0.f;
        olo[j][0] = olo[j][1] = olo[j][2] = olo[j][3] = 0.f;
    }

    gemm2_issue(0, 0, sbase, tid, m0, n0);

    uint32_t arow = (uint32_t)((warp * 16 + (lane & 15)) * 48 + (lane >> 4) * 16);
    uint32_t brow = (uint32_t)(((lane & 7) + ((lane >> 4) << 3)) * 48 + ((lane & 8) ? 16 : 0));

    for (int c = 0; c < NCH; c++) {
        int buf = c & 1;
        if (c + 1 < NCH) {
            gemm2_issue(c + 1, buf ^ 1, sbase, tid, m0, n0);
            asm volatile("cp.async.wait_group 1;");
        } else {
            asm volatile("cp.async.wait_group 0;");
        }
        __syncthreads();

        uint32_t ab = sbase + buf * F_STAGE;
        uint32_t bb = ab + F_LVL_B;
        uint32_t ah0, ah1, ah2, ah3;
        ldsm_x4(ah0, ah1, ah2, ah3, ab + arow);
#pragma unroll
        for (int np = 0; np < 8; np++) {
            uint32_t baddr = bb + (uint32_t)(np * 16 * 48) + brow;
            uint32_t bh0, bh1, bh2, bh3, bl0, bl1, bl2, bl3;
            ldsm_x4(bh0, bh1, bh2, bh3, baddr + 0 * F_LVL_B);
            ldsm_x4(bl0, bl1, bl2, bl3, baddr + 1 * F_LVL_B);
            mmah(ohi[np * 2 + 0], ah0, ah1, ah2, ah3, bh0, bh1);
            mmah(ohi[np * 2 + 1], ah0, ah1, ah2, ah3, bh2, bh3);
            mmah(olo[np * 2 + 0], ah0, ah1, ah2, ah3, bl0, bl1);
            mmah(olo[np * 2 + 1], ah0, ah1, ah2, ah3, bl2, bl3);
        }
        __syncthreads();
    }

    int r0l = lane >> 2, c2 = (lane & 3) * 2;
    int mrow0 = m0 + warp * 16 + r0l;
    int mrow1 = mrow0 + 8;
#pragma unroll
    for (int j = 0; j < 16; j++) {
        int col = n0 + j * 8 + c2;
        float2 bv = *(const float2*)(bias + col);
        *(float2*)(outp + (size_t)mrow0 * D_MODEL + col) =
            make_float2(ohi[j][0] + olo[j][0] + bv.x, ohi[j][1] + olo[j][1] + bv.y);
        *(float2*)(outp + (size_t)mrow1 * D_MODEL + col) =
            make_float2(ohi[j][2] + olo[j][2] + bv.x, ohi[j][3] + olo[j][3] + bv.y);
    }
}

// ================================================================ attention
// QK: fp16x2 (3 products). PV: bf16x3 (6 products). Fixed-max softmax.
// 64-query CTAs (128 threads), 2 CTAs/SM.
#define KT_LVL 8192
#define KT_BUF (5 * KT_LVL)     // 2 fp16 levels + 3 bf16 levels = 40960 B
#define ATTN_SMEM (2 * KT_BUF)  // 81920 B

#define P_SCL 0.18033688011111793f
#define P_OFF -23.083120654223414f

__device__ __forceinline__ void attn_stage(uint32_t dstbase, int b, int kbase,
                                           int k0, int r, int h, int tid) {
#pragma unroll
    for (int it = 0; it < 20; it++) {
        int idx = tid + it * 128;          // 0..2559
        int lvl = idx >> 9;                // 0..4
        int rem = idx & 511;
        int key = rem >> 3;
        int c16 = rem & 7;
        int posk = kbase + (k0 + key) * r;
        uint32_t goff = (uint32_t)(b * SEQ + posk) * D_MODEL + h * HD + c16 * 8;
        const uint16_t* src;
        switch (lvl) {
            case 0: src = g_fh + goff; break;
            case 1: src = g_fl + goff; break;
            case 2: src = g_qh + goff; break;
            case 3: src = g_qm + goff; break;
            default: src = g_ql + goff; break;
        }
        uint32_t dst = dstbase + lvl * KT_LVL + SWZ((uint32_t)(key * 128 + c16 * 16));
        CP_ASYNC16(dst, src);
    }
    CP_COMMIT();
}

__global__ __launch_bounds__(128, 2) void attn_mma_kernel() {
    extern __shared__ uint8_t ksm[];

    int inst = blockIdx.y;
    int b, h, seg, r, off, slen;
    if (inst < 32)      { b = inst >> 4; int t = inst & 15; seg = t >> 2; h = t & 3;            r = 1; off = 0; slen = 2048; }
    else if (inst < 48) { int t = inst - 32; b = t >> 3; t &= 7; seg = t >> 2; h = 4 + (t & 3); r = 2; off = 1; slen = 4096; }
    else                { int t = inst - 48; b = t >> 2; h = 8 + (t & 3); seg = 0;              r = 4; off = 2; slen = 8192; }

    int tid = threadIdx.x;
    int warp = tid >> 5, lane = tid & 31;
    int kbase = seg * slen + off;
    int qrow0 = blockIdx.x * 64 + warp * 16;

    uint32_t smb = smem_u32(ksm);

    int r0l = lane >> 2;
    int c2 = (lane & 3) * 2;

    // -------- Q fragments (fp16x2 levels)
    int posq0 = kbase + (qrow0 + r0l) * r;
    int posq1 = kbase + (qrow0 + r0l + 8) * r;
    uint32_t qb0 = (uint32_t)(b * SEQ + posq0) * D_MODEL + h * HD;
    uint32_t qb1 = (uint32_t)(b * SEQ + posq1) * D_MODEL + h * HD;
    uint32_t qh[16], ql[16];
#pragma unroll
    for (int kc = 0; kc < 4; kc++) {
        uint32_t i00 = (qb0 + kc * 16 + c2) >> 1;
        uint32_t i10 = (qb1 + kc * 16 + c2) >> 1;
        uint32_t i01 = (qb0 + kc * 16 + c2 + 8) >> 1;
        uint32_t i11 = (qb1 + kc * 16 + c2 + 8) >> 1;
        qh[kc * 4 + 0] = ((const uint32_t*)g_fh)[i00];
        ql[kc * 4 + 0] = ((const uint32_t*)g_fl)[i00];
        qh[kc * 4 + 1] = ((const uint32_t*)g_fh)[i10];
        ql[kc * 4 + 1] = ((const uint32_t*)g_fl)[i10];
        qh[kc * 4 + 2] = ((const uint32_t*)g_fh)[i01];
        ql[kc * 4 + 2] = ((const uint32_t*)g_fl)[i01];
        qh[kc * 4 + 3] = ((const uint32_t*)g_fh)[i11];
        ql[kc * 4 + 3] = ((const uint32_t*)g_fl)[i11];
    }

    float ohi[8][4], olo[8][4];
#pragma unroll
    for (int j = 0; j < 8; j++) {
        ohi[j][0] = ohi[j][1] = ohi[j][2] = ohi[j][3] = 0.f;
        olo[j][0] = olo[j][1] = olo[j][2] = olo[j][3] = 0.f;
    }
    float l0 = 0.f, l1 = 0.f;

    attn_stage(smb, b, kbase, 0, r, h, tid);

    int buf = 0;
    for (int kt = 0; kt < SE / 64; kt++) {
        if (kt + 1 < SE / 64) {
            attn_stage(smb + (buf ^ 1) * KT_BUF, b, kbase, (kt + 1) * 64, r, h, tid);
            asm volatile("cp.async.wait_group 1;");
        } else {
            asm volatile("cp.async.wait_group 0;");
        }
        __syncthreads();

        uint32_t kh_b = smb + buf * KT_BUF;          // fp16 h
        uint32_t kl_b = kh_b + KT_LVL;               // fp16 l
        uint32_t vh_b = kh_b + 2 * KT_LVL;           // bf16 h
        uint32_t vm_b = kh_b + 3 * KT_LVL;           // bf16 m
        uint32_t vl_b = kh_b + 4 * KT_LVL;           // bf16 l

        // -------- S = Q K^T : fp16x2, split accumulators
        float shi[8][4], slo[8][4];
#pragma unroll
        for (int j = 0; j < 8; j++) {
            shi[j][0] = shi[j][1] = shi[j][2] = shi[j][3] = 0.f;
            slo[j][0] = slo[j][1] = slo[j][2] = slo[j][3] = 0.f;
        }
#pragma unroll
        for (int kc = 0; kc < 4; kc++) {
            uint32_t a0h = qh[kc * 4 + 0], a1h = qh[kc * 4 + 1],
                     a2h = qh[kc * 4 + 2], a3h = qh[kc * 4 + 3];
            uint32_t a0l = ql[kc * 4 + 0], a1l = ql[kc * 4 + 1],
                     a2l = ql[kc * 4 + 2], a3l = ql[kc * 4 + 3];
#pragma unroll
            for (int np = 0; np < 4; np++) {
                int key = np * 16 + (lane & 7) + ((lane >> 4) << 3);
                int dim = kc * 16 + (lane & 8);
                uint32_t so = SWZ((uint32_t)(key * 128 + dim * 2));
                uint32_t bh0, bh1, bh2, bh3, bl0, bl1, bl2, bl3;
                ldsm_x4(bh0, bh1, bh2, bh3, kh_b + so);
                ldsm_x4(bl0, bl1, bl2, bl3, kl_b + so);
                mmah(shi[np * 2 + 0], a0h, a1h, a2h, a3h, bh0, bh1);
                mmah(shi[np * 2 + 1], a0h, a1h, a2h, a3h, bh2, bh3);
                mmah(slo[np * 2 + 0], a0h, a1h, a2h, a3h, bl0, bl1);
                mmah(slo[np * 2 + 1], a0h, a1h, a2h, a3h, bl2, bl3);
                mmah(slo[np * 2 + 0], a0l, a1l, a2l, a3l, bh0, bh1);
                mmah(slo[np * 2 + 1], a0l, a1l, a2l, a3l, bh2, bh3);
            }
        }

        // -------- fixed-max softmax: p = exp2(ssum*P_SCL + P_OFF), bf16x3 split
        uint32_t pah[8], pam[8], pal[8], pbh[8], pbm[8], pbl[8];
#pragma unroll
        for (int j = 0; j < 8; j++) {
            float p0 = fexp2(fmaf(shi[j][0] + slo[j][0], P_SCL, P_OFF));
            float p1 = fexp2(fmaf(shi[j][1] + slo[j][1], P_SCL, P_OFF));
            float p2 = fexp2(fmaf(shi[j][2] + slo[j][2], P_SCL, P_OFF));
            float p3 = fexp2(fmaf(shi[j][3] + slo[j][3], P_SCL, P_OFF));
            l0 += p0 + p1;
            l1 += p2 + p3;
            split3(p0, p1, pah[j], pam[j], pal[j]);
            split3(p2, p3, pbh[j], pbm[j], pbl[j]);
        }

        // -------- O += P V : bf16x3, split accumulators (interleaved chains)
#pragma unroll
        for (int kk = 0; kk < 4; kk++) {
            uint32_t a0h = pah[kk * 2], a1h = pbh[kk * 2],
                     a2h = pah[kk * 2 + 1], a3h = pbh[kk * 2 + 1];
            uint32_t a0m = pam[kk * 2], a1m = pbm[kk * 2],
                     a2m = pam[kk * 2 + 1], a3m = pbm[kk * 2 + 1];
            uint32_t a0l = pal[kk * 2], a1l = pbl[kk * 2],
                     a2l = pal[kk * 2 + 1], a3l = pbl[kk * 2 + 1];
#pragma unroll
            for (int np = 0; np < 4; np++) {
                int key = kk * 16 + (lane & 7) + (lane & 8);
                int dim = np * 16 + ((lane >> 4) << 3);
                uint32_t so = SWZ((uint32_t)(key * 128 + dim * 2));
                uint32_t bh0, bh1, bh2, bh3, bm0, bm1, bm2, bm3, bl0, bl1, bl2, bl3;
                ldsm_x4_t(bh0, bh1, bh2, bh3, vh_b + so);
                ldsm_x4_t(bm0, bm1, bm2, bm3, vm_b + so);
                ldsm_x4_t(bl0, bl1, bl2, bl3, vl_b + so);
                mma16816(ohi[np * 2 + 0], a0h, a1h, a2h, a3h, bh0, bh1);
                mma16816(ohi[np * 2 + 1], a0h, a1h, a2h, a3h, bh2, bh3);
                mma16816(olo[np * 2 + 0], a0h, a1h, a2h, a3h, bm0, bm1);
                mma16816(olo[np * 2 + 1], a0h, a1h, a2h, a3h, bm2, bm3);
                mma16816(olo[np * 2 + 0], a0m, a1m, a2m, a3m, bh0, bh1);
                mma16816(olo[np * 2 + 1], a0m, a1m, a2m, a3m, bh2, bh3);
                mma16816(olo[np * 2 + 0], a0m, a1m, a2m, a3m, bm0, bm1);
                mma16816(olo[np * 2 + 1], a0m, a1m, a2m, a3m, bm2, bm3);
                mma16816(olo[np * 2 + 0], a0h, a1h, a2h, a3h, bl0, bl1);
                mma16816(olo[np * 2 + 1], a0h, a1h, a2h, a3h, bl2, bl3);
                mma16816(olo[np * 2 + 0], a0l, a1l, a2l, a3l, bh0, bh1);
                mma16816(olo[np * 2 + 1], a0l, a1l, a2l, a3l, bh2, bh3);
            }
        }
        __syncthreads();
        buf ^= 1;
    }

    // -------- finalize
    l0 += __shfl_xor_sync(0xffffffffu, l0, 1);
    l0 += __shfl_xor_sync(0xffffffffu, l0, 2);
    l1 += __shfl_xor_sync(0xffffffffu, l1, 1);
    l1 += __shfl_xor_sync(0xffffffffu, l1, 2);
    float inv0 = 1.0f / l0, inv1 = 1.0f / l1;
    float* op0 = g_o + ((size_t)b * SEQ + posq0) * D_MODEL + h * HD;
    float* op1 = g_o + ((size_t)b * SEQ + posq1) * D_MODEL + h * HD;
#pragma unroll
    for (int j = 0; j < 8; j++) {
        *(float2*)(op0 + j * 8 + c2) = make_float2((ohi[j][0] + olo[j][0]) * inv0,
                                                   (ohi[j][1] + olo[j][1]) * inv0);
        *(float2*)(op1 + j * 8 + c2) = make_float2((ohi[j][2] + olo[j][2]) * inv1,
                                                   (ohi[j][3] + olo[j][3]) * inv1);
    }
}

// ---------------------------------------------------------------- renorm sums
__global__ __launch_bounds__(256) void reduce1_kernel() {
    int bc = blockIdx.x;
    int b = bc / 3, cb = bc % 3;
    int c = cb * 256 + threadIdx.x;
    size_t base = (size_t)(b * SEQ + blockIdx.y * 256) * D_MODEL + c;
    float acc = 0.f;
    for (int rr = 0; rr < 256; rr++) acc += g_o[base + (size_t)rr * D_MODEL];
    g_part[blockIdx.y][b * D_MODEL + c] = acc;
}
__global__ void reduce2_kernel() {
    int idx = blockIdx.x * 256 + threadIdx.x;
    float acc = 0.f;
#pragma unroll
    for (int j = 0; j < 32; j++) acc += g_part[j][idx];
    g_sum[idx] = acc;
}

// ---------------------------------------------------------------- layernorm (writes fp16 A for gemm2)
__device__ __forceinline__ float blk_sum(float v, float* sh) {
    int lane = threadIdx.x & 31, w = threadIdx.x >> 5;
#pragma unroll
    for (int off = 16; off; off >>= 1) v += __shfl_xor_sync(0xffffffffu, v, off);
    if (lane == 0) sh[w] = v;
    __syncthreads();
    if (threadIdx.x == 0) {
        float t = 0.f;
#pragma unroll
        for (int i = 0; i < 8; i++) t += sh[i];
        sh[8] = t;
    }
    __syncthreads();
    return sh[8];
}

__global__ __launch_bounds__(256) void ln_kernel(const float* __restrict__ gamma,
                                                 const float* __restrict__ beta) {
    __shared__ float sh[9];
    int row = blockIdx.x;
    int b = row >> 13;
    const float* in = g_o + (size_t)row * D_MODEL;
    float v[3];
    float s = 0.f;
#pragma unroll
    for (int i = 0; i < 3; i++) {
        int c = threadIdx.x + i * 256;
        float val = in[c] / (3.0f * g_sum[b * D_MODEL + c]);
        v[i] = val;
        s += val;
    }
    float mean = blk_sum(s, sh) * (1.0f / 768.0f);
    float vs = 0.f;
#pragma unroll
    for (int i = 0; i < 3; i++) {
        float d = v[i] - mean;
        vs += d * d;
    }
    float var = blk_sum(vs, sh) * (1.0f / 768.0f);
    float rstd = rsqrtf(var + 1e-5f);
#pragma unroll
    for (int i = 0; i < 3; i++) {
        int c = threadIdx.x + i * 256;
        float outv = (v[i] - mean) * rstd * gamma[c] + beta[c];
        g_ah[(size_t)row * D_MODEL + c] = __half_as_ushort(__float2half_rn(outv));
    }
}

// ---------------------------------------------------------------- launch
extern "C" void kernel_launch(void* const* d_in, const int* in_sizes, int n_in,
                              void* d_out, int out_size) {
    const float* x      = (const float*)d_in[0];
    const float* w_in   = (const float*)d_in[1];
    const float* b_in   = (const float*)d_in[2];
    const float* w_out  = (const float*)d_in[3];
    const float* b_out  = (const float*)d_in[4];
    const float* gamma  = (const float*)d_in[5];
    const float* beta   = (const float*)d_in[6];
    float* out = (float*)d_out;

    cudaFuncSetAttribute(gemm_mma_kernel, cudaFuncAttributeMaxDynamicSharedMemorySize,
                         GEMM_SMEM_B);
    cudaFuncSetAttribute(gemm2_f16_kernel, cudaFuncAttributeMaxDynamicSharedMemorySize,
                         GEMM2_SMEM_B);
    cudaFuncSetAttribute(attn_mma_kernel, cudaFuncAttributeMaxDynamicSharedMemorySize,
                         ATTN_SMEM);

    const int nbig4 = NTOK * D_MODEL / 4;
    const int nw4 = D_MODEL * D_MODEL / 4;

    zero_o_kernel<<<3072, 256>>>();
    split_kernel<<<(nbig4 + 255) / 256, 256>>>(x, nbig4, 0);
    split_kernel<<<(nw4 + 255) / 256, 256>>>(w_in, nw4, 1);
    split2_kernel<<<(nw4 + 255) / 256, 256>>>(w_out, nw4);
    gemm_mma_kernel<<<dim3(6, 128), 256, GEMM_SMEM_B>>>(b_in);
    attn_mma_kernel<<<dim3(32, 56), 128, ATTN_SMEM>>>();
    reduce1_kernel<<<dim3(6, 32), 256>>>();
    reduce2_kernel<<<6, 256>>>();
    ln_kernel<<<NTOK, 256>>>(gamma, beta);
    gemm2_f16_kernel<<<dim3(6, 128), 256, GEMM2_SMEM_B>>>(b_out, out);
}

// round 14
// speedup vs baseline: 1.9104x; 1.0576x over previous
#include <cuda_runtime.h>
#include <cuda_bf16.h>
#include <cuda_fp16.h>
#include <stdint.h>
#include <math.h>

#define D_MODEL 768
#define NHEADS 12
#define HD 64
#define BATCH 2
#define SEQ 8192
#define NTOK (BATCH * SEQ)
#define SE 2048
#define LOG2E 1.4426950408889634f

// Scratch (allocation-free rule: __device__ globals)
__device__ float g_o[NTOK * D_MODEL];
__device__ float g_part[32][BATCH * D_MODEL];
__device__ float g_sum[BATCH * D_MODEL];
// g_a*: bf16x3 of x for gemm1; g_ah later holds fp16 of ln-out for gemm2
__device__ uint16_t g_ah[NTOK * D_MODEL], g_am[NTOK * D_MODEL], g_al[NTOK * D_MODEL];
// projected q: bf16x3 (V side of PV; renorm-amplified O-path)
__device__ uint16_t g_qh[NTOK * D_MODEL], g_qm[NTOK * D_MODEL], g_ql[NTOK * D_MODEL];
// projected q: fp16x2 (QK S-path)
__device__ uint16_t g_fh[NTOK * D_MODEL], g_fl[NTOK * D_MODEL];
// weights: w1 bf16x3 (amplified), w2 fp16x2 (un-amplified)
__device__ uint16_t g_w1h[D_MODEL * D_MODEL], g_w1m[D_MODEL * D_MODEL], g_w1l[D_MODEL * D_MODEL];
__device__ uint16_t g_w2h[D_MODEL * D_MODEL], g_w2l[D_MODEL * D_MODEL];

// ================================================================ helpers
__device__ __forceinline__ uint32_t smem_u32(const void* p) {
    uint32_t a;
    asm("{ .reg .u64 t; cvta.to.shared.u64 t, %1; cvt.u32.u64 %0, t; }" : "=r"(a) : "l"(p));
    return a;
}

#define SWZ(off) ((off) ^ (((off) >> 3) & 0x70))

__device__ __forceinline__ void ldsm_x4(uint32_t& r0, uint32_t& r1, uint32_t& r2,
                                        uint32_t& r3, uint32_t addr) {
    asm volatile("ldmatrix.sync.aligned.m8n8.x4.shared.b16 {%0,%1,%2,%3}, [%4];"
                 : "=r"(r0), "=r"(r1), "=r"(r2), "=r"(r3) : "r"(addr));
}
__device__ __forceinline__ void ldsm_x4_t(uint32_t& r0, uint32_t& r1, uint32_t& r2,
                                          uint32_t& r3, uint32_t addr) {
    asm volatile("ldmatrix.sync.aligned.m8n8.x4.trans.shared.b16 {%0,%1,%2,%3}, [%4];"
                 : "=r"(r0), "=r"(r1), "=r"(r2), "=r"(r3) : "r"(addr));
}
// bf16 mma
__device__ __forceinline__ void mma16816(float* c, uint32_t a0, uint32_t a1, uint32_t a2,
                                         uint32_t a3, uint32_t b0, uint32_t b1) {
    asm volatile(
        "mma.sync.aligned.m16n8k16.row.col.f32.bf16.bf16.f32 "
        "{%0,%1,%2,%3}, {%4,%5,%6,%7}, {%8,%9}, {%0,%1,%2,%3};"
        : "+f"(c[0]), "+f"(c[1]), "+f"(c[2]), "+f"(c[3])
        : "r"(a0), "r"(a1), "r"(a2), "r"(a3), "r"(b0), "r"(b1));
}
// fp16 mma
__device__ __forceinline__ void mmah(float* c, uint32_t a0, uint32_t a1, uint32_t a2,
                                     uint32_t a3, uint32_t b0, uint32_t b1) {
    asm volatile(
        "mma.sync.aligned.m16n8k16.row.col.f32.f16.f16.f32 "
        "{%0,%1,%2,%3}, {%4,%5,%6,%7}, {%8,%9}, {%0,%1,%2,%3};"
        : "+f"(c[0]), "+f"(c[1]), "+f"(c[2]), "+f"(c[3])
        : "r"(a0), "r"(a1), "r"(a2), "r"(a3), "r"(b0), "r"(b1));
}
#define CP_ASYNC16(dst, src) \
    asm volatile("cp.async.cg.shared.global [%0], [%1], 16;" :: "r"(dst), "l"(src))
#define CP_COMMIT() asm volatile("cp.async.commit_group;")

// packed bf16x3 split: cvt.rn.bf16x2.f32 converts+packs both halves in one
// instruction (hi=b, lo=a, matching pack_bf2); residual recovery via exact
// bit ops (bf16<<16 IS the f32 value). Bit-identical to the scalar version.
__device__ __forceinline__ void split3(float a, float b,
                                       uint32_t& h, uint32_t& m, uint32_t& l) {
    uint32_t hp;
    asm("cvt.rn.bf16x2.f32 %0, %1, %2;" : "=r"(hp) : "f"(b), "f"(a));
    float ra = a - __uint_as_float(hp << 16);
    float rb = b - __uint_as_float(hp & 0xffff0000u);
    uint32_t mp;
    asm("cvt.rn.bf16x2.f32 %0, %1, %2;" : "=r"(mp) : "f"(rb), "f"(ra));
    float ra2 = ra - __uint_as_float(mp << 16);
    float rb2 = rb - __uint_as_float(mp & 0xffff0000u);
    uint32_t lp;
    asm("cvt.rn.bf16x2.f32 %0, %1, %2;" : "=r"(lp) : "f"(rb2), "f"(ra2));
    h = hp; m = mp; l = lp;
}
__device__ __forceinline__ uint32_t pack_h2(__half lo, __half hi) {
    return ((uint32_t)__half_as_ushort(hi) << 16) | (uint32_t)__half_as_ushort(lo);
}
__device__ __forceinline__ void split2(float a, float b, uint32_t& h, uint32_t& l) {
    __half ha = __float2half_rn(a), hb = __float2half_rn(b);
    __half la = __float2half_rn(a - __half2float(ha));
    __half lb = __float2half_rn(b - __half2float(hb));
    h = pack_h2(ha, hb);
    l = pack_h2(la, lb);
}

// MUFU exp2 (1 issue slot; max rel err ~2^-22, same class as the old poly)
__device__ __forceinline__ float ex2(float f) {
    float r;
    asm("ex2.approx.ftz.f32 %0, %1;" : "=f"(r) : "f"(f));
    return r;
}

// ---------------------------------------------------------------- zero fill
// Only channels [256,768) need zeroing: channels 0-255 (heads 0-3, r=1 group)
// are written at every position by the attention kernel.
__global__ void zero_o_kernel() {
    int idx = blockIdx.x * blockDim.x + threadIdx.x;
    const int per_tok = 512 / 4;
    const int n4 = NTOK * per_tok;
    float4 z = make_float4(0.f, 0.f, 0.f, 0.f);
    for (int i = idx; i < n4; i += gridDim.x * blockDim.x) {
        int tok = i / per_tok;
        int c4 = i % per_tok;
        ((float4*)(g_o + (size_t)tok * D_MODEL + 256))[c4] = z;
    }
}

// ---------------------------------------------------------------- splits
__global__ __launch_bounds__(256) void split_kernel(const float* __restrict__ src,
                                                    int n4, int sel) {
    int i = blockIdx.x * blockDim.x + threadIdx.x;
    if (i >= n4) return;
    float4 v = ((const float4*)src)[i];
    uint32_t h0, m0, l0, h1, m1, l1;
    split3(v.x, v.y, h0, m0, l0);
    split3(v.z, v.w, h1, m1, l1);
    uint2* dh; uint2* dm; uint2* dl;
    if (sel == 0) { dh = (uint2*)g_ah;  dm = (uint2*)g_am;  dl = (uint2*)g_al; }
    else          { dh = (uint2*)g_w1h; dm = (uint2*)g_w1m; dl = (uint2*)g_w1l; }
    dh[i] = make_uint2(h0, h1);
    dm[i] = make_uint2(m0, m1);
    dl[i] = make_uint2(l0, l1);
}
__global__ __launch_bounds__(256) void split2_kernel(const float* __restrict__ src, int n4) {
    int i = blockIdx.x * blockDim.x + threadIdx.x;
    if (i >= n4) return;
    float4 v = ((const float4*)src)[i];
    uint32_t h0, l0, h1, l1;
    split2(v.x, v.y, h0, l0);
    split2(v.z, v.w, h1, l1);
    ((uint2*)g_w2h)[i] = make_uint2(h0, h1);
    ((uint2*)g_w2l)[i] = make_uint2(l0, l1);
}

// ================================================================ GEMM1 (bf16x3, 6 products) -> q bf16x3 + fp16x2
#define GKC 16
#define NCH (D_MODEL / GKC)       // 48
#define G_LVL_B (128 * 48)
#define G_OP_B (3 * G_LVL_B)
#define G_STAGE (2 * G_OP_B)
#define GEMM_SMEM_B (2 * G_STAGE)

__device__ __forceinline__ void gemm_issue(int c, int buf, uint32_t sbase, int tid,
                                           int m0, int n0) {
    int k0 = c * GKC;
    uint32_t sb = sbase + buf * G_STAGE;
    int row = tid >> 1, half = tid & 1;
    const uint16_t* srcs[6] = {g_ah, g_am, g_al, g_w1h, g_w1m, g_w1l};
#pragma unroll
    for (int it = 0; it < 6; it++) {
        int grow = (it < 3 ? m0 : n0) + row;
        const uint16_t* sp = srcs[it] + (size_t)grow * D_MODEL + k0 + half * 8;
        uint32_t dst = sb + (it < 3 ? 0 : G_OP_B) + (it % 3) * G_LVL_B + row * 48 + half * 16;
        CP_ASYNC16(dst, sp);
    }
    CP_COMMIT();
}

__global__ __launch_bounds__(256, 1) void gemm_mma_kernel(const float* __restrict__ bias) {
    extern __shared__ uint8_t gsm[];
    uint32_t sbase = smem_u32(gsm);
    int tid = threadIdx.x, warp = tid >> 5, lane = tid & 31;
    int m0 = blockIdx.y * 128, n0 = blockIdx.x * 128;

    float ohi[16][4], olo[16][4];
#pragma unroll
    for (int j = 0; j < 16; j++) {
        ohi[j][0] = ohi[j][1] = ohi[j][2] = ohi[j][3] = 0.f;
        olo[j][0] = olo[j][1] = olo[j][2] = olo[j][3] = 0.f;
    }

    gemm_issue(0, 0, sbase, tid, m0, n0);

    uint32_t arow = (uint32_t)((warp * 16 + (lane & 15)) * 48 + (lane >> 4) * 16);
    uint32_t brow = (uint32_t)(((lane & 7) + ((lane >> 4) << 3)) * 48 + ((lane & 8) ? 16 : 0));

    for (int c = 0; c < NCH; c++) {
        int buf = c & 1;
        if (c + 1 < NCH) {
            gemm_issue(c + 1, buf ^ 1, sbase, tid, m0, n0);
            asm volatile("cp.async.wait_group 1;");
        } else {
            asm volatile("cp.async.wait_group 0;");
        }
        __syncthreads();

        uint32_t ab = sbase + buf * G_STAGE;
        uint32_t bb = ab + G_OP_B;
        uint32_t ah0, ah1, ah2, ah3, am0, am1, am2, am3, al0, al1, al2, al3;
        ldsm_x4(ah0, ah1, ah2, ah3, ab + 0 * G_LVL_B + arow);
        ldsm_x4(am0, am1, am2, am3, ab + 1 * G_LVL_B + arow);
        ldsm_x4(al0, al1, al2, al3, ab + 2 * G_LVL_B + arow);
#pragma unroll
        for (int np = 0; np < 8; np++) {
            uint32_t baddr = bb + (uint32_t)(np * 16 * 48) + brow;
            uint32_t bh0, bh1, bh2, bh3, bm0, bm1, bm2, bm3, bl0, bl1, bl2, bl3;
            ldsm_x4(bh0, bh1, bh2, bh3, baddr + 0 * G_LVL_B);
            ldsm_x4(bm0, bm1, bm2, bm3, baddr + 1 * G_LVL_B);
            ldsm_x4(bl0, bl1, bl2, bl3, baddr + 2 * G_LVL_B);
            mma16816(ohi[np * 2 + 0], ah0, ah1, ah2, ah3, bh0, bh1);
            mma16816(ohi[np * 2 + 1], ah0, ah1, ah2, ah3, bh2, bh3);
            mma16816(olo[np * 2 + 0], ah0, ah1, ah2, ah3, bm0, bm1);
            mma16816(olo[np * 2 + 1], ah0, ah1, ah2, ah3, bm2, bm3);
            mma16816(olo[np * 2 + 0], am0, am1, am2, am3, bh0, bh1);
            mma16816(olo[np * 2 + 1], am0, am1, am2, am3, bh2, bh3);
            mma16816(olo[np * 2 + 0], am0, am1, am2, am3, bm0, bm1);
            mma16816(olo[np * 2 + 1], am0, am1, am2, am3, bm2, bm3);
            mma16816(olo[np * 2 + 0], ah0, ah1, ah2, ah3, bl0, bl1);
            mma16816(olo[np * 2 + 1], ah0, ah1, ah2, ah3, bl2, bl3);
            mma16816(olo[np * 2 + 0], al0, al1, al2, al3, bh0, bh1);
            mma16816(olo[np * 2 + 1], al0, al1, al2, al3, bh2, bh3);
        }
        __syncthreads();
    }

    // epilogue: write q as bf16x3 (V side) AND fp16x2 (QK side)
    int r0l = lane >> 2, c2 = (lane & 3) * 2;
    int mrow0 = m0 + warp * 16 + r0l;
    int mrow1 = mrow0 + 8;
#pragma unroll
    for (int j = 0; j < 16; j++) {
        int col = n0 + j * 8 + c2;
        float2 bv = *(const float2*)(bias + col);
        float v0 = ohi[j][0] + olo[j][0] + bv.x;
        float v1 = ohi[j][1] + olo[j][1] + bv.y;
        float v2 = ohi[j][2] + olo[j][2] + bv.x;
        float v3 = ohi[j][3] + olo[j][3] + bv.y;
        uint32_t h, m, l;
        uint32_t fh, fl;
        split3(v0, v1, h, m, l);
        split2(v0, v1, fh, fl);
        uint32_t i0 = (uint32_t)(mrow0 * D_MODEL + col) >> 1;
        ((uint32_t*)g_qh)[i0] = h;
        ((uint32_t*)g_qm)[i0] = m;
        ((uint32_t*)g_ql)[i0] = l;
        ((uint32_t*)g_fh)[i0] = fh;
        ((uint32_t*)g_fl)[i0] = fl;
        split3(v2, v3, h, m, l);
        split2(v2, v3, fh, fl);
        uint32_t i1 = (uint32_t)(mrow1 * D_MODEL + col) >> 1;
        ((uint32_t*)g_qh)[i1] = h;
        ((uint32_t*)g_qm)[i1] = m;
        ((uint32_t*)g_ql)[i1] = l;
        ((uint32_t*)g_fh)[i1] = fh;
        ((uint32_t*)g_fl)[i1] = fl;
    }
}

// ================================================================ GEMM2 (2 products: A_h*W_h + A_h*W_l; A single fp16)
#define F_LVL_B (128 * 48)
#define F_STAGE (3 * F_LVL_B)
#define GEMM2_SMEM_B (2 * F_STAGE)

__device__ __forceinline__ void gemm2_issue(int c, int buf, uint32_t sbase, int tid,
                                            int m0, int n0) {
    int k0 = c * GKC;
    uint32_t sb = sbase + buf * F_STAGE;
    int row = tid >> 1, half = tid & 1;
    const uint16_t* srcs[3] = {g_ah, g_w2h, g_w2l};
#pragma unroll
    for (int it = 0; it < 3; it++) {
        int grow = (it < 1 ? m0 : n0) + row;
        const uint16_t* sp = srcs[it] + (size_t)grow * D_MODEL + k0 + half * 8;
        uint32_t dst = sb + it * F_LVL_B + row * 48 + half * 16;
        CP_ASYNC16(dst, sp);
    }
    CP_COMMIT();
}

__global__ __launch_bounds__(256, 1) void gemm2_f16_kernel(const float* __restrict__ bias,
                                                           float* __restrict__ outp) {
    extern __shared__ uint8_t gsm[];
    uint32_t sbase = smem_u32(gsm);
    int tid = threadIdx.x, warp = tid >> 5, lane = tid & 31;
    int m0 = blockIdx.y * 128, n0 = blockIdx.x * 128;

    float ohi[16][4], olo[16][4];
#pragma unroll
    for (int j = 0; j < 16; j++) {
        ohi[j][0] = ohi[j][1] = ohi[j][2] = ohi[j][3] = 0.f;
        olo[j][0] = olo[j][1] = olo[j][2] = olo[j][3] = 0.f;
    }

    gemm2_issue(0, 0, sbase, tid, m0, n0);

    uint32_t arow = (uint32_t)((warp * 16 + (lane & 15)) * 48 + (lane >> 4) * 16);
    uint32_t brow = (uint32_t)(((lane & 7) + ((lane >> 4) << 3)) * 48 + ((lane & 8) ? 16 : 0));

    for (int c = 0; c < NCH; c++) {
        int buf = c & 1;
        if (c + 1 < NCH) {
            gemm2_issue(c + 1, buf ^ 1, sbase, tid, m0, n0);
            asm volatile("cp.async.wait_group 1;");
        } else {
            asm volatile("cp.async.wait_group 0;");
        }
        __syncthreads();

        uint32_t ab = sbase + buf * F_STAGE;
        uint32_t bb = ab + F_LVL_B;
        uint32_t ah0, ah1, ah2, ah3;
        ldsm_x4(ah0, ah1, ah2, ah3, ab + arow);
#pragma unroll
        for (int np = 0; np < 8; np++) {
            uint32_t baddr = bb + (uint32_t)(np * 16 * 48) + brow;
            uint32_t bh0, bh1, bh2, bh3, bl0, bl1, bl2, bl3;
            ldsm_x4(bh0, bh1, bh2, bh3, baddr + 0 * F_LVL_B);
            ldsm_x4(bl0, bl1, bl2, bl3, baddr + 1 * F_LVL_B);
            mmah(ohi[np * 2 + 0], ah0, ah1, ah2, ah3, bh0, bh1);
            mmah(ohi[np * 2 + 1], ah0, ah1, ah2, ah3, bh2, bh3);
            mmah(olo[np * 2 + 0], ah0, ah1, ah2, ah3, bl0, bl1);
            mmah(olo[np * 2 + 1], ah0, ah1, ah2, ah3, bl2, bl3);
        }
        __syncthreads();
    }

    int r0l = lane >> 2, c2 = (lane & 3) * 2;
    int mrow0 = m0 + warp * 16 + r0l;
    int mrow1 = mrow0 + 8;
#pragma unroll
    for (int j = 0; j < 16; j++) {
        int col = n0 + j * 8 + c2;
        float2 bv = *(const float2*)(bias + col);
        *(float2*)(outp + (size_t)mrow0 * D_MODEL + col) =
            make_float2(ohi[j][0] + olo[j][0] + bv.x, ohi[j][1] + olo[j][1] + bv.y);
        *(float2*)(outp + (size_t)mrow1 * D_MODEL + col) =
            make_float2(ohi[j][2] + olo[j][2] + bv.x, ohi[j][3] + olo[j][3] + bv.y);
    }
}

// ================================================================ attention
// QK: fp16x2 (3 products). PV: bf16x3 (6 products). Fixed-max softmax via MUFU.
// 64-query CTAs (128 threads), 2 CTAs/SM.
#define KT_LVL 8192
#define KT_BUF (5 * KT_LVL)
#define ATTN_SMEM (2 * KT_BUF)

#define P_SCL 0.18033688011111793f
#define P_OFF -23.083120654223414f

__device__ __forceinline__ void attn_stage(uint32_t dstbase, int b, int kbase,
                                           int k0, int r, int h, int tid) {
#pragma unroll
    for (int it = 0; it < 20; it++) {
        int idx = tid + it * 128;
        int lvl = idx >> 9;
        int rem = idx & 511;
        int key = rem >> 3;
        int c16 = rem & 7;
        int posk = kbase + (k0 + key) * r;
        uint32_t goff = (uint32_t)(b * SEQ + posk) * D_MODEL + h * HD + c16 * 8;
        const uint16_t* src;
        switch (lvl) {
            case 0: src = g_fh + goff; break;
            case 1: src = g_fl + goff; break;
            case 2: src = g_qh + goff; break;
            case 3: src = g_qm + goff; break;
            default: src = g_ql + goff; break;
        }
        uint32_t dst = dstbase + lvl * KT_LVL + SWZ((uint32_t)(key * 128 + c16 * 16));
        CP_ASYNC16(dst, src);
    }
    CP_COMMIT();
}

__global__ __launch_bounds__(128, 2) void attn_mma_kernel() {
    extern __shared__ uint8_t ksm[];

    int inst = blockIdx.y;
    int b, h, seg, r, off, slen;
    if (inst < 32)      { b = inst >> 4; int t = inst & 15; seg = t >> 2; h = t & 3;            r = 1; off = 0; slen = 2048; }
    else if (inst < 48) { int t = inst - 32; b = t >> 3; t &= 7; seg = t >> 2; h = 4 + (t & 3); r = 2; off = 1; slen = 4096; }
    else                { int t = inst - 48; b = t >> 2; h = 8 + (t & 3); seg = 0;              r = 4; off = 2; slen = 8192; }

    int tid = threadIdx.x;
    int warp = tid >> 5, lane = tid & 31;
    int kbase = seg * slen + off;
    int qrow0 = blockIdx.x * 64 + warp * 16;

    uint32_t smb = smem_u32(ksm);

    int r0l = lane >> 2;
    int c2 = (lane & 3) * 2;

    // -------- Q fragments (fp16x2 levels)
    int posq0 = kbase + (qrow0 + r0l) * r;
    int posq1 = kbase + (qrow0 + r0l + 8) * r;
    uint32_t qb0 = (uint32_t)(b * SEQ + posq0) * D_MODEL + h * HD;
    uint32_t qb1 = (uint32_t)(b * SEQ + posq1) * D_MODEL + h * HD;
    uint32_t qh[16], ql[16];
#pragma unroll
    for (int kc = 0; kc < 4; kc++) {
        uint32_t i00 = (qb0 + kc * 16 + c2) >> 1;
        uint32_t i10 = (qb1 + kc * 16 + c2) >> 1;
        uint32_t i01 = (qb0 + kc * 16 + c2 + 8) >> 1;
        uint32_t i11 = (qb1 + kc * 16 + c2 + 8) >> 1;
        qh[kc * 4 + 0] = ((const uint32_t*)g_fh)[i00];
        ql[kc * 4 + 0] = ((const uint32_t*)g_fl)[i00];
        qh[kc * 4 + 1] = ((const uint32_t*)g_fh)[i10];
        ql[kc * 4 + 1] = ((const uint32_t*)g_fl)[i10];
        qh[kc * 4 + 2] = ((const uint32_t*)g_fh)[i01];
        ql[kc * 4 + 2] = ((const uint32_t*)g_fl)[i01];
        qh[kc * 4 + 3] = ((const uint32_t*)g_fh)[i11];
        ql[kc * 4 + 3] = ((const uint32_t*)g_fl)[i11];
    }

    float ohi[8][4], olo[8][4];
#pragma unroll
    for (int j = 0; j < 8; j++) {
        ohi[j][0] = ohi[j][1] = ohi[j][2] = ohi[j][3] = 0.f;
        olo[j][0] = olo[j][1] = olo[j][2] = olo[j][3] = 0.f;
    }
    float l0 = 0.f, l1 = 0.f;

    attn_stage(smb, b, kbase, 0, r, h, tid);

    int buf = 0;
    for (int kt = 0; kt < SE / 64; kt++) {
        if (kt + 1 < SE / 64) {
            attn_stage(smb + (buf ^ 1) * KT_BUF, b, kbase, (kt + 1) * 64, r, h, tid);
            asm volatile("cp.async.wait_group 1;");
        } else {
            asm volatile("cp.async.wait_group 0;");
        }
        __syncthreads();

        uint32_t kh_b = smb + buf * KT_BUF;
        uint32_t kl_b = kh_b + KT_LVL;
        uint32_t vh_b = kh_b + 2 * KT_LVL;
        uint32_t vm_b = kh_b + 3 * KT_LVL;
        uint32_t vl_b = kh_b + 4 * KT_LVL;

        // -------- S = Q K^T : fp16x2, split accumulators
        float shi[8][4], slo[8][4];
#pragma unroll
        for (int j = 0; j < 8; j++) {
            shi[j][0] = shi[j][1] = shi[j][2] = shi[j][3] = 0.f;
            slo[j][0] = slo[j][1] = slo[j][2] = slo[j][3] = 0.f;
        }
#pragma unroll
        for (int kc = 0; kc < 4; kc++) {
            uint32_t a0h = qh[kc * 4 + 0], a1h = qh[kc * 4 + 1],
                     a2h = qh[kc * 4 + 2], a3h = qh[kc * 4 + 3];
            uint32_t a0l = ql[kc * 4 + 0], a1l = ql[kc * 4 + 1],
                     a2l = ql[kc * 4 + 2], a3l = ql[kc * 4 + 3];
#pragma unroll
            for (int np = 0; np < 4; np++) {
                int key = np * 16 + (lane & 7) + ((lane >> 4) << 3);
                int dim = kc * 16 + (lane & 8);
                uint32_t so = SWZ((uint32_t)(key * 128 + dim * 2));
                uint32_t bh0, bh1, bh2, bh3, bl0, bl1, bl2, bl3;
                ldsm_x4(bh0, bh1, bh2, bh3, kh_b + so);
                ldsm_x4(bl0, bl1, bl2, bl3, kl_b + so);
                mmah(shi[np * 2 + 0], a0h, a1h, a2h, a3h, bh0, bh1);
                mmah(shi[np * 2 + 1], a0h, a1h, a2h, a3h, bh2, bh3);
                mmah(slo[np * 2 + 0], a0h, a1h, a2h, a3h, bl0, bl1);
                mmah(slo[np * 2 + 1], a0h, a1h, a2h, a3h, bl2, bl3);
                mmah(slo[np * 2 + 0], a0l, a1l, a2l, a3l, bh0, bh1);
                mmah(slo[np * 2 + 1], a0l, a1l, a2l, a3l, bh2, bh3);
            }
        }

        // -------- fixed-max softmax: p = exp2(ssum*P_SCL + P_OFF) via MUFU,
        //          bf16x3 split via packed cvt
        uint32_t pah[8], pam[8], pal[8], pbh[8], pbm[8], pbl[8];
#pragma unroll
        for (int j = 0; j < 8; j++) {
            float p0 = ex2(fmaf(shi[j][0] + slo[j][0], P_SCL, P_OFF));
            float p1 = ex2(fmaf(shi[j][1] + slo[j][1], P_SCL, P_OFF));
            float p2 = ex2(fmaf(shi[j][2] + slo[j][2], P_SCL, P_OFF));
            float p3 = ex2(fmaf(shi[j][3] + slo[j][3], P_SCL, P_OFF));
            l0 += p0 + p1;
            l1 += p2 + p3;
            split3(p0, p1, pah[j], pam[j], pal[j]);
            split3(p2, p3, pbh[j], pbm[j], pbl[j]);
        }

        // -------- O += P V : bf16x3, split accumulators (interleaved chains)
#pragma unroll
        for (int kk = 0; kk < 4; kk++) {
            uint32_t a0h = pah[kk * 2], a1h = pbh[kk * 2],
                     a2h = pah[kk * 2 + 1], a3h = pbh[kk * 2 + 1];
            uint32_t a0m = pam[kk * 2], a1m = pbm[kk * 2],
                     a2m = pam[kk * 2 + 1], a3m = pbm[kk * 2 + 1];
            uint32_t a0l = pal[kk * 2], a1l = pbl[kk * 2],
                     a2l = pal[kk * 2 + 1], a3l = pbl[kk * 2 + 1];
#pragma unroll
            for (int np = 0; np < 4; np++) {
                int key = kk * 16 + (lane & 7) + (lane & 8);
                int dim = np * 16 + ((lane >> 4) << 3);
                uint32_t so = SWZ((uint32_t)(key * 128 + dim * 2));
                uint32_t bh0, bh1, bh2, bh3, bm0, bm1, bm2, bm3, bl0, bl1, bl2, bl3;
                ldsm_x4_t(bh0, bh1, bh2, bh3, vh_b + so);
                ldsm_x4_t(bm0, bm1, bm2, bm3, vm_b + so);
                ldsm_x4_t(bl0, bl1, bl2, bl3, vl_b + so);
                mma16816(ohi[np * 2 + 0], a0h, a1h, a2h, a3h, bh0, bh1);
                mma16816(ohi[np * 2 + 1], a0h, a1h, a2h, a3h, bh2, bh3);
                mma16816(olo[np * 2 + 0], a0h, a1h, a2h, a3h, bm0, bm1);
                mma16816(olo[np * 2 + 1], a0h, a1h, a2h, a3h, bm2, bm3);
                mma16816(olo[np * 2 + 0], a0m, a1m, a2m, a3m, bh0, bh1);
                mma16816(olo[np * 2 + 1], a0m, a1m, a2m, a3m, bh2, bh3);
                mma16816(olo[np * 2 + 0], a0m, a1m, a2m, a3m, bm0, bm1);
                mma16816(olo[np * 2 + 1], a0m, a1m, a2m, a3m, bm2, bm3);
                mma16816(olo[np * 2 + 0], a0h, a1h, a2h, a3h, bl0, bl1);
                mma16816(olo[np * 2 + 1], a0h, a1h, a2h, a3h, bl2, bl3);
                mma16816(olo[np * 2 + 0], a0l, a1l, a2l, a3l, bh0, bh1);
                mma16816(olo[np * 2 + 1], a0l, a1l, a2l, a3l, bh2, bh3);
            }
        }
        __syncthreads();
        buf ^= 1;
    }

    // -------- finalize
    l0 += __shfl_xor_sync(0xffffffffu, l0, 1);
    l0 += __shfl_xor_sync(0xffffffffu, l0, 2);
    l1 += __shfl_xor_sync(0xffffffffu, l1, 1);
    l1 += __shfl_xor_sync(0xffffffffu, l1, 2);
    float inv0 = 1.0f / l0, inv1 = 1.0f / l1;
    float* op0 = g_o + ((size_t)b * SEQ + posq0) * D_MODEL + h * HD;
    float* op1 = g_o + ((size_t)b * SEQ + posq1) * D_MODEL + h * HD;
#pragma unroll
    for (int j = 0; j < 8; j++) {
        *(float2*)(op0 + j * 8 + c2) = make_float2((ohi[j][0] + olo[j][0]) * inv0,
                                                   (ohi[j][1] + olo[j][1]) * inv0);
        *(float2*)(op1 + j * 8 + c2) = make_float2((ohi[j][2] + olo[j][2]) * inv1,
                                                   (ohi[j][3] + olo[j][3]) * inv1);
    }
}

// ---------------------------------------------------------------- renorm sums
__global__ __launch_bounds__(256) void reduce1_kernel() {
    int bc = blockIdx.x;
    int b = bc / 3, cb = bc % 3;
    int c = cb * 256 + threadIdx.x;
    size_t base = (size_t)(b * SEQ + blockIdx.y * 256) * D_MODEL + c;
    float acc = 0.f;
    for (int rr = 0; rr < 256; rr++) acc += g_o[base + (size_t)rr * D_MODEL];
    g_part[blockIdx.y][b * D_MODEL + c] = acc;
}
__global__ void reduce2_kernel() {
    int idx = blockIdx.x * 256 + threadIdx.x;
    float acc = 0.f;
#pragma unroll
    for (int j = 0; j < 32; j++) acc += g_part[j][idx];
    g_sum[idx] = acc;
}

// ---------------------------------------------------------------- layernorm (writes fp16 A for gemm2)
__device__ __forceinline__ float blk_sum(float v, float* sh) {
    int lane = threadIdx.x & 31, w = threadIdx.x >> 5;
#pragma unroll
    for (int off = 16; off; off >>= 1) v += __shfl_xor_sync(0xffffffffu, v, off);
    if (lane == 0) sh[w] = v;
    __syncthreads();
    if (threadIdx.x == 0) {
        float t = 0.f;
#pragma unroll
        for (int i = 0; i < 8; i++) t += sh[i];
        sh[8] = t;
    }
    __syncthreads();
    return sh[8];
}

__global__ __launch_bounds__(256) void ln_kernel(const float* __restrict__ gamma,
                                                 const float* __restrict__ beta) {
    __shared__ float sh[9];
    int row = blockIdx.x;
    int b = row >> 13;
    const float* in = g_o + (size_t)row * D_MODEL;
    float v[3];
    float s = 0.f;
#pragma unroll
    for (int i = 0; i < 3; i++) {
        int c = threadIdx.x + i * 256;
        float val = in[c] / (3.0f * g_sum[b * D_MODEL + c]);
        v[i] = val;
        s += val;
    }
    float mean = blk_sum(s, sh) * (1.0f / 768.0f);
    float vs = 0.f;
#pragma unroll
    for (int i = 0; i < 3; i++) {
        float d = v[i] - mean;
        vs += d * d;
    }
    float var = blk_sum(vs, sh) * (1.0f / 768.0f);
    float rstd = rsqrtf(var + 1e-5f);
#pragma unroll
    for (int i = 0; i < 3; i++) {
        int c = threadIdx.x + i * 256;
        float outv = (v[i] - mean) * rstd * gamma[c] + beta[c];
        g_ah[(size_t)row * D_MODEL + c] = __half_as_ushort(__float2half_rn(outv));
    }
}

// ---------------------------------------------------------------- launch
extern "C" void kernel_launch(void* const* d_in, const int* in_sizes, int n_in,
                              void* d_out, int out_size) {
    const float* x      = (const float*)d_in[0];
    const float* w_in   = (const float*)d_in[1];
    const float* b_in   = (const float*)d_in[2];
    const float* w_out  = (const float*)d_in[3];
    const float* b_out  = (const float*)d_in[4];
    const float* gamma  = (const float*)d_in[5];
    const float* beta   = (const float*)d_in[6];
    float* out = (float*)d_out;

    cudaFuncSetAttribute(gemm_mma_kernel, cudaFuncAttributeMaxDynamicSharedMemorySize,
                         GEMM_SMEM_B);
    cudaFuncSetAttribute(gemm2_f16_kernel, cudaFuncAttributeMaxDynamicSharedMemorySize,
                         GEMM2_SMEM_B);
    cudaFuncSetAttribute(attn_mma_kernel, cudaFuncAttributeMaxDynamicSharedMemorySize,
                         ATTN_SMEM);

    const int nbig4 = NTOK * D_MODEL / 4;
    const int nw4 = D_MODEL * D_MODEL / 4;

    zero_o_kernel<<<3072, 256>>>();
    split_kernel<<<(nbig4 + 255) / 256, 256>>>(x, nbig4, 0);
    split_kernel<<<(nw4 + 255) / 256, 256>>>(w_in, nw4, 1);
    split2_kernel<<<(nw4 + 255) / 256, 256>>>(w_out, nw4);
    gemm_mma_kernel<<<dim3(6, 128), 256, GEMM_SMEM_B>>>(b_in);
    attn_mma_kernel<<<dim3(32, 56), 128, ATTN_SMEM>>>();
    reduce1_kernel<<<dim3(6, 32), 256>>>();
    reduce2_kernel<<<6, 256>>>();
    ln_kernel<<<NTOK, 256>>>(gamma, beta);
    gemm2_f16_kernel<<<dim3(6, 128), 256, GEMM2_SMEM_B>>>(b_out, out);
}

// round 15
// speedup vs baseline: 2.1873x; 1.1449x over previous
#include <cuda_runtime.h>
#include <cuda_bf16.h>
#include <cuda_fp16.h>
#include <stdint.h>
#include <math.h>

#define D_MODEL 768
#define NHEADS 12
#define HD 64
#define BATCH 2
#define SEQ 8192
#define NTOK (BATCH * SEQ)
#define SE 2048
#define LOG2E 1.4426950408889634f
#define W1_SCALE 32.0f
#define W1_INV 0.03125f

// Scratch (allocation-free rule: __device__ globals)
__device__ float g_o[NTOK * D_MODEL];
__device__ float g_part[32][BATCH * D_MODEL];
__device__ float g_sum[BATCH * D_MODEL];
// g_a*: fp16x2 of x for gemm1; g_ah later holds fp16 of ln-out for gemm2
__device__ uint16_t g_ah[NTOK * D_MODEL], g_al[NTOK * D_MODEL];
// projected q: bf16x3 (V side of PV; renorm-amplified O-path)
__device__ uint16_t g_qh[NTOK * D_MODEL], g_qm[NTOK * D_MODEL], g_ql[NTOK * D_MODEL];
// projected q: fp16x2 (QK S-path)
__device__ uint16_t g_fh[NTOK * D_MODEL], g_fl[NTOK * D_MODEL];
// weights: w1 fp16x2 (x32 pre-scaled), w2 fp16x2
__device__ uint16_t g_w1h[D_MODEL * D_MODEL], g_w1l[D_MODEL * D_MODEL];
__device__ uint16_t g_w2h[D_MODEL * D_MODEL], g_w2l[D_MODEL * D_MODEL];

// ================================================================ helpers
__device__ __forceinline__ uint32_t smem_u32(const void* p) {
    uint32_t a;
    asm("{ .reg .u64 t; cvta.to.shared.u64 t, %1; cvt.u32.u64 %0, t; }" : "=r"(a) : "l"(p));
    return a;
}

#define SWZ(off) ((off) ^ (((off) >> 3) & 0x70))

__device__ __forceinline__ void ldsm_x4(uint32_t& r0, uint32_t& r1, uint32_t& r2,
                                        uint32_t& r3, uint32_t addr) {
    asm volatile("ldmatrix.sync.aligned.m8n8.x4.shared.b16 {%0,%1,%2,%3}, [%4];"
                 : "=r"(r0), "=r"(r1), "=r"(r2), "=r"(r3) : "r"(addr));
}
__device__ __forceinline__ void ldsm_x4_t(uint32_t& r0, uint32_t& r1, uint32_t& r2,
                                          uint32_t& r3, uint32_t addr) {
    asm volatile("ldmatrix.sync.aligned.m8n8.x4.trans.shared.b16 {%0,%1,%2,%3}, [%4];"
                 : "=r"(r0), "=r"(r1), "=r"(r2), "=r"(r3) : "r"(addr));
}
// bf16 mma
__device__ __forceinline__ void mma16816(float* c, uint32_t a0, uint32_t a1, uint32_t a2,
                                         uint32_t a3, uint32_t b0, uint32_t b1) {
    asm volatile(
        "mma.sync.aligned.m16n8k16.row.col.f32.bf16.bf16.f32 "
        "{%0,%1,%2,%3}, {%4,%5,%6,%7}, {%8,%9}, {%0,%1,%2,%3};"
        : "+f"(c[0]), "+f"(c[1]), "+f"(c[2]), "+f"(c[3])
        : "r"(a0), "r"(a1), "r"(a2), "r"(a3), "r"(b0), "r"(b1));
}
// fp16 mma
__device__ __forceinline__ void mmah(float* c, uint32_t a0, uint32_t a1, uint32_t a2,
                                     uint32_t a3, uint32_t b0, uint32_t b1) {
    asm volatile(
        "mma.sync.aligned.m16n8k16.row.col.f32.f16.f16.f32 "
        "{%0,%1,%2,%3}, {%4,%5,%6,%7}, {%8,%9}, {%0,%1,%2,%3};"
        : "+f"(c[0]), "+f"(c[1]), "+f"(c[2]), "+f"(c[3])
        : "r"(a0), "r"(a1), "r"(a2), "r"(a3), "r"(b0), "r"(b1));
}
#define CP_ASYNC16(dst, src) \
    asm volatile("cp.async.cg.shared.global [%0], [%1], 16;" :: "r"(dst), "l"(src))
#define CP_COMMIT() asm volatile("cp.async.commit_group;")

// packed bf16x3 split (bit-identical to scalar version)
__device__ __forceinline__ void split3(float a, float b,
                                       uint32_t& h, uint32_t& m, uint32_t& l) {
    uint32_t hp;
    asm("cvt.rn.bf16x2.f32 %0, %1, %2;" : "=r"(hp) : "f"(b), "f"(a));
    float ra = a - __uint_as_float(hp << 16);
    float rb = b - __uint_as_float(hp & 0xffff0000u);
    uint32_t mp;
    asm("cvt.rn.bf16x2.f32 %0, %1, %2;" : "=r"(mp) : "f"(rb), "f"(ra));
    float ra2 = ra - __uint_as_float(mp << 16);
    float rb2 = rb - __uint_as_float(mp & 0xffff0000u);
    uint32_t lp;
    asm("cvt.rn.bf16x2.f32 %0, %1, %2;" : "=r"(lp) : "f"(rb2), "f"(ra2));
    h = hp; m = mp; l = lp;
}
__device__ __forceinline__ uint32_t pack_h2(__half lo, __half hi) {
    return ((uint32_t)__half_as_ushort(hi) << 16) | (uint32_t)__half_as_ushort(lo);
}
__device__ __forceinline__ void split2(float a, float b, uint32_t& h, uint32_t& l) {
    __half ha = __float2half_rn(a), hb = __float2half_rn(b);
    __half la = __float2half_rn(a - __half2float(ha));
    __half lb = __float2half_rn(b - __half2float(hb));
    h = pack_h2(ha, hb);
    l = pack_h2(la, lb);
}

// MUFU exp2
__device__ __forceinline__ float ex2(float f) {
    float r;
    asm("ex2.approx.ftz.f32 %0, %1;" : "=f"(r) : "f"(f));
    return r;
}

// ---------------------------------------------------------------- zero fill
__global__ void zero_o_kernel() {
    int idx = blockIdx.x * blockDim.x + threadIdx.x;
    const int per_tok = 512 / 4;
    const int n4 = NTOK * per_tok;
    float4 z = make_float4(0.f, 0.f, 0.f, 0.f);
    for (int i = idx; i < n4; i += gridDim.x * blockDim.x) {
        int tok = i / per_tok;
        int c4 = i % per_tok;
        ((float4*)(g_o + (size_t)tok * D_MODEL + 256))[c4] = z;
    }
}

// ---------------------------------------------------------------- fp16x2 split (with scale)
// sel: 0 -> g_a*, 1 -> g_w1* (scale 32), 2 -> g_w2*
__global__ __launch_bounds__(256) void split2_kernel(const float* __restrict__ src,
                                                     int n4, int sel) {
    int i = blockIdx.x * blockDim.x + threadIdx.x;
    if (i >= n4) return;
    float4 v = ((const float4*)src)[i];
    float s = (sel == 1) ? W1_SCALE : 1.0f;
    uint32_t h0, l0, h1, l1;
    split2(v.x * s, v.y * s, h0, l0);
    split2(v.z * s, v.w * s, h1, l1);
    uint2* dh; uint2* dl;
    if (sel == 0)      { dh = (uint2*)g_ah;  dl = (uint2*)g_al; }
    else if (sel == 1) { dh = (uint2*)g_w1h; dl = (uint2*)g_w1l; }
    else               { dh = (uint2*)g_w2h; dl = (uint2*)g_w2l; }
    dh[i] = make_uint2(h0, h1);
    dl[i] = make_uint2(l0, l1);
}

// ================================================================ GEMM1 (fp16x2, 3 products, w1 x32-prescaled) -> q bf16x3 + fp16x2
#define GKC 16
#define NCH (D_MODEL / GKC)       // 48
#define G_LVL_B (128 * 48)
#define G_OP_B (2 * G_LVL_B)
#define G_STAGE (2 * G_OP_B)
#define GEMM_SMEM_B (2 * G_STAGE)  // 49152

__device__ __forceinline__ void gemm_issue(int c, int buf, uint32_t sbase, int tid,
                                           int m0, int n0) {
    int k0 = c * GKC;
    uint32_t sb = sbase + buf * G_STAGE;
    int row = tid >> 1, half = tid & 1;
    const uint16_t* srcs[4] = {g_ah, g_al, g_w1h, g_w1l};
#pragma unroll
    for (int it = 0; it < 4; it++) {
        int grow = (it < 2 ? m0 : n0) + row;
        const uint16_t* sp = srcs[it] + (size_t)grow * D_MODEL + k0 + half * 8;
        uint32_t dst = sb + (it < 2 ? 0 : G_OP_B) + (it & 1) * G_LVL_B + row * 48 + half * 16;
        CP_ASYNC16(dst, sp);
    }
    CP_COMMIT();
}

__global__ __launch_bounds__(256, 1) void gemm_mma_kernel(const float* __restrict__ bias) {
    extern __shared__ uint8_t gsm[];
    uint32_t sbase = smem_u32(gsm);
    int tid = threadIdx.x, warp = tid >> 5, lane = tid & 31;
    int m0 = blockIdx.y * 128, n0 = blockIdx.x * 128;

    float ohi[16][4], olo[16][4];
#pragma unroll
    for (int j = 0; j < 16; j++) {
        ohi[j][0] = ohi[j][1] = ohi[j][2] = ohi[j][3] = 0.f;
        olo[j][0] = olo[j][1] = olo[j][2] = olo[j][3] = 0.f;
    }

    gemm_issue(0, 0, sbase, tid, m0, n0);

    uint32_t arow = (uint32_t)((warp * 16 + (lane & 15)) * 48 + (lane >> 4) * 16);
    uint32_t brow = (uint32_t)(((lane & 7) + ((lane >> 4) << 3)) * 48 + ((lane & 8) ? 16 : 0));

    for (int c = 0; c < NCH; c++) {
        int buf = c & 1;
        if (c + 1 < NCH) {
            gemm_issue(c + 1, buf ^ 1, sbase, tid, m0, n0);
            asm volatile("cp.async.wait_group 1;");
        } else {
            asm volatile("cp.async.wait_group 0;");
        }
        __syncthreads();

        uint32_t ab = sbase + buf * G_STAGE;
        uint32_t bb = ab + G_OP_B;
        uint32_t ah0, ah1, ah2, ah3, al0, al1, al2, al3;
        ldsm_x4(ah0, ah1, ah2, ah3, ab + 0 * G_LVL_B + arow);
        ldsm_x4(al0, al1, al2, al3, ab + 1 * G_LVL_B + arow);
#pragma unroll
        for (int np = 0; np < 8; np++) {
            uint32_t baddr = bb + (uint32_t)(np * 16 * 48) + brow;
            uint32_t bh0, bh1, bh2, bh3, bl0, bl1, bl2, bl3;
            ldsm_x4(bh0, bh1, bh2, bh3, baddr + 0 * G_LVL_B);
            ldsm_x4(bl0, bl1, bl2, bl3, baddr + 1 * G_LVL_B);
            mmah(ohi[np * 2 + 0], ah0, ah1, ah2, ah3, bh0, bh1);
            mmah(ohi[np * 2 + 1], ah0, ah1, ah2, ah3, bh2, bh3);
            mmah(olo[np * 2 + 0], ah0, ah1, ah2, ah3, bl0, bl1);
            mmah(olo[np * 2 + 1], ah0, ah1, ah2, ah3, bl2, bl3);
            mmah(olo[np * 2 + 0], al0, al1, al2, al3, bh0, bh1);
            mmah(olo[np * 2 + 1], al0, al1, al2, al3, bh2, bh3);
        }
        __syncthreads();
    }

    // epilogue: undo w1 x32 scale, add bias, write q as bf16x3 + fp16x2
    int r0l = lane >> 2, c2 = (lane & 3) * 2;
    int mrow0 = m0 + warp * 16 + r0l;
    int mrow1 = mrow0 + 8;
#pragma unroll
    for (int j = 0; j < 16; j++) {
        int col = n0 + j * 8 + c2;
        float2 bv = *(const float2*)(bias + col);
        float v0 = (ohi[j][0] + olo[j][0]) * W1_INV + bv.x;
        float v1 = (ohi[j][1] + olo[j][1]) * W1_INV + bv.y;
        float v2 = (ohi[j][2] + olo[j][2]) * W1_INV + bv.x;
        float v3 = (ohi[j][3] + olo[j][3]) * W1_INV + bv.y;
        uint32_t h, m, l;
        uint32_t fh, fl;
        split3(v0, v1, h, m, l);
        split2(v0, v1, fh, fl);
        uint32_t i0 = (uint32_t)(mrow0 * D_MODEL + col) >> 1;
        ((uint32_t*)g_qh)[i0] = h;
        ((uint32_t*)g_qm)[i0] = m;
        ((uint32_t*)g_ql)[i0] = l;
        ((uint32_t*)g_fh)[i0] = fh;
        ((uint32_t*)g_fl)[i0] = fl;
        split3(v2, v3, h, m, l);
        split2(v2, v3, fh, fl);
        uint32_t i1 = (uint32_t)(mrow1 * D_MODEL + col) >> 1;
        ((uint32_t*)g_qh)[i1] = h;
        ((uint32_t*)g_qm)[i1] = m;
        ((uint32_t*)g_ql)[i1] = l;
        ((uint32_t*)g_fh)[i1] = fh;
        ((uint32_t*)g_fl)[i1] = fl;
    }
}

// ================================================================ GEMM2 (2 products: A_h*W_h + A_h*W_l; A single fp16)
#define F_LVL_B (128 * 48)
#define F_STAGE (3 * F_LVL_B)
#define GEMM2_SMEM_B (2 * F_STAGE)

__device__ __forceinline__ void gemm2_issue(int c, int buf, uint32_t sbase, int tid,
                                            int m0, int n0) {
    int k0 = c * GKC;
    uint32_t sb = sbase + buf * F_STAGE;
    int row = tid >> 1, half = tid & 1;
    const uint16_t* srcs[3] = {g_ah, g_w2h, g_w2l};
#pragma unroll
    for (int it = 0; it < 3; it++) {
        int grow = (it < 1 ? m0 : n0) + row;
        const uint16_t* sp = srcs[it] + (size_t)grow * D_MODEL + k0 + half * 8;
        uint32_t dst = sb + it * F_LVL_B + row * 48 + half * 16;
        CP_ASYNC16(dst, sp);
    }
    CP_COMMIT();
}

__global__ __launch_bounds__(256, 1) void gemm2_f16_kernel(const float* __restrict__ bias,
                                                           float* __restrict__ outp) {
    extern __shared__ uint8_t gsm[];
    uint32_t sbase = smem_u32(gsm);
    int tid = threadIdx.x, warp = tid >> 5, lane = tid & 31;
    int m0 = blockIdx.y * 128, n0 = blockIdx.x * 128;

    float ohi[16][4], olo[16][4];
#pragma unroll
    for (int j = 0; j < 16; j++) {
        ohi[j][0] = ohi[j][1] = ohi[j][2] = ohi[j][3] = 0.f;
        olo[j][0] = olo[j][1] = olo[j][2] = olo[j][3] = 0.f;
    }

    gemm2_issue(0, 0, sbase, tid, m0, n0);

    uint32_t arow = (uint32_t)((warp * 16 + (lane & 15)) * 48 + (lane >> 4) * 16);
    uint32_t brow = (uint32_t)(((lane & 7) + ((lane >> 4) << 3)) * 48 + ((lane & 8) ? 16 : 0));

    for (int c = 0; c < NCH; c++) {
        int buf = c & 1;
        if (c + 1 < NCH) {
            gemm2_issue(c + 1, buf ^ 1, sbase, tid, m0, n0);
            asm volatile("cp.async.wait_group 1;");
        } else {
            asm volatile("cp.async.wait_group 0;");
        }
        __syncthreads();

        uint32_t ab = sbase + buf * F_STAGE;
        uint32_t bb = ab + F_LVL_B;
        uint32_t ah0, ah1, ah2, ah3;
        ldsm_x4(ah0, ah1, ah2, ah3, ab + arow);
#pragma unroll
        for (int np = 0; np < 8; np++) {
            uint32_t baddr = bb + (uint32_t)(np * 16 * 48) + brow;
            uint32_t bh0, bh1, bh2, bh3, bl0, bl1, bl2, bl3;
            ldsm_x4(bh0, bh1, bh2, bh3, baddr + 0 * F_LVL_B);
            ldsm_x4(bl0, bl1, bl2, bl3, baddr + 1 * F_LVL_B);
            mmah(ohi[np * 2 + 0], ah0, ah1, ah2, ah3, bh0, bh1);
            mmah(ohi[np * 2 + 1], ah0, ah1, ah2, ah3, bh2, bh3);
            mmah(olo[np * 2 + 0], ah0, ah1, ah2, ah3, bl0, bl1);
            mmah(olo[np * 2 + 1], ah0, ah1, ah2, ah3, bl2, bl3);
        }
        __syncthreads();
    }

    int r0l = lane >> 2, c2 = (lane & 3) * 2;
    int mrow0 = m0 + warp * 16 + r0l;
    int mrow1 = mrow0 + 8;
#pragma unroll
    for (int j = 0; j < 16; j++) {
        int col = n0 + j * 8 + c2;
        float2 bv = *(const float2*)(bias + col);
        *(float2*)(outp + (size_t)mrow0 * D_MODEL + col) =
            make_float2(ohi[j][0] + olo[j][0] + bv.x, ohi[j][1] + olo[j][1] + bv.y);
        *(float2*)(outp + (size_t)mrow1 * D_MODEL + col) =
            make_float2(ohi[j][2] + olo[j][2] + bv.x, ohi[j][3] + olo[j][3] + bv.y);
    }
}

// ================================================================ attention
// QK: fp16x2 (3 products). PV: bf16x3 (6 products). Fixed-max softmax via MUFU.
#define KT_LVL 8192
#define KT_BUF (5 * KT_LVL)
#define ATTN_SMEM (2 * KT_BUF)

#define P_SCL 0.18033688011111793f
#define P_OFF -23.083120654223414f

__device__ __forceinline__ void attn_stage(uint32_t dstbase, int b, int kbase,
                                           int k0, int r, int h, int tid) {
#pragma unroll
    for (int it = 0; it < 20; it++) {
        int idx = tid + it * 128;
        int lvl = idx >> 9;
        int rem = idx & 511;
        int key = rem >> 3;
        int c16 = rem & 7;
        int posk = kbase + (k0 + key) * r;
        uint32_t goff = (uint32_t)(b * SEQ + posk) * D_MODEL + h * HD + c16 * 8;
        const uint16_t* src;
        switch (lvl) {
            case 0: src = g_fh + goff; break;
            case 1: src = g_fl + goff; break;
            case 2: src = g_qh + goff; break;
            case 3: src = g_qm + goff; break;
            default: src = g_ql + goff; break;
        }
        uint32_t dst = dstbase + lvl * KT_LVL + SWZ((uint32_t)(key * 128 + c16 * 16));
        CP_ASYNC16(dst, src);
    }
    CP_COMMIT();
}

__global__ __launch_bounds__(128, 2) void attn_mma_kernel() {
    extern __shared__ uint8_t ksm[];

    int inst = blockIdx.y;
    int b, h, seg, r, off, slen;
    if (inst < 32)      { b = inst >> 4; int t = inst & 15; seg = t >> 2; h = t & 3;            r = 1; off = 0; slen = 2048; }
    else if (inst < 48) { int t = inst - 32; b = t >> 3; t &= 7; seg = t >> 2; h = 4 + (t & 3); r = 2; off = 1; slen = 4096; }
    else                { int t = inst - 48; b = t >> 2; h = 8 + (t & 3); seg = 0;              r = 4; off = 2; slen = 8192; }

    int tid = threadIdx.x;
    int warp = tid >> 5, lane = tid & 31;
    int kbase = seg * slen + off;
    int qrow0 = blockIdx.x * 64 + warp * 16;

    uint32_t smb = smem_u32(ksm);

    int r0l = lane >> 2;
    int c2 = (lane & 3) * 2;

    // -------- Q fragments (fp16x2 levels)
    int posq0 = kbase + (qrow0 + r0l) * r;
    int posq1 = kbase + (qrow0 + r0l + 8) * r;
    uint32_t qb0 = (uint32_t)(b * SEQ + posq0) * D_MODEL + h * HD;
    uint32_t qb1 = (uint32_t)(b * SEQ + posq1) * D_MODEL + h * HD;
    uint32_t qh[16], ql[16];
#pragma unroll
    for (int kc = 0; kc < 4; kc++) {
        uint32_t i00 = (qb0 + kc * 16 + c2) >> 1;
        uint32_t i10 = (qb1 + kc * 16 + c2) >> 1;
        uint32_t i01 = (qb0 + kc * 16 + c2 + 8) >> 1;
        uint32_t i11 = (qb1 + kc * 16 + c2 + 8) >> 1;
        qh[kc * 4 + 0] = ((const uint32_t*)g_fh)[i00];
        ql[kc * 4 + 0] = ((const uint32_t*)g_fl)[i00];
        qh[kc * 4 + 1] = ((const uint32_t*)g_fh)[i10];
        ql[kc * 4 + 1] = ((const uint32_t*)g_fl)[i10];
        qh[kc * 4 + 2] = ((const uint32_t*)g_fh)[i01];
        ql[kc * 4 + 2] = ((const uint32_t*)g_fl)[i01];
        qh[kc * 4 + 3] = ((const uint32_t*)g_fh)[i11];
        ql[kc * 4 + 3] = ((const uint32_t*)g_fl)[i11];
    }

    float ohi[8][4], olo[8][4];
#pragma unroll
    for (int j = 0; j < 8; j++) {
        ohi[j][0] = ohi[j][1] = ohi[j][2] = ohi[j][3] = 0.f;
        olo[j][0] = olo[j][1] = olo[j][2] = olo[j][3] = 0.f;
    }
    float l0 = 0.f, l1 = 0.f;

    attn_stage(smb, b, kbase, 0, r, h, tid);

    int buf = 0;
    for (int kt = 0; kt < SE / 64; kt++) {
        if (kt + 1 < SE / 64) {
            attn_stage(smb + (buf ^ 1) * KT_BUF, b, kbase, (kt + 1) * 64, r, h, tid);
            asm volatile("cp.async.wait_group 1;");
        } else {
            asm volatile("cp.async.wait_group 0;");
        }
        __syncthreads();

        uint32_t kh_b = smb + buf * KT_BUF;
        uint32_t kl_b = kh_b + KT_LVL;
        uint32_t vh_b = kh_b + 2 * KT_LVL;
        uint32_t vm_b = kh_b + 3 * KT_LVL;
        uint32_t vl_b = kh_b + 4 * KT_LVL;

        // -------- S = Q K^T : fp16x2, split accumulators
        float shi[8][4], slo[8][4];
#pragma unroll
        for (int j = 0; j < 8; j++) {
            shi[j][0] = shi[j][1] = shi[j][2] = shi[j][3] = 0.f;
            slo[j][0] = slo[j][1] = slo[j][2] = slo[j][3] = 0.f;
        }
#pragma unroll
        for (int kc = 0; kc < 4; kc++) {
            uint32_t a0h = qh[kc * 4 + 0], a1h = qh[kc * 4 + 1],
                     a2h = qh[kc * 4 + 2], a3h = qh[kc * 4 + 3];
            uint32_t a0l = ql[kc * 4 + 0], a1l = ql[kc * 4 + 1],
                     a2l = ql[kc * 4 + 2], a3l = ql[kc * 4 + 3];
#pragma unroll
            for (int np = 0; np < 4; np++) {
                int key = np * 16 + (lane & 7) + ((lane >> 4) << 3);
                int dim = kc * 16 + (lane & 8);
                uint32_t so = SWZ((uint32_t)(key * 128 + dim * 2));
                uint32_t bh0, bh1, bh2, bh3, bl0, bl1, bl2, bl3;
                ldsm_x4(bh0, bh1, bh2, bh3, kh_b + so);
                ldsm_x4(bl0, bl1, bl2, bl3, kl_b + so);
                mmah(shi[np * 2 + 0], a0h, a1h, a2h, a3h, bh0, bh1);
                mmah(shi[np * 2 + 1], a0h, a1h, a2h, a3h, bh2, bh3);
                mmah(slo[np * 2 + 0], a0h, a1h, a2h, a3h, bl0, bl1);
                mmah(slo[np * 2 + 1], a0h, a1h, a2h, a3h, bl2, bl3);
                mmah(slo[np * 2 + 0], a0l, a1l, a2l, a3l, bh0, bh1);
                mmah(slo[np * 2 + 1], a0l, a1l, a2l, a3l, bh2, bh3);
            }
        }

        // -------- fixed-max softmax via MUFU; bf16x3 split via packed cvt
        uint32_t pah[8], pam[8], pal[8], pbh[8], pbm[8], pbl[8];
#pragma unroll
        for (int j = 0; j < 8; j++) {
            float p0 = ex2(fmaf(shi[j][0] + slo[j][0], P_SCL, P_OFF));
            float p1 = ex2(fmaf(shi[j][1] + slo[j][1], P_SCL, P_OFF));
            float p2 = ex2(fmaf(shi[j][2] + slo[j][2], P_SCL, P_OFF));
            float p3 = ex2(fmaf(shi[j][3] + slo[j][3], P_SCL, P_OFF));
            l0 += p0 + p1;
            l1 += p2 + p3;
            split3(p0, p1, pah[j], pam[j], pal[j]);
            split3(p2, p3, pbh[j], pbm[j], pbl[j]);
        }

        // -------- O += P V : bf16x3, split accumulators (interleaved chains)
#pragma unroll
        for (int kk = 0; kk < 4; kk++) {
            uint32_t a0h = pah[kk * 2], a1h = pbh[kk * 2],
                     a2h = pah[kk * 2 + 1], a3h = pbh[kk * 2 + 1];
            uint32_t a0m = pam[kk * 2], a1m = pbm[kk * 2],
                     a2m = pam[kk * 2 + 1], a3m = pbm[kk * 2 + 1];
            uint32_t a0l = pal[kk * 2], a1l = pbl[kk * 2],
                     a2l = pal[kk * 2 + 1], a3l = pbl[kk * 2 + 1];
#pragma unroll
            for (int np = 0; np < 4; np++) {
                int key = kk * 16 + (lane & 7) + (lane & 8);
                int dim = np * 16 + ((lane >> 4) << 3);
                uint32_t so = SWZ((uint32_t)(key * 128 + dim * 2));
                uint32_t bh0, bh1, bh2, bh3, bm0, bm1, bm2, bm3, bl0, bl1, bl2, bl3;
                ldsm_x4_t(bh0, bh1, bh2, bh3, vh_b + so);
                ldsm_x4_t(bm0, bm1, bm2, bm3, vm_b + so);
                ldsm_x4_t(bl0, bl1, bl2, bl3, vl_b + so);
                mma16816(ohi[np * 2 + 0], a0h, a1h, a2h, a3h, bh0, bh1);
                mma16816(ohi[np * 2 + 1], a0h, a1h, a2h, a3h, bh2, bh3);
                mma16816(olo[np * 2 + 0], a0h, a1h, a2h, a3h, bm0, bm1);
                mma16816(olo[np * 2 + 1], a0h, a1h, a2h, a3h, bm2, bm3);
                mma16816(olo[np * 2 + 0], a0m, a1m, a2m, a3m, bh0, bh1);
                mma16816(olo[np * 2 + 1], a0m, a1m, a2m, a3m, bh2, bh3);
                mma16816(olo[np * 2 + 0], a0m, a1m, a2m, a3m, bm0, bm1);
                mma16816(olo[np * 2 + 1], a0m, a1m, a2m, a3m, bm2, bm3);
                mma16816(olo[np * 2 + 0], a0h, a1h, a2h, a3h, bl0, bl1);
                mma16816(olo[np * 2 + 1], a0h, a1h, a2h, a3h, bl2, bl3);
                mma16816(olo[np * 2 + 0], a0l, a1l, a2l, a3l, bh0, bh1);
                mma16816(olo[np * 2 + 1], a0l, a1l, a2l, a3l, bh2, bh3);
            }
        }
        __syncthreads();
        buf ^= 1;
    }

    // -------- finalize
    l0 += __shfl_xor_sync(0xffffffffu, l0, 1);
    l0 += __shfl_xor_sync(0xffffffffu, l0, 2);
    l1 += __shfl_xor_sync(0xffffffffu, l1, 1);
    l1 += __shfl_xor_sync(0xffffffffu, l1, 2);
    float inv0 = 1.0f / l0, inv1 = 1.0f / l1;
    float* op0 = g_o + ((size_t)b * SEQ + posq0) * D_MODEL + h * HD;
    float* op1 = g_o + ((size_t)b * SEQ + posq1) * D_MODEL + h * HD;
#pragma unroll
    for (int j = 0; j < 8; j++) {
        *(float2*)(op0 + j * 8 + c2) = make_float2((ohi[j][0] + olo[j][0]) * inv0,
                                                   (ohi[j][1] + olo[j][1]) * inv0);
        *(float2*)(op1 + j * 8 + c2) = make_float2((ohi[j][2] + olo[j][2]) * inv1,
                                                   (ohi[j][3] + olo[j][3]) * inv1);
    }
}

// ---------------------------------------------------------------- renorm sums
__global__ __launch_bounds__(256) void reduce1_kernel() {
    int bc = blockIdx.x;
    int b = bc / 3, cb = bc % 3;
    int c = cb * 256 + threadIdx.x;
    size_t base = (size_t)(b * SEQ + blockIdx.y * 256) * D_MODEL + c;
    float acc = 0.f;
    for (int rr = 0; rr < 256; rr++) acc += g_o[base + (size_t)rr * D_MODEL];
    g_part[blockIdx.y][b * D_MODEL + c] = acc;
}
__global__ void reduce2_kernel() {
    int idx = blockIdx.x * 256 + threadIdx.x;
    float acc = 0.f;
#pragma unroll
    for (int j = 0; j < 32; j++) acc += g_part[j][idx];
    g_sum[idx] = acc;
}

// ---------------------------------------------------------------- layernorm (writes fp16 A for gemm2)
__device__ __forceinline__ float blk_sum(float v, float* sh) {
    int lane = threadIdx.x & 31, w = threadIdx.x >> 5;
#pragma unroll
    for (int off = 16; off; off >>= 1) v += __shfl_xor_sync(0xffffffffu, v, off);
    if (lane == 0) sh[w] = v;
    __syncthreads();
    if (threadIdx.x == 0) {
        float t = 0.f;
#pragma unroll
        for (int i = 0; i < 8; i++) t += sh[i];
        sh[8] = t;
    }
    __syncthreads();
    return sh[8];
}

__global__ __launch_bounds__(256) void ln_kernel(const float* __restrict__ gamma,
                                                 const float* __restrict__ beta) {
    __shared__ float sh[9];
    int row = blockIdx.x;
    int b = row >> 13;
    const float* in = g_o + (size_t)row * D_MODEL;
    float v[3];
    float s = 0.f;
#pragma unroll
    for (int i = 0; i < 3; i++) {
        int c = threadIdx.x + i * 256;
        float val = in[c] / (3.0f * g_sum[b * D_MODEL + c]);
        v[i] = val;
        s += val;
    }
    float mean = blk_sum(s, sh) * (1.0f / 768.0f);
    float vs = 0.f;
#pragma unroll
    for (int i = 0; i < 3; i++) {
        float d = v[i] - mean;
        vs += d * d;
    }
    float var = blk_sum(vs, sh) * (1.0f / 768.0f);
    float rstd = rsqrtf(var + 1e-5f);
#pragma unroll
    for (int i = 0; i < 3; i++) {
        int c = threadIdx.x + i * 256;
        float outv = (v[i] - mean) * rstd * gamma[c] + beta[c];
        g_ah[(size_t)row * D_MODEL + c] = __half_as_ushort(__float2half_rn(outv));
    }
}

// ---------------------------------------------------------------- launch
extern "C" void kernel_launch(void* const* d_in, const int* in_sizes, int n_in,
                              void* d_out, int out_size) {
    const float* x      = (const float*)d_in[0];
    const float* w_in   = (const float*)d_in[1];
    const float* b_in   = (const float*)d_in[2];
    const float* w_out  = (const float*)d_in[3];
    const float* b_out  = (const float*)d_in[4];
    const float* gamma  = (const float*)d_in[5];
    const float* beta   = (const float*)d_in[6];
    float* out = (float*)d_out;

    cudaFuncSetAttribute(gemm_mma_kernel, cudaFuncAttributeMaxDynamicSharedMemorySize,
                         GEMM_SMEM_B);
    cudaFuncSetAttribute(gemm2_f16_kernel, cudaFuncAttributeMaxDynamicSharedMemorySize,
                         GEMM2_SMEM_B);
    cudaFuncSetAttribute(attn_mma_kernel, cudaFuncAttributeMaxDynamicSharedMemorySize,
                         ATTN_SMEM);

    const int nbig4 = NTOK * D_MODEL / 4;
    const int nw4 = D_MODEL * D_MODEL / 4;

    zero_o_kernel<<<3072, 256>>>();
    split2_kernel<<<(nbig4 + 255) / 256, 256>>>(x, nbig4, 0);
    split2_kernel<<<(nw4 + 255) / 256, 256>>>(w_in, nw4, 1);
    split2_kernel<<<(nw4 + 255) / 256, 256>>>(w_out, nw4, 2);
    gemm_mma_kernel<<<dim3(6, 128), 256, GEMM_SMEM_B>>>(b_in);
    attn_mma_kernel<<<dim3(32, 56), 128, ATTN_SMEM>>>();
    reduce1_kernel<<<dim3(6, 32), 256>>>();
    reduce2_kernel<<<6, 256>>>();
    ln_kernel<<<NTOK, 256>>>(gamma, beta);
    gemm2_f16_kernel<<<dim3(6, 128), 256, GEMM2_SMEM_B>>>(b_out, out);
}

// round 16
// speedup vs baseline: 2.1919x; 1.0021x over previous
#include <cuda_runtime.h>
#include <cuda_bf16.h>
#include <cuda_fp16.h>
#include <stdint.h>
#include <math.h>

#define D_MODEL 768
#define NHEADS 12
#define HD 64
#define BATCH 2
#define SEQ 8192
#define NTOK (BATCH * SEQ)
#define SE 2048
#define LOG2E 1.4426950408889634f
#define W1_SCALE 32.0f
#define W1_INV 0.03125f

// Scratch (allocation-free rule: __device__ globals)
__device__ float g_o[NTOK * D_MODEL];
__device__ float g_part[32][BATCH * D_MODEL];
__device__ float g_sum[BATCH * D_MODEL];
// g_a*: fp16x2 of x for gemm1; g_ah later holds fp16 of ln-out for gemm2
__device__ uint16_t g_ah[NTOK * D_MODEL], g_al[NTOK * D_MODEL];
// projected q: bf16x3 (V side of PV; renorm-amplified O-path)
__device__ uint16_t g_qh[NTOK * D_MODEL], g_qm[NTOK * D_MODEL], g_ql[NTOK * D_MODEL];
// projected q: fp16x2 (QK S-path)
__device__ uint16_t g_fh[NTOK * D_MODEL], g_fl[NTOK * D_MODEL];
// weights: w1 fp16x2 (x32 pre-scaled), w2 fp16x2
__device__ uint16_t g_w1h[D_MODEL * D_MODEL], g_w1l[D_MODEL * D_MODEL];
__device__ uint16_t g_w2h[D_MODEL * D_MODEL], g_w2l[D_MODEL * D_MODEL];

// ================================================================ helpers
__device__ __forceinline__ uint32_t smem_u32(const void* p) {
    uint32_t a;
    asm("{ .reg .u64 t; cvta.to.shared.u64 t, %1; cvt.u32.u64 %0, t; }" : "=r"(a) : "l"(p));
    return a;
}

#define SWZ(off) ((off) ^ (((off) >> 3) & 0x70))

__device__ __forceinline__ void ldsm_x4(uint32_t& r0, uint32_t& r1, uint32_t& r2,
                                        uint32_t& r3, uint32_t addr) {
    asm volatile("ldmatrix.sync.aligned.m8n8.x4.shared.b16 {%0,%1,%2,%3}, [%4];"
                 : "=r"(r0), "=r"(r1), "=r"(r2), "=r"(r3) : "r"(addr));
}
__device__ __forceinline__ void ldsm_x4_t(uint32_t& r0, uint32_t& r1, uint32_t& r2,
                                          uint32_t& r3, uint32_t addr) {
    asm volatile("ldmatrix.sync.aligned.m8n8.x4.trans.shared.b16 {%0,%1,%2,%3}, [%4];"
                 : "=r"(r0), "=r"(r1), "=r"(r2), "=r"(r3) : "r"(addr));
}
// bf16 mma
__device__ __forceinline__ void mma16816(float* c, uint32_t a0, uint32_t a1, uint32_t a2,
                                         uint32_t a3, uint32_t b0, uint32_t b1) {
    asm volatile(
        "mma.sync.aligned.m16n8k16.row.col.f32.bf16.bf16.f32 "
        "{%0,%1,%2,%3}, {%4,%5,%6,%7}, {%8,%9}, {%0,%1,%2,%3};"
        : "+f"(c[0]), "+f"(c[1]), "+f"(c[2]), "+f"(c[3])
        : "r"(a0), "r"(a1), "r"(a2), "r"(a3), "r"(b0), "r"(b1));
}
// fp16 mma
__device__ __forceinline__ void mmah(float* c, uint32_t a0, uint32_t a1, uint32_t a2,
                                     uint32_t a3, uint32_t b0, uint32_t b1) {
    asm volatile(
        "mma.sync.aligned.m16n8k16.row.col.f32.f16.f16.f32 "
        "{%0,%1,%2,%3}, {%4,%5,%6,%7}, {%8,%9}, {%0,%1,%2,%3};"
        : "+f"(c[0]), "+f"(c[1]), "+f"(c[2]), "+f"(c[3])
        : "r"(a0), "r"(a1), "r"(a2), "r"(a3), "r"(b0), "r"(b1));
}
#define CP_ASYNC16(dst, src) \
    asm volatile("cp.async.cg.shared.global [%0], [%1], 16;" :: "r"(dst), "l"(src))
#define CP_COMMIT() asm volatile("cp.async.commit_group;")

// packed bf16x3 split (bit-identical to scalar version)
__device__ __forceinline__ void split3(float a, float b,
                                       uint32_t& h, uint32_t& m, uint32_t& l) {
    uint32_t hp;
    asm("cvt.rn.bf16x2.f32 %0, %1, %2;" : "=r"(hp) : "f"(b), "f"(a));
    float ra = a - __uint_as_float(hp << 16);
    float rb = b - __uint_as_float(hp & 0xffff0000u);
    uint32_t mp;
    asm("cvt.rn.bf16x2.f32 %0, %1, %2;" : "=r"(mp) : "f"(rb), "f"(ra));
    float ra2 = ra - __uint_as_float(mp << 16);
    float rb2 = rb - __uint_as_float(mp & 0xffff0000u);
    uint32_t lp;
    asm("cvt.rn.bf16x2.f32 %0, %1, %2;" : "=r"(lp) : "f"(rb2), "f"(ra2));
    h = hp; m = mp; l = lp;
}
__device__ __forceinline__ uint32_t pack_h2(__half lo, __half hi) {
    return ((uint32_t)__half_as_ushort(hi) << 16) | (uint32_t)__half_as_ushort(lo);
}
__device__ __forceinline__ void split2(float a, float b, uint32_t& h, uint32_t& l) {
    __half ha = __float2half_rn(a), hb = __float2half_rn(b);
    __half la = __float2half_rn(a - __half2float(ha));
    __half lb = __float2half_rn(b - __half2float(hb));
    h = pack_h2(ha, hb);
    l = pack_h2(la, lb);
}

// MUFU exp2
__device__ __forceinline__ float ex2(float f) {
    float r;
    asm("ex2.approx.ftz.f32 %0, %1;" : "=f"(r) : "f"(f));
    return r;
}

// ---------------------------------------------------------------- zero fill
__global__ void zero_o_kernel() {
    int idx = blockIdx.x * blockDim.x + threadIdx.x;
    const int per_tok = 512 / 4;
    const int n4 = NTOK * per_tok;
    float4 z = make_float4(0.f, 0.f, 0.f, 0.f);
    for (int i = idx; i < n4; i += gridDim.x * blockDim.x) {
        int tok = i / per_tok;
        int c4 = i % per_tok;
        ((float4*)(g_o + (size_t)tok * D_MODEL + 256))[c4] = z;
    }
}

// ---------------------------------------------------------------- fp16x2 split (with scale)
// sel: 0 -> g_a*, 1 -> g_w1* (scale 32), 2 -> g_w2*
__global__ __launch_bounds__(256) void split2_kernel(const float* __restrict__ src,
                                                     int n4, int sel) {
    int i = blockIdx.x * blockDim.x + threadIdx.x;
    if (i >= n4) return;
    float4 v = ((const float4*)src)[i];
    float s = (sel == 1) ? W1_SCALE : 1.0f;
    uint32_t h0, l0, h1, l1;
    split2(v.x * s, v.y * s, h0, l0);
    split2(v.z * s, v.w * s, h1, l1);
    uint2* dh; uint2* dl;
    if (sel == 0)      { dh = (uint2*)g_ah;  dl = (uint2*)g_al; }
    else if (sel == 1) { dh = (uint2*)g_w1h; dl = (uint2*)g_w1l; }
    else               { dh = (uint2*)g_w2h; dl = (uint2*)g_w2l; }
    dh[i] = make_uint2(h0, h1);
    dl[i] = make_uint2(l0, l1);
}

// ================================================================ GEMM1 (fp16x2, 3 products, w1 x32-prescaled) -> q bf16x3 + fp16x2
#define GKC 16
#define NCH (D_MODEL / GKC)       // 48
#define G_LVL_B (128 * 48)
#define G_OP_B (2 * G_LVL_B)
#define G_STAGE (2 * G_OP_B)
#define GEMM_SMEM_B (2 * G_STAGE)

__device__ __forceinline__ void gemm_issue(int c, int buf, uint32_t sbase, int tid,
                                           int m0, int n0) {
    int k0 = c * GKC;
    uint32_t sb = sbase + buf * G_STAGE;
    int row = tid >> 1, half = tid & 1;
    const uint16_t* srcs[4] = {g_ah, g_al, g_w1h, g_w1l};
#pragma unroll
    for (int it = 0; it < 4; it++) {
        int grow = (it < 2 ? m0 : n0) + row;
        const uint16_t* sp = srcs[it] + (size_t)grow * D_MODEL + k0 + half * 8;
        uint32_t dst = sb + (it < 2 ? 0 : G_OP_B) + (it & 1) * G_LVL_B + row * 48 + half * 16;
        CP_ASYNC16(dst, sp);
    }
    CP_COMMIT();
}

__global__ __launch_bounds__(256, 1) void gemm_mma_kernel(const float* __restrict__ bias) {
    extern __shared__ uint8_t gsm[];
    uint32_t sbase = smem_u32(gsm);
    int tid = threadIdx.x, warp = tid >> 5, lane = tid & 31;
    int m0 = blockIdx.y * 128, n0 = blockIdx.x * 128;

    float ohi[16][4], olo[16][4];
#pragma unroll
    for (int j = 0; j < 16; j++) {
        ohi[j][0] = ohi[j][1] = ohi[j][2] = ohi[j][3] = 0.f;
        olo[j][0] = olo[j][1] = olo[j][2] = olo[j][3] = 0.f;
    }

    gemm_issue(0, 0, sbase, tid, m0, n0);

    uint32_t arow = (uint32_t)((warp * 16 + (lane & 15)) * 48 + (lane >> 4) * 16);
    uint32_t brow = (uint32_t)(((lane & 7) + ((lane >> 4) << 3)) * 48 + ((lane & 8) ? 16 : 0));

    for (int c = 0; c < NCH; c++) {
        int buf = c & 1;
        if (c + 1 < NCH) {
            gemm_issue(c + 1, buf ^ 1, sbase, tid, m0, n0);
            asm volatile("cp.async.wait_group 1;");
        } else {
            asm volatile("cp.async.wait_group 0;");
        }
        __syncthreads();

        uint32_t ab = sbase + buf * G_STAGE;
        uint32_t bb = ab + G_OP_B;
        uint32_t ah0, ah1, ah2, ah3, al0, al1, al2, al3;
        ldsm_x4(ah0, ah1, ah2, ah3, ab + 0 * G_LVL_B + arow);
        ldsm_x4(al0, al1, al2, al3, ab + 1 * G_LVL_B + arow);
        // hoist all B loads, then round-robin mmas across accumulators
        uint32_t B[8][8];
#pragma unroll
        for (int np = 0; np < 8; np++) {
            uint32_t baddr = bb + (uint32_t)(np * 16 * 48) + brow;
            ldsm_x4(B[np][0], B[np][1], B[np][2], B[np][3], baddr + 0 * G_LVL_B);
            ldsm_x4(B[np][4], B[np][5], B[np][6], B[np][7], baddr + 1 * G_LVL_B);
        }
#pragma unroll
        for (int np = 0; np < 8; np++) {
            mmah(ohi[np * 2 + 0], ah0, ah1, ah2, ah3, B[np][0], B[np][1]);
            mmah(ohi[np * 2 + 1], ah0, ah1, ah2, ah3, B[np][2], B[np][3]);
        }
#pragma unroll
        for (int np = 0; np < 8; np++) {
            mmah(olo[np * 2 + 0], ah0, ah1, ah2, ah3, B[np][4], B[np][5]);
            mmah(olo[np * 2 + 1], ah0, ah1, ah2, ah3, B[np][6], B[np][7]);
        }
#pragma unroll
        for (int np = 0; np < 8; np++) {
            mmah(olo[np * 2 + 0], al0, al1, al2, al3, B[np][0], B[np][1]);
            mmah(olo[np * 2 + 1], al0, al1, al2, al3, B[np][2], B[np][3]);
        }
        __syncthreads();
    }

    // epilogue: undo w1 x32 scale, add bias, write q as bf16x3 + fp16x2
    int r0l = lane >> 2, c2 = (lane & 3) * 2;
    int mrow0 = m0 + warp * 16 + r0l;
    int mrow1 = mrow0 + 8;
#pragma unroll
    for (int j = 0; j < 16; j++) {
        int col = n0 + j * 8 + c2;
        float2 bv = *(const float2*)(bias + col);
        float v0 = (ohi[j][0] + olo[j][0]) * W1_INV + bv.x;
        float v1 = (ohi[j][1] + olo[j][1]) * W1_INV + bv.y;
        float v2 = (ohi[j][2] + olo[j][2]) * W1_INV + bv.x;
        float v3 = (ohi[j][3] + olo[j][3]) * W1_INV + bv.y;
        uint32_t h, m, l;
        uint32_t fh, fl;
        split3(v0, v1, h, m, l);
        split2(v0, v1, fh, fl);
        uint32_t i0 = (uint32_t)(mrow0 * D_MODEL + col) >> 1;
        ((uint32_t*)g_qh)[i0] = h;
        ((uint32_t*)g_qm)[i0] = m;
        ((uint32_t*)g_ql)[i0] = l;
        ((uint32_t*)g_fh)[i0] = fh;
        ((uint32_t*)g_fl)[i0] = fl;
        split3(v2, v3, h, m, l);
        split2(v2, v3, fh, fl);
        uint32_t i1 = (uint32_t)(mrow1 * D_MODEL + col) >> 1;
        ((uint32_t*)g_qh)[i1] = h;
        ((uint32_t*)g_qm)[i1] = m;
        ((uint32_t*)g_ql)[i1] = l;
        ((uint32_t*)g_fh)[i1] = fh;
        ((uint32_t*)g_fl)[i1] = fl;
    }
}

// ================================================================ GEMM2 (2 products: A_h*W_h + A_h*W_l; A single fp16)
#define F_LVL_B (128 * 48)
#define F_STAGE (3 * F_LVL_B)
#define GEMM2_SMEM_B (2 * F_STAGE)

__device__ __forceinline__ void gemm2_issue(int c, int buf, uint32_t sbase, int tid,
                                            int m0, int n0) {
    int k0 = c * GKC;
    uint32_t sb = sbase + buf * F_STAGE;
    int row = tid >> 1, half = tid & 1;
    const uint16_t* srcs[3] = {g_ah, g_w2h, g_w2l};
#pragma unroll
    for (int it = 0; it < 3; it++) {
        int grow = (it < 1 ? m0 : n0) + row;
        const uint16_t* sp = srcs[it] + (size_t)grow * D_MODEL + k0 + half * 8;
        uint32_t dst = sb + it * F_LVL_B + row * 48 + half * 16;
        CP_ASYNC16(dst, sp);
    }
    CP_COMMIT();
}

__global__ __launch_bounds__(256, 1) void gemm2_f16_kernel(const float* __restrict__ bias,
                                                           float* __restrict__ outp) {
    extern __shared__ uint8_t gsm[];
    uint32_t sbase = smem_u32(gsm);
    int tid = threadIdx.x, warp = tid >> 5, lane = tid & 31;
    int m0 = blockIdx.y * 128, n0 = blockIdx.x * 128;

    float ohi[16][4], olo[16][4];
#pragma unroll
    for (int j = 0; j < 16; j++) {
        ohi[j][0] = ohi[j][1] = ohi[j][2] = ohi[j][3] = 0.f;
        olo[j][0] = olo[j][1] = olo[j][2] = olo[j][3] = 0.f;
    }

    gemm2_issue(0, 0, sbase, tid, m0, n0);

    uint32_t arow = (uint32_t)((warp * 16 + (lane & 15)) * 48 + (lane >> 4) * 16);
    uint32_t brow = (uint32_t)(((lane & 7) + ((lane >> 4) << 3)) * 48 + ((lane & 8) ? 16 : 0));

    for (int c = 0; c < NCH; c++) {
        int buf = c & 1;
        if (c + 1 < NCH) {
            gemm2_issue(c + 1, buf ^ 1, sbase, tid, m0, n0);
            asm volatile("cp.async.wait_group 1;");
        } else {
            asm volatile("cp.async.wait_group 0;");
        }
        __syncthreads();

        uint32_t ab = sbase + buf * F_STAGE;
        uint32_t bb = ab + F_LVL_B;
        uint32_t ah0, ah1, ah2, ah3;
        ldsm_x4(ah0, ah1, ah2, ah3, ab + arow);
        uint32_t B[8][8];
#pragma unroll
        for (int np = 0; np < 8; np++) {
            uint32_t baddr = bb + (uint32_t)(np * 16 * 48) + brow;
            ldsm_x4(B[np][0], B[np][1], B[np][2], B[np][3], baddr + 0 * F_LVL_B);
            ldsm_x4(B[np][4], B[np][5], B[np][6], B[np][7], baddr + 1 * F_LVL_B);
        }
#pragma unroll
        for (int np = 0; np < 8; np++) {
            mmah(ohi[np * 2 + 0], ah0, ah1, ah2, ah3, B[np][0], B[np][1]);
            mmah(ohi[np * 2 + 1], ah0, ah1, ah2, ah3, B[np][2], B[np][3]);
        }
#pragma unroll
        for (int np = 0; np < 8; np++) {
            mmah(olo[np * 2 + 0], ah0, ah1, ah2, ah3, B[np][4], B[np][5]);
            mmah(olo[np * 2 + 1], ah0, ah1, ah2, ah3, B[np][6], B[np][7]);
        }
        __syncthreads();
    }

    int r0l = lane >> 2, c2 = (lane & 3) * 2;
    int mrow0 = m0 + warp * 16 + r0l;
    int mrow1 = mrow0 + 8;
#pragma unroll
    for (int j = 0; j < 16; j++) {
        int col = n0 + j * 8 + c2;
        float2 bv = *(const float2*)(bias + col);
        *(float2*)(outp + (size_t)mrow0 * D_MODEL + col) =
            make_float2(ohi[j][0] + olo[j][0] + bv.x, ohi[j][1] + olo[j][1] + bv.y);
        *(float2*)(outp + (size_t)mrow1 * D_MODEL + col) =
            make_float2(ohi[j][2] + olo[j][2] + bv.x, ohi[j][3] + olo[j][3] + bv.y);
    }
}

// ================================================================ attention
// QK: fp16x2 (3 products). PV: bf16x3 (6 products). Fixed-max softmax via MUFU.
// Latency-optimized: per-kc/kk all LDSMs hoisted, mmas round-robin over 8 chains.
#define KT_LVL 8192
#define KT_BUF (5 * KT_LVL)
#define ATTN_SMEM (2 * KT_BUF)

#define P_SCL 0.18033688011111793f
#define P_OFF -23.083120654223414f

__device__ __forceinline__ void attn_stage(uint32_t dstbase, int b, int kbase,
                                           int k0, int r, int h, int tid) {
#pragma unroll
    for (int it = 0; it < 20; it++) {
        int idx = tid + it * 128;
        int lvl = idx >> 9;
        int rem = idx & 511;
        int key = rem >> 3;
        int c16 = rem & 7;
        int posk = kbase + (k0 + key) * r;
        uint32_t goff = (uint32_t)(b * SEQ + posk) * D_MODEL + h * HD + c16 * 8;
        const uint16_t* src;
        switch (lvl) {
            case 0: src = g_fh + goff; break;
            case 1: src = g_fl + goff; break;
            case 2: src = g_qh + goff; break;
            case 3: src = g_qm + goff; break;
            default: src = g_ql + goff; break;
        }
        uint32_t dst = dstbase + lvl * KT_LVL + SWZ((uint32_t)(key * 128 + c16 * 16));
        CP_ASYNC16(dst, src);
    }
    CP_COMMIT();
}

__global__ __launch_bounds__(128, 2) void attn_mma_kernel() {
    extern __shared__ uint8_t ksm[];

    int inst = blockIdx.y;
    int b, h, seg, r, off, slen;
    if (inst < 32)      { b = inst >> 4; int t = inst & 15; seg = t >> 2; h = t & 3;            r = 1; off = 0; slen = 2048; }
    else if (inst < 48) { int t = inst - 32; b = t >> 3; t &= 7; seg = t >> 2; h = 4 + (t & 3); r = 2; off = 1; slen = 4096; }
    else                { int t = inst - 48; b = t >> 2; h = 8 + (t & 3); seg = 0;              r = 4; off = 2; slen = 8192; }

    int tid = threadIdx.x;
    int warp = tid >> 5, lane = tid & 31;
    int kbase = seg * slen + off;
    int qrow0 = blockIdx.x * 64 + warp * 16;

    uint32_t smb = smem_u32(ksm);

    int r0l = lane >> 2;
    int c2 = (lane & 3) * 2;

    // -------- Q fragments (fp16x2 levels)
    int posq0 = kbase + (qrow0 + r0l) * r;
    int posq1 = kbase + (qrow0 + r0l + 8) * r;
    uint32_t qb0 = (uint32_t)(b * SEQ + posq0) * D_MODEL + h * HD;
    uint32_t qb1 = (uint32_t)(b * SEQ + posq1) * D_MODEL + h * HD;
    uint32_t qh[16], ql[16];
#pragma unroll
    for (int kc = 0; kc < 4; kc++) {
        uint32_t i00 = (qb0 + kc * 16 + c2) >> 1;
        uint32_t i10 = (qb1 + kc * 16 + c2) >> 1;
        uint32_t i01 = (qb0 + kc * 16 + c2 + 8) >> 1;
        uint32_t i11 = (qb1 + kc * 16 + c2 + 8) >> 1;
        qh[kc * 4 + 0] = ((const uint32_t*)g_fh)[i00];
        ql[kc * 4 + 0] = ((const uint32_t*)g_fl)[i00];
        qh[kc * 4 + 1] = ((const uint32_t*)g_fh)[i10];
        ql[kc * 4 + 1] = ((const uint32_t*)g_fl)[i10];
        qh[kc * 4 + 2] = ((const uint32_t*)g_fh)[i01];
        ql[kc * 4 + 2] = ((const uint32_t*)g_fl)[i01];
        qh[kc * 4 + 3] = ((const uint32_t*)g_fh)[i11];
        ql[kc * 4 + 3] = ((const uint32_t*)g_fl)[i11];
    }

    float ohi[8][4], olo[8][4];
#pragma unroll
    for (int j = 0; j < 8; j++) {
        ohi[j][0] = ohi[j][1] = ohi[j][2] = ohi[j][3] = 0.f;
        olo[j][0] = olo[j][1] = olo[j][2] = olo[j][3] = 0.f;
    }
    float l0 = 0.f, l1 = 0.f;

    attn_stage(smb, b, kbase, 0, r, h, tid);

    int buf = 0;
    for (int kt = 0; kt < SE / 64; kt++) {
        if (kt + 1 < SE / 64) {
            attn_stage(smb + (buf ^ 1) * KT_BUF, b, kbase, (kt + 1) * 64, r, h, tid);
            asm volatile("cp.async.wait_group 1;");
        } else {
            asm volatile("cp.async.wait_group 0;");
        }
        __syncthreads();

        uint32_t kh_b = smb + buf * KT_BUF;
        uint32_t kl_b = kh_b + KT_LVL;
        uint32_t vh_b = kh_b + 2 * KT_LVL;
        uint32_t vm_b = kh_b + 3 * KT_LVL;
        uint32_t vl_b = kh_b + 4 * KT_LVL;

        // -------- S = Q K^T : fp16x2, split accumulators, 8-chain round-robin
        float shi[8][4], slo[8][4];
#pragma unroll
        for (int j = 0; j < 8; j++) {
            shi[j][0] = shi[j][1] = shi[j][2] = shi[j][3] = 0.f;
            slo[j][0] = slo[j][1] = slo[j][2] = slo[j][3] = 0.f;
        }
#pragma unroll
        for (int kc = 0; kc < 4; kc++) {
            uint32_t a0h = qh[kc * 4 + 0], a1h = qh[kc * 4 + 1],
                     a2h = qh[kc * 4 + 2], a3h = qh[kc * 4 + 3];
            uint32_t a0l = ql[kc * 4 + 0], a1l = ql[kc * 4 + 1],
                     a2l = ql[kc * 4 + 2], a3l = ql[kc * 4 + 3];
            uint32_t B[4][8];
#pragma unroll
            for (int np = 0; np < 4; np++) {
                int key = np * 16 + (lane & 7) + ((lane >> 4) << 3);
                int dim = kc * 16 + (lane & 8);
                uint32_t so = SWZ((uint32_t)(key * 128 + dim * 2));
                ldsm_x4(B[np][0], B[np][1], B[np][2], B[np][3], kh_b + so);
                ldsm_x4(B[np][4], B[np][5], B[np][6], B[np][7], kl_b + so);
            }
#pragma unroll
            for (int np = 0; np < 4; np++) {
                mmah(shi[np * 2 + 0], a0h, a1h, a2h, a3h, B[np][0], B[np][1]);
                mmah(shi[np * 2 + 1], a0h, a1h, a2h, a3h, B[np][2], B[np][3]);
            }
#pragma unroll
            for (int np = 0; np < 4; np++) {
                mmah(slo[np * 2 + 0], a0h, a1h, a2h, a3h, B[np][4], B[np][5]);
                mmah(slo[np * 2 + 1], a0h, a1h, a2h, a3h, B[np][6], B[np][7]);
            }
#pragma unroll
            for (int np = 0; np < 4; np++) {
                mmah(slo[np * 2 + 0], a0l, a1l, a2l, a3l, B[np][0], B[np][1]);
                mmah(slo[np * 2 + 1], a0l, a1l, a2l, a3l, B[np][2], B[np][3]);
            }
        }

        // -------- fixed-max softmax via MUFU; bf16x3 split via packed cvt
        uint32_t pah[8], pam[8], pal[8], pbh[8], pbm[8], pbl[8];
#pragma unroll
        for (int j = 0; j < 8; j++) {
            float p0 = ex2(fmaf(shi[j][0] + slo[j][0], P_SCL, P_OFF));
            float p1 = ex2(fmaf(shi[j][1] + slo[j][1], P_SCL, P_OFF));
            float p2 = ex2(fmaf(shi[j][2] + slo[j][2], P_SCL, P_OFF));
            float p3 = ex2(fmaf(shi[j][3] + slo[j][3], P_SCL, P_OFF));
            l0 += p0 + p1;
            l1 += p2 + p3;
            split3(p0, p1, pah[j], pam[j], pal[j]);
            split3(p2, p3, pbh[j], pbm[j], pbl[j]);
        }

        // -------- O += P V : bf16x3, split accumulators, 8-chain round-robin
#pragma unroll
        for (int kk = 0; kk < 4; kk++) {
            uint32_t a0h = pah[kk * 2], a1h = pbh[kk * 2],
                     a2h = pah[kk * 2 + 1], a3h = pbh[kk * 2 + 1];
            uint32_t a0m = pam[kk * 2], a1m = pbm[kk * 2],
                     a2m = pam[kk * 2 + 1], a3m = pbm[kk * 2 + 1];
            uint32_t a0l = pal[kk * 2], a1l = pbl[kk * 2],
                     a2l = pal[kk * 2 + 1], a3l = pbl[kk * 2 + 1];
            uint32_t B[4][12];
#pragma unroll
            for (int np = 0; np < 4; np++) {
                int key = kk * 16 + (lane & 7) + (lane & 8);
                int dim = np * 16 + ((lane >> 4) << 3);
                uint32_t so = SWZ((uint32_t)(key * 128 + dim * 2));
                ldsm_x4_t(B[np][0], B[np][1], B[np][2], B[np][3], vh_b + so);
                ldsm_x4_t(B[np][4], B[np][5], B[np][6], B[np][7], vm_b + so);
                ldsm_x4_t(B[np][8], B[np][9], B[np][10], B[np][11], vl_b + so);
            }
#pragma unroll
            for (int np = 0; np < 4; np++) {
                mma16816(ohi[np * 2 + 0], a0h, a1h, a2h, a3h, B[np][0], B[np][1]);
                mma16816(ohi[np * 2 + 1], a0h, a1h, a2h, a3h, B[np][2], B[np][3]);
            }
#pragma unroll
            for (int np = 0; np < 4; np++) {
                mma16816(olo[np * 2 + 0], a0h, a1h, a2h, a3h, B[np][4], B[np][5]);
                mma16816(olo[np * 2 + 1], a0h, a1h, a2h, a3h, B[np][6], B[np][7]);
            }
#pragma unroll
            for (int np = 0; np < 4; np++) {
                mma16816(olo[np * 2 + 0], a0m, a1m, a2m, a3m, B[np][0], B[np][1]);
                mma16816(olo[np * 2 + 1], a0m, a1m, a2m, a3m, B[np][2], B[np][3]);
            }
#pragma unroll
            for (int np = 0; np < 4; np++) {
                mma16816(olo[np * 2 + 0], a0m, a1m, a2m, a3m, B[np][4], B[np][5]);
                mma16816(olo[np * 2 + 1], a0m, a1m, a2m, a3m, B[np][6], B[np][7]);
            }
#pragma unroll
            for (int np = 0; np < 4; np++) {
                mma16816(olo[np * 2 + 0], a0h, a1h, a2h, a3h, B[np][8], B[np][9]);
                mma16816(olo[np * 2 + 1], a0h, a1h, a2h, a3h, B[np][10], B[np][11]);
            }
#pragma unroll
            for (int np = 0; np < 4; np++) {
                mma16816(olo[np * 2 + 0], a0l, a1l, a2l, a3l, B[np][0], B[np][1]);
                mma16816(olo[np * 2 + 1], a0l, a1l, a2l, a3l, B[np][2], B[np][3]);
            }
        }
        __syncthreads();
        buf ^= 1;
    }

    // -------- finalize
    l0 += __shfl_xor_sync(0xffffffffu, l0, 1);
    l0 += __shfl_xor_sync(0xffffffffu, l0, 2);
    l1 += __shfl_xor_sync(0xffffffffu, l1, 1);
    l1 += __shfl_xor_sync(0xffffffffu, l1, 2);
    float inv0 = 1.0f / l0, inv1 = 1.0f / l1;
    float* op0 = g_o + ((size_t)b * SEQ + posq0) * D_MODEL + h * HD;
    float* op1 = g_o + ((size_t)b * SEQ + posq1) * D_MODEL + h * HD;
#pragma unroll
    for (int j = 0; j < 8; j++) {
        *(float2*)(op0 + j * 8 + c2) = make_float2((ohi[j][0] + olo[j][0]) * inv0,
                                                   (ohi[j][1] + olo[j][1]) * inv0);
        *(float2*)(op1 + j * 8 + c2) = make_float2((ohi[j][2] + olo[j][2]) * inv1,
                                                   (ohi[j][3] + olo[j][3]) * inv1);
    }
}

// ---------------------------------------------------------------- renorm sums
__global__ __launch_bounds__(256) void reduce1_kernel() {
    int bc = blockIdx.x;
    int b = bc / 3, cb = bc % 3;
    int c = cb * 256 + threadIdx.x;
    size_t base = (size_t)(b * SEQ + blockIdx.y * 256) * D_MODEL + c;
    float acc = 0.f;
    for (int rr = 0; rr < 256; rr++) acc += g_o[base + (size_t)rr * D_MODEL];
    g_part[blockIdx.y][b * D_MODEL + c] = acc;
}
__global__ void reduce2_kernel() {
    int idx = blockIdx.x * 256 + threadIdx.x;
    float acc = 0.f;
#pragma unroll
    for (int j = 0; j < 32; j++) acc += g_part[j][idx];
    g_sum[idx] = acc;
}

// ---------------------------------------------------------------- layernorm (writes fp16 A for gemm2)
__device__ __forceinline__ float blk_sum(float v, float* sh) {
    int lane = threadIdx.x & 31, w = threadIdx.x >> 5;
#pragma unroll
    for (int off = 16; off; off >>= 1) v += __shfl_xor_sync(0xffffffffu, v, off);
    if (lane == 0) sh[w] = v;
    __syncthreads();
    if (threadIdx.x == 0) {
        float t = 0.f;
#pragma unroll
        for (int i = 0; i < 8; i++) t += sh[i];
        sh[8] = t;
    }
    __syncthreads();
    return sh[8];
}

__global__ __launch_bounds__(256) void ln_kernel(const float* __restrict__ gamma,
                                                 const float* __restrict__ beta) {
    __shared__ float sh[9];
    int row = blockIdx.x;
    int b = row >> 13;
    const float* in = g_o + (size_t)row * D_MODEL;
    float v[3];
    float s = 0.f;
#pragma unroll
    for (int i = 0; i < 3; i++) {
        int c = threadIdx.x + i * 256;
        float val = in[c] / (3.0f * g_sum[b * D_MODEL + c]);
        v[i] = val;
        s += val;
    }
    float mean = blk_sum(s, sh) * (1.0f / 768.0f);
    float vs = 0.f;
#pragma unroll
    for (int i = 0; i < 3; i++) {
        float d = v[i] - mean;
        vs += d * d;
    }
    float var = blk_sum(vs, sh) * (1.0f / 768.0f);
    float rstd = rsqrtf(var + 1e-5f);
#pragma unroll
    for (int i = 0; i < 3; i++) {
        int c = threadIdx.x + i * 256;
        float outv = (v[i] - mean) * rstd * gamma[c] + beta[c];
        g_ah[(size_t)row * D_MODEL + c] = __half_as_ushort(__float2half_rn(outv));
    }
}

// ---------------------------------------------------------------- launch
extern "C" void kernel_launch(void* const* d_in, const int* in_sizes, int n_in,
                              void* d_out, int out_size) {
    const float* x      = (const float*)d_in[0];
    const float* w_in   = (const float*)d_in[1];
    const float* b_in   = (const float*)d_in[2];
    const float* w_out  = (const float*)d_in[3];
    const float* b_out  = (const float*)d_in[4];
    const float* gamma  = (const float*)d_in[5];
    const float* beta   = (const float*)d_in[6];
    float* out = (float*)d_out;

    cudaFuncSetAttribute(gemm_mma_kernel, cudaFuncAttributeMaxDynamicSharedMemorySize,
                         GEMM_SMEM_B);
    cudaFuncSetAttribute(gemm2_f16_kernel, cudaFuncAttributeMaxDynamicSharedMemorySize,
                         GEMM2_SMEM_B);
    cudaFuncSetAttribute(attn_mma_kernel, cudaFuncAttributeMaxDynamicSharedMemorySize,
                         ATTN_SMEM);

    const int nbig4 = NTOK * D_MODEL / 4;
    const int nw4 = D_MODEL * D_MODEL / 4;

    zero_o_kernel<<<3072, 256>>>();
    split2_kernel<<<(nbig4 + 255) / 256, 256>>>(x, nbig4, 0);
    split2_kernel<<<(nw4 + 255) / 256, 256>>>(w_in, nw4, 1);
    split2_kernel<<<(nw4 + 255) / 256, 256>>>(w_out, nw4, 2);
    gemm_mma_kernel<<<dim3(6, 128), 256, GEMM_SMEM_B>>>(b_in);
    attn_mma_kernel<<<dim3(32, 56), 128, ATTN_SMEM>>>();
    reduce1_kernel<<<dim3(6, 32), 256>>>();
    reduce2_kernel<<<6, 256>>>();
    ln_kernel<<<NTOK, 256>>>(gamma, beta);
    gemm2_f16_kernel<<<dim3(6, 128), 256, GEMM2_SMEM_B>>>(b_out, out);
}

// round 17
// speedup vs baseline: 2.1988x; 1.0031x over previous
#include <cuda_runtime.h>
#include <cuda_bf16.h>
#include <cuda_fp16.h>
#include <stdint.h>
#include <math.h>

#define D_MODEL 768
#define NHEADS 12
#define HD 64
#define BATCH 2
#define SEQ 8192
#define NTOK (BATCH * SEQ)
#define SE 2048
#define LOG2E 1.4426950408889634f
#define W1_SCALE 32.0f
#define W1_INV 0.03125f

// Scratch (allocation-free rule: __device__ globals)
__device__ float g_o[NTOK * D_MODEL];
__device__ float g_part[32][BATCH * D_MODEL];
__device__ float g_sum[BATCH * D_MODEL];
// g_a*: fp16x2 of x for gemm1; g_ah later holds fp16 of ln-out for gemm2
__device__ uint16_t g_ah[NTOK * D_MODEL], g_al[NTOK * D_MODEL];
// projected q: bf16x3 (V side of PV; renorm-amplified O-path)
__device__ uint16_t g_qh[NTOK * D_MODEL], g_qm[NTOK * D_MODEL], g_ql[NTOK * D_MODEL];
// projected q: fp16x2 (QK S-path)
__device__ uint16_t g_fh[NTOK * D_MODEL], g_fl[NTOK * D_MODEL];
// weights: w1 fp16x2 (x32 pre-scaled), w2 fp16x2
__device__ uint16_t g_w1h[D_MODEL * D_MODEL], g_w1l[D_MODEL * D_MODEL];
__device__ uint16_t g_w2h[D_MODEL * D_MODEL], g_w2l[D_MODEL * D_MODEL];

// ================================================================ helpers
__device__ __forceinline__ uint32_t smem_u32(const void* p) {
    uint32_t a;
    asm("{ .reg .u64 t; cvta.to.shared.u64 t, %1; cvt.u32.u64 %0, t; }" : "=r"(a) : "l"(p));
    return a;
}

#define SWZ(off) ((off) ^ (((off) >> 3) & 0x70))

__device__ __forceinline__ void ldsm_x4(uint32_t& r0, uint32_t& r1, uint32_t& r2,
                                        uint32_t& r3, uint32_t addr) {
    asm volatile("ldmatrix.sync.aligned.m8n8.x4.shared.b16 {%0,%1,%2,%3}, [%4];"
                 : "=r"(r0), "=r"(r1), "=r"(r2), "=r"(r3) : "r"(addr));
}
__device__ __forceinline__ void ldsm_x4_t(uint32_t& r0, uint32_t& r1, uint32_t& r2,
                                          uint32_t& r3, uint32_t addr) {
    asm volatile("ldmatrix.sync.aligned.m8n8.x4.trans.shared.b16 {%0,%1,%2,%3}, [%4];"
                 : "=r"(r0), "=r"(r1), "=r"(r2), "=r"(r3) : "r"(addr));
}
// bf16 mma
__device__ __forceinline__ void mma16816(float* c, uint32_t a0, uint32_t a1, uint32_t a2,
                                         uint32_t a3, uint32_t b0, uint32_t b1) {
    asm volatile(
        "mma.sync.aligned.m16n8k16.row.col.f32.bf16.bf16.f32 "
        "{%0,%1,%2,%3}, {%4,%5,%6,%7}, {%8,%9}, {%0,%1,%2,%3};"
        : "+f"(c[0]), "+f"(c[1]), "+f"(c[2]), "+f"(c[3])
        : "r"(a0), "r"(a1), "r"(a2), "r"(a3), "r"(b0), "r"(b1));
}
// fp16 mma
__device__ __forceinline__ void mmah(float* c, uint32_t a0, uint32_t a1, uint32_t a2,
                                     uint32_t a3, uint32_t b0, uint32_t b1) {
    asm volatile(
        "mma.sync.aligned.m16n8k16.row.col.f32.f16.f16.f32 "
        "{%0,%1,%2,%3}, {%4,%5,%6,%7}, {%8,%9}, {%0,%1,%2,%3};"
        : "+f"(c[0]), "+f"(c[1]), "+f"(c[2]), "+f"(c[3])
        : "r"(a0), "r"(a1), "r"(a2), "r"(a3), "r"(b0), "r"(b1));
}
#define CP_ASYNC16(dst, src) \
    asm volatile("cp.async.cg.shared.global [%0], [%1], 16;" :: "r"(dst), "l"(src))
#define CP_COMMIT() asm volatile("cp.async.commit_group;")

// packed bf16x3 split (bit-identical to scalar version)
__device__ __forceinline__ void split3(float a, float b,
                                       uint32_t& h, uint32_t& m, uint32_t& l) {
    uint32_t hp;
    asm("cvt.rn.bf16x2.f32 %0, %1, %2;" : "=r"(hp) : "f"(b), "f"(a));
    float ra = a - __uint_as_float(hp << 16);
    float rb = b - __uint_as_float(hp & 0xffff0000u);
    uint32_t mp;
    asm("cvt.rn.bf16x2.f32 %0, %1, %2;" : "=r"(mp) : "f"(rb), "f"(ra));
    float ra2 = ra - __uint_as_float(mp << 16);
    float rb2 = rb - __uint_as_float(mp & 0xffff0000u);
    uint32_t lp;
    asm("cvt.rn.bf16x2.f32 %0, %1, %2;" : "=r"(lp) : "f"(rb2), "f"(ra2));
    h = hp; m = mp; l = lp;
}
__device__ __forceinline__ uint32_t pack_h2(__half lo, __half hi) {
    return ((uint32_t)__half_as_ushort(hi) << 16) | (uint32_t)__half_as_ushort(lo);
}
__device__ __forceinline__ void split2(float a, float b, uint32_t& h, uint32_t& l) {
    __half ha = __float2half_rn(a), hb = __float2half_rn(b);
    __half la = __float2half_rn(a - __half2float(ha));
    __half lb = __float2half_rn(b - __half2float(hb));
    h = pack_h2(ha, hb);
    l = pack_h2(la, lb);
}

// MUFU exp2
__device__ __forceinline__ float ex2(float f) {
    float r;
    asm("ex2.approx.ftz.f32 %0, %1;" : "=f"(r) : "f"(f));
    return r;
}

// ---------------------------------------------------------------- zero fill
__global__ void zero_o_kernel() {
    int idx = blockIdx.x * blockDim.x + threadIdx.x;
    const int per_tok = 512 / 4;
    const int n4 = NTOK * per_tok;
    float4 z = make_float4(0.f, 0.f, 0.f, 0.f);
    for (int i = idx; i < n4; i += gridDim.x * blockDim.x) {
        int tok = i / per_tok;
        int c4 = i % per_tok;
        ((float4*)(g_o + (size_t)tok * D_MODEL + 256))[c4] = z;
    }
}

// ---------------------------------------------------------------- fp16x2 split (with scale)
// sel: 0 -> g_a*, 1 -> g_w1* (scale 32), 2 -> g_w2*
__global__ __launch_bounds__(256) void split2_kernel(const float* __restrict__ src,
                                                     int n4, int sel) {
    int i = blockIdx.x * blockDim.x + threadIdx.x;
    if (i >= n4) return;
    float4 v = ((const float4*)src)[i];
    float s = (sel == 1) ? W1_SCALE : 1.0f;
    uint32_t h0, l0, h1, l1;
    split2(v.x * s, v.y * s, h0, l0);
    split2(v.z * s, v.w * s, h1, l1);
    uint2* dh; uint2* dl;
    if (sel == 0)      { dh = (uint2*)g_ah;  dl = (uint2*)g_al; }
    else if (sel == 1) { dh = (uint2*)g_w1h; dl = (uint2*)g_w1l; }
    else               { dh = (uint2*)g_w2h; dl = (uint2*)g_w2l; }
    dh[i] = make_uint2(h0, h1);
    dl[i] = make_uint2(l0, l1);
}

// ================================================================ GEMM1 (fp16x2, 3 products, w1 x32-prescaled) -> q bf16x3 + fp16x2
#define GKC 16
#define NCH (D_MODEL / GKC)       // 48
#define G_LVL_B (128 * 48)
#define G_OP_B (2 * G_LVL_B)
#define G_STAGE (2 * G_OP_B)
#define GEMM_SMEM_B (2 * G_STAGE)

__device__ __forceinline__ void gemm_issue(int c, int buf, uint32_t sbase, int tid,
                                           int m0, int n0) {
    int k0 = c * GKC;
    uint32_t sb = sbase + buf * G_STAGE;
    int row = tid >> 1, half = tid & 1;
    const uint16_t* srcs[4] = {g_ah, g_al, g_w1h, g_w1l};
#pragma unroll
    for (int it = 0; it < 4; it++) {
        int grow = (it < 2 ? m0 : n0) + row;
        const uint16_t* sp = srcs[it] + (size_t)grow * D_MODEL + k0 + half * 8;
        uint32_t dst = sb + (it < 2 ? 0 : G_OP_B) + (it & 1) * G_LVL_B + row * 48 + half * 16;
        CP_ASYNC16(dst, sp);
    }
    CP_COMMIT();
}

__global__ __launch_bounds__(256, 1) void gemm_mma_kernel(const float* __restrict__ bias) {
    extern __shared__ uint8_t gsm[];
    uint32_t sbase = smem_u32(gsm);
    int tid = threadIdx.x, warp = tid >> 5, lane = tid & 31;
    int m0 = blockIdx.y * 128, n0 = blockIdx.x * 128;

    float ohi[16][4], olo[16][4];
#pragma unroll
    for (int j = 0; j < 16; j++) {
        ohi[j][0] = ohi[j][1] = ohi[j][2] = ohi[j][3] = 0.f;
        olo[j][0] = olo[j][1] = olo[j][2] = olo[j][3] = 0.f;
    }

    gemm_issue(0, 0, sbase, tid, m0, n0);

    uint32_t arow = (uint32_t)((warp * 16 + (lane & 15)) * 48 + (lane >> 4) * 16);
    uint32_t brow = (uint32_t)(((lane & 7) + ((lane >> 4) << 3)) * 48 + ((lane & 8) ? 16 : 0));

    for (int c = 0; c < NCH; c++) {
        int buf = c & 1;
        if (c + 1 < NCH) {
            gemm_issue(c + 1, buf ^ 1, sbase, tid, m0, n0);
            asm volatile("cp.async.wait_group 1;");
        } else {
            asm volatile("cp.async.wait_group 0;");
        }
        __syncthreads();

        uint32_t ab = sbase + buf * G_STAGE;
        uint32_t bb = ab + G_OP_B;
        uint32_t ah0, ah1, ah2, ah3, al0, al1, al2, al3;
        ldsm_x4(ah0, ah1, ah2, ah3, ab + 0 * G_LVL_B + arow);
        ldsm_x4(al0, al1, al2, al3, ab + 1 * G_LVL_B + arow);
        // hoist all B loads, then round-robin mmas across accumulators
        uint32_t B[8][8];
#pragma unroll
        for (int np = 0; np < 8; np++) {
            uint32_t baddr = bb + (uint32_t)(np * 16 * 48) + brow;
            ldsm_x4(B[np][0], B[np][1], B[np][2], B[np][3], baddr + 0 * G_LVL_B);
            ldsm_x4(B[np][4], B[np][5], B[np][6], B[np][7], baddr + 1 * G_LVL_B);
        }
#pragma unroll
        for (int np = 0; np < 8; np++) {
            mmah(ohi[np * 2 + 0], ah0, ah1, ah2, ah3, B[np][0], B[np][1]);
            mmah(ohi[np * 2 + 1], ah0, ah1, ah2, ah3, B[np][2], B[np][3]);
        }
#pragma unroll
        for (int np = 0; np < 8; np++) {
            mmah(olo[np * 2 + 0], ah0, ah1, ah2, ah3, B[np][4], B[np][5]);
            mmah(olo[np * 2 + 1], ah0, ah1, ah2, ah3, B[np][6], B[np][7]);
        }
#pragma unroll
        for (int np = 0; np < 8; np++) {
            mmah(olo[np * 2 + 0], al0, al1, al2, al3, B[np][0], B[np][1]);
            mmah(olo[np * 2 + 1], al0, al1, al2, al3, B[np][2], B[np][3]);
        }
        __syncthreads();
    }

    // epilogue: undo w1 x32 scale, add bias, write q as bf16x3 + fp16x2
    int r0l = lane >> 2, c2 = (lane & 3) * 2;
    int mrow0 = m0 + warp * 16 + r0l;
    int mrow1 = mrow0 + 8;
#pragma unroll
    for (int j = 0; j < 16; j++) {
        int col = n0 + j * 8 + c2;
        float2 bv = *(const float2*)(bias + col);
        float v0 = (ohi[j][0] + olo[j][0]) * W1_INV + bv.x;
        float v1 = (ohi[j][1] + olo[j][1]) * W1_INV + bv.y;
        float v2 = (ohi[j][2] + olo[j][2]) * W1_INV + bv.x;
        float v3 = (ohi[j][3] + olo[j][3]) * W1_INV + bv.y;
        uint32_t h, m, l;
        uint32_t fh, fl;
        split3(v0, v1, h, m, l);
        split2(v0, v1, fh, fl);
        uint32_t i0 = (uint32_t)(mrow0 * D_MODEL + col) >> 1;
        ((uint32_t*)g_qh)[i0] = h;
        ((uint32_t*)g_qm)[i0] = m;
        ((uint32_t*)g_ql)[i0] = l;
        ((uint32_t*)g_fh)[i0] = fh;
        ((uint32_t*)g_fl)[i0] = fl;
        split3(v2, v3, h, m, l);
        split2(v2, v3, fh, fl);
        uint32_t i1 = (uint32_t)(mrow1 * D_MODEL + col) >> 1;
        ((uint32_t*)g_qh)[i1] = h;
        ((uint32_t*)g_qm)[i1] = m;
        ((uint32_t*)g_ql)[i1] = l;
        ((uint32_t*)g_fh)[i1] = fh;
        ((uint32_t*)g_fl)[i1] = fl;
    }
}

// ================================================================ GEMM2 (2 products: A_h*W_h + A_h*W_l; A single fp16)
#define F_LVL_B (128 * 48)
#define F_STAGE (3 * F_LVL_B)
#define GEMM2_SMEM_B (2 * F_STAGE)

__device__ __forceinline__ void gemm2_issue(int c, int buf, uint32_t sbase, int tid,
                                            int m0, int n0) {
    int k0 = c * GKC;
    uint32_t sb = sbase + buf * F_STAGE;
    int row = tid >> 1, half = tid & 1;
    const uint16_t* srcs[3] = {g_ah, g_w2h, g_w2l};
#pragma unroll
    for (int it = 0; it < 3; it++) {
        int grow = (it < 1 ? m0 : n0) + row;
        const uint16_t* sp = srcs[it] + (size_t)grow * D_MODEL + k0 + half * 8;
        uint32_t dst = sb + it * F_LVL_B + row * 48 + half * 16;
        CP_ASYNC16(dst, sp);
    }
    CP_COMMIT();
}

__global__ __launch_bounds__(256, 1) void gemm2_f16_kernel(const float* __restrict__ bias,
                                                           float* __restrict__ outp) {
    extern __shared__ uint8_t gsm[];
    uint32_t sbase = smem_u32(gsm);
    int tid = threadIdx.x, warp = tid >> 5, lane = tid & 31;
    int m0 = blockIdx.y * 128, n0 = blockIdx.x * 128;

    float ohi[16][4], olo[16][4];
#pragma unroll
    for (int j = 0; j < 16; j++) {
        ohi[j][0] = ohi[j][1] = ohi[j][2] = ohi[j][3] = 0.f;
        olo[j][0] = olo[j][1] = olo[j][2] = olo[j][3] = 0.f;
    }

    gemm2_issue(0, 0, sbase, tid, m0, n0);

    uint32_t arow = (uint32_t)((warp * 16 + (lane & 15)) * 48 + (lane >> 4) * 16);
    uint32_t brow = (uint32_t)(((lane & 7) + ((lane >> 4) << 3)) * 48 + ((lane & 8) ? 16 : 0));

    for (int c = 0; c < NCH; c++) {
        int buf = c & 1;
        if (c + 1 < NCH) {
            gemm2_issue(c + 1, buf ^ 1, sbase, tid, m0, n0);
            asm volatile("cp.async.wait_group 1;");
        } else {
            asm volatile("cp.async.wait_group 0;");
        }
        __syncthreads();

        uint32_t ab = sbase + buf * F_STAGE;
        uint32_t bb = ab + F_LVL_B;
        uint32_t ah0, ah1, ah2, ah3;
        ldsm_x4(ah0, ah1, ah2, ah3, ab + arow);
        uint32_t B[8][8];
#pragma unroll
        for (int np = 0; np < 8; np++) {
            uint32_t baddr = bb + (uint32_t)(np * 16 * 48) + brow;
            ldsm_x4(B[np][0], B[np][1], B[np][2], B[np][3], baddr + 0 * F_LVL_B);
            ldsm_x4(B[np][4], B[np][5], B[np][6], B[np][7], baddr + 1 * F_LVL_B);
        }
#pragma unroll
        for (int np = 0; np < 8; np++) {
            mmah(ohi[np * 2 + 0], ah0, ah1, ah2, ah3, B[np][0], B[np][1]);
            mmah(ohi[np * 2 + 1], ah0, ah1, ah2, ah3, B[np][2], B[np][3]);
        }
#pragma unroll
        for (int np = 0; np < 8; np++) {
            mmah(olo[np * 2 + 0], ah0, ah1, ah2, ah3, B[np][4], B[np][5]);
            mmah(olo[np * 2 + 1], ah0, ah1, ah2, ah3, B[np][6], B[np][7]);
        }
        __syncthreads();
    }

    int r0l = lane >> 2, c2 = (lane & 3) * 2;
    int mrow0 = m0 + warp * 16 + r0l;
    int mrow1 = mrow0 + 8;
#pragma unroll
    for (int j = 0; j < 16; j++) {
        int col = n0 + j * 8 + c2;
        float2 bv = *(const float2*)(bias + col);
        *(float2*)(outp + (size_t)mrow0 * D_MODEL + col) =
            make_float2(ohi[j][0] + olo[j][0] + bv.x, ohi[j][1] + olo[j][1] + bv.y);
        *(float2*)(outp + (size_t)mrow1 * D_MODEL + col) =
            make_float2(ohi[j][2] + olo[j][2] + bv.x, ohi[j][3] + olo[j][3] + bv.y);
    }
}

// ================================================================ attention
// QK: fp16x2 (3 products). PV: bf16x3 (6 products). Fixed-max softmax via MUFU.
// Latency-optimized: per-kc/kk all LDSMs hoisted, mmas round-robin over 8 chains.
#define KT_LVL 8192
#define KT_BUF (5 * KT_LVL)
#define ATTN_SMEM (2 * KT_BUF)

#define P_SCL 0.18033688011111793f
#define P_OFF -23.083120654223414f

__device__ __forceinline__ void attn_stage(uint32_t dstbase, int b, int kbase,
                                           int k0, int r, int h, int tid) {
#pragma unroll
    for (int it = 0; it < 20; it++) {
        int idx = tid + it * 128;
        int lvl = idx >> 9;
        int rem = idx & 511;
        int key = rem >> 3;
        int c16 = rem & 7;
        int posk = kbase + (k0 + key) * r;
        uint32_t goff = (uint32_t)(b * SEQ + posk) * D_MODEL + h * HD + c16 * 8;
        const uint16_t* src;
        switch (lvl) {
            case 0: src = g_fh + goff; break;
            case 1: src = g_fl + goff; break;
            case 2: src = g_qh + goff; break;
            case 3: src = g_qm + goff; break;
            default: src = g_ql + goff; break;
        }
        uint32_t dst = dstbase + lvl * KT_LVL + SWZ((uint32_t)(key * 128 + c16 * 16));
        CP_ASYNC16(dst, src);
    }
    CP_COMMIT();
}

__global__ __launch_bounds__(128, 2) void attn_mma_kernel() {
    extern __shared__ uint8_t ksm[];

    int inst = blockIdx.y;
    int b, h, seg, r, off, slen;
    if (inst < 32)      { b = inst >> 4; int t = inst & 15; seg = t >> 2; h = t & 3;            r = 1; off = 0; slen = 2048; }
    else if (inst < 48) { int t = inst - 32; b = t >> 3; t &= 7; seg = t >> 2; h = 4 + (t & 3); r = 2; off = 1; slen = 4096; }
    else                { int t = inst - 48; b = t >> 2; h = 8 + (t & 3); seg = 0;              r = 4; off = 2; slen = 8192; }

    int tid = threadIdx.x;
    int warp = tid >> 5, lane = tid & 31;
    int kbase = seg * slen + off;
    int qrow0 = blockIdx.x * 64 + warp * 16;

    uint32_t smb = smem_u32(ksm);

    int r0l = lane >> 2;
    int c2 = (lane & 3) * 2;

    // -------- Q fragments (fp16x2 levels)
    int posq0 = kbase + (qrow0 + r0l) * r;
    int posq1 = kbase + (qrow0 + r0l + 8) * r;
    uint32_t qb0 = (uint32_t)(b * SEQ + posq0) * D_MODEL + h * HD;
    uint32_t qb1 = (uint32_t)(b * SEQ + posq1) * D_MODEL + h * HD;
    uint32_t qh[16], ql[16];
#pragma unroll
    for (int kc = 0; kc < 4; kc++) {
        uint32_t i00 = (qb0 + kc * 16 + c2) >> 1;
        uint32_t i10 = (qb1 + kc * 16 + c2) >> 1;
        uint32_t i01 = (qb0 + kc * 16 + c2 + 8) >> 1;
        uint32_t i11 = (qb1 + kc * 16 + c2 + 8) >> 1;
        qh[kc * 4 + 0] = ((const uint32_t*)g_fh)[i00];
        ql[kc * 4 + 0] = ((const uint32_t*)g_fl)[i00];
        qh[kc * 4 + 1] = ((const uint32_t*)g_fh)[i10];
        ql[kc * 4 + 1] = ((const uint32_t*)g_fl)[i10];
        qh[kc * 4 + 2] = ((const uint32_t*)g_fh)[i01];
        ql[kc * 4 + 2] = ((const uint32_t*)g_fl)[i01];
        qh[kc * 4 + 3] = ((const uint32_t*)g_fh)[i11];
        ql[kc * 4 + 3] = ((const uint32_t*)g_fl)[i11];
    }

    float ohi[8][4], olo[8][4];
#pragma unroll
    for (int j = 0; j < 8; j++) {
        ohi[j][0] = ohi[j][1] = ohi[j][2] = ohi[j][3] = 0.f;
        olo[j][0] = olo[j][1] = olo[j][2] = olo[j][3] = 0.f;
    }
    float l0 = 0.f, l1 = 0.f;

    attn_stage(smb, b, kbase, 0, r, h, tid);

    int buf = 0;
    for (int kt = 0; kt < SE / 64; kt++) {
        if (kt + 1 < SE / 64) {
            attn_stage(smb + (buf ^ 1) * KT_BUF, b, kbase, (kt + 1) * 64, r, h, tid);
            asm volatile("cp.async.wait_group 1;");
        } else {
            asm volatile("cp.async.wait_group 0;");
        }
        __syncthreads();

        uint32_t kh_b = smb + buf * KT_BUF;
        uint32_t kl_b = kh_b + KT_LVL;
        uint32_t vh_b = kh_b + 2 * KT_LVL;
        uint32_t vm_b = kh_b + 3 * KT_LVL;
        uint32_t vl_b = kh_b + 4 * KT_LVL;

        // -------- S = Q K^T : fp16x2, split accumulators, 8-chain round-robin
        float shi[8][4], slo[8][4];
#pragma unroll
        for (int j = 0; j < 8; j++) {
            shi[j][0] = shi[j][1] = shi[j][2] = shi[j][3] = 0.f;
            slo[j][0] = slo[j][1] = slo[j][2] = slo[j][3] = 0.f;
        }
#pragma unroll
        for (int kc = 0; kc < 4; kc++) {
            uint32_t a0h = qh[kc * 4 + 0], a1h = qh[kc * 4 + 1],
                     a2h = qh[kc * 4 + 2], a3h = qh[kc * 4 + 3];
            uint32_t a0l = ql[kc * 4 + 0], a1l = ql[kc * 4 + 1],
                     a2l = ql[kc * 4 + 2], a3l = ql[kc * 4 + 3];
            uint32_t B[4][8];
#pragma unroll
            for (int np = 0; np < 4; np++) {
                int key = np * 16 + (lane & 7) + ((lane >> 4) << 3);
                int dim = kc * 16 + (lane & 8);
                uint32_t so = SWZ((uint32_t)(key * 128 + dim * 2));
                ldsm_x4(B[np][0], B[np][1], B[np][2], B[np][3], kh_b + so);
                ldsm_x4(B[np][4], B[np][5], B[np][6], B[np][7], kl_b + so);
            }
#pragma unroll
            for (int np = 0; np < 4; np++) {
                mmah(shi[np * 2 + 0], a0h, a1h, a2h, a3h, B[np][0], B[np][1]);
                mmah(shi[np * 2 + 1], a0h, a1h, a2h, a3h, B[np][2], B[np][3]);
            }
#pragma unroll
            for (int np = 0; np < 4; np++) {
                mmah(slo[np * 2 + 0], a0h, a1h, a2h, a3h, B[np][4], B[np][5]);
                mmah(slo[np * 2 + 1], a0h, a1h, a2h, a3h, B[np][6], B[np][7]);
            }
#pragma unroll
            for (int np = 0; np < 4; np++) {
                mmah(slo[np * 2 + 0], a0l, a1l, a2l, a3l, B[np][0], B[np][1]);
                mmah(slo[np * 2 + 1], a0l, a1l, a2l, a3l, B[np][2], B[np][3]);
            }
        }

        // -------- fixed-max softmax via MUFU; bf16x3 split via packed cvt
        uint32_t pah[8], pam[8], pal[8], pbh[8], pbm[8], pbl[8];
#pragma unroll
        for (int j = 0; j < 8; j++) {
            float p0 = ex2(fmaf(shi[j][0] + slo[j][0], P_SCL, P_OFF));
            float p1 = ex2(fmaf(shi[j][1] + slo[j][1], P_SCL, P_OFF));
            float p2 = ex2(fmaf(shi[j][2] + slo[j][2], P_SCL, P_OFF));
            float p3 = ex2(fmaf(shi[j][3] + slo[j][3], P_SCL, P_OFF));
            l0 += p0 + p1;
            l1 += p2 + p3;
            split3(p0, p1, pah[j], pam[j], pal[j]);
            split3(p2, p3, pbh[j], pbm[j], pbl[j]);
        }

        // -------- O += P V : bf16x3, split accumulators, 8-chain round-robin
#pragma unroll
        for (int kk = 0; kk < 4; kk++) {
            uint32_t a0h = pah[kk * 2], a1h = pbh[kk * 2],
                     a2h = pah[kk * 2 + 1], a3h = pbh[kk * 2 + 1];
            uint32_t a0m = pam[kk * 2], a1m = pbm[kk * 2],
                     a2m = pam[kk * 2 + 1], a3m = pbm[kk * 2 + 1];
            uint32_t a0l = pal[kk * 2], a1l = pbl[kk * 2],
                     a2l = pal[kk * 2 + 1], a3l = pbl[kk * 2 + 1];
            uint32_t B[4][12];
#pragma unroll
            for (int np = 0; np < 4; np++) {
                int key = kk * 16 + (lane & 7) + (lane & 8);
                int dim = np * 16 + ((lane >> 4) << 3);
                uint32_t so = SWZ((uint32_t)(key * 128 + dim * 2));
                ldsm_x4_t(B[np][0], B[np][1], B[np][2], B[np][3], vh_b + so);
                ldsm_x4_t(B[np][4], B[np][5], B[np][6], B[np][7], vm_b + so);
                ldsm_x4_t(B[np][8], B[np][9], B[np][10], B[np][11], vl_b + so);
            }
#pragma unroll
            for (int np = 0; np < 4; np++) {
                mma16816(ohi[np * 2 + 0], a0h, a1h, a2h, a3h, B[np][0], B[np][1]);
                mma16816(ohi[np * 2 + 1], a0h, a1h, a2h, a3h, B[np][2], B[np][3]);
            }
#pragma unroll
            for (int np = 0; np < 4; np++) {
                mma16816(olo[np * 2 + 0], a0h, a1h, a2h, a3h, B[np][4], B[np][5]);
                mma16816(olo[np * 2 + 1], a0h, a1h, a2h, a3h, B[np][6], B[np][7]);
            }
#pragma unroll
            for (int np = 0; np < 4; np++) {
                mma16816(olo[np * 2 + 0], a0m, a1m, a2m, a3m, B[np][0], B[np][1]);
                mma16816(olo[np * 2 + 1], a0m, a1m, a2m, a3m, B[np][2], B[np][3]);
            }
#pragma unroll
            for (int np = 0; np < 4; np++) {
                mma16816(olo[np * 2 + 0], a0m, a1m, a2m, a3m, B[np][4], B[np][5]);
                mma16816(olo[np * 2 + 1], a0m, a1m, a2m, a3m, B[np][6], B[np][7]);
            }
#pragma unroll
            for (int np = 0; np < 4; np++) {
                mma16816(olo[np * 2 + 0], a0h, a1h, a2h, a3h, B[np][8], B[np][9]);
                mma16816(olo[np * 2 + 1], a0h, a1h, a2h, a3h, B[np][10], B[np][11]);
            }
#pragma unroll
            for (int np = 0; np < 4; np++) {
                mma16816(olo[np * 2 + 0], a0l, a1l, a2l, a3l, B[np][0], B[np][1]);
                mma16816(olo[np * 2 + 1], a0l, a1l, a2l, a3l, B[np][2], B[np][3]);
            }
        }
        __syncthreads();
        buf ^= 1;
    }

    // -------- finalize
    l0 += __shfl_xor_sync(0xffffffffu, l0, 1);
    l0 += __shfl_xor_sync(0xffffffffu, l0, 2);
    l1 += __shfl_xor_sync(0xffffffffu, l1, 1);
    l1 += __shfl_xor_sync(0xffffffffu, l1, 2);
    float inv0 = 1.0f / l0, inv1 = 1.0f / l1;
    float* op0 = g_o + ((size_t)b * SEQ + posq0) * D_MODEL + h * HD;
    float* op1 = g_o + ((size_t)b * SEQ + posq1) * D_MODEL + h * HD;
#pragma unroll
    for (int j = 0; j < 8; j++) {
        *(float2*)(op0 + j * 8 + c2) = make_float2((ohi[j][0] + olo[j][0]) * inv0,
                                                   (ohi[j][1] + olo[j][1]) * inv0);
        *(float2*)(op1 + j * 8 + c2) = make_float2((ohi[j][2] + olo[j][2]) * inv1,
                                                   (ohi[j][3] + olo[j][3]) * inv1);
    }
}

// ---------------------------------------------------------------- renorm sums
__global__ __launch_bounds__(256) void reduce1_kernel() {
    int bc = blockIdx.x;
    int b = bc / 3, cb = bc % 3;
    int c = cb * 256 + threadIdx.x;
    size_t base = (size_t)(b * SEQ + blockIdx.y * 256) * D_MODEL + c;
    float acc = 0.f;
    for (int rr = 0; rr < 256; rr++) acc += g_o[base + (size_t)rr * D_MODEL];
    g_part[blockIdx.y][b * D_MODEL + c] = acc;
}
__global__ void reduce2_kernel() {
    int idx = blockIdx.x * 256 + threadIdx.x;
    float acc = 0.f;
#pragma unroll
    for (int j = 0; j < 32; j++) acc += g_part[j][idx];
    g_sum[idx] = acc;
}

// ---------------------------------------------------------------- layernorm (writes fp16 A for gemm2)
__device__ __forceinline__ float blk_sum(float v, float* sh) {
    int lane = threadIdx.x & 31, w = threadIdx.x >> 5;
#pragma unroll
    for (int off = 16; off; off >>= 1) v += __shfl_xor_sync(0xffffffffu, v, off);
    if (lane == 0) sh[w] = v;
    __syncthreads();
    if (threadIdx.x == 0) {
        float t = 0.f;
#pragma unroll
        for (int i = 0; i < 8; i++) t += sh[i];
        sh[8] = t;
    }
    __syncthreads();
    return sh[8];
}

__global__ __launch_bounds__(256) void ln_kernel(const float* __restrict__ gamma,
                                                 const float* __restrict__ beta) {
    __shared__ float sh[9];
    int row = blockIdx.x;
    int b = row >> 13;
    const float* in = g_o + (size_t)row * D_MODEL;
    float v[3];
    float s = 0.f;
#pragma unroll
    for (int i = 0; i < 3; i++) {
        int c = threadIdx.x + i * 256;
        float val = in[c] / (3.0f * g_sum[b * D_MODEL + c]);
        v[i] = val;
        s += val;
    }
    float mean = blk_sum(s, sh) * (1.0f / 768.0f);
    float vs = 0.f;
#pragma unroll
    for (int i = 0; i < 3; i++) {
        float d = v[i] - mean;
        vs += d * d;
    }
    float var = blk_sum(vs, sh) * (1.0f / 768.0f);
    float rstd = rsqrtf(var + 1e-5f);
#pragma unroll
    for (int i = 0; i < 3; i++) {
        int c = threadIdx.x + i * 256;
        float outv = (v[i] - mean) * rstd * gamma[c] + beta[c];
        g_ah[(size_t)row * D_MODEL + c] = __half_as_ushort(__float2half_rn(outv));
    }
}

// ---------------------------------------------------------------- launch
extern "C" void kernel_launch(void* const* d_in, const int* in_sizes, int n_in,
                              void* d_out, int out_size) {
    const float* x      = (const float*)d_in[0];
    const float* w_in   = (const float*)d_in[1];
    const float* b_in   = (const float*)d_in[2];
    const float* w_out  = (const float*)d_in[3];
    const float* b_out  = (const float*)d_in[4];
    const float* gamma  = (const float*)d_in[5];
    const float* beta   = (const float*)d_in[6];
    float* out = (float*)d_out;

    cudaFuncSetAttribute(gemm_mma_kernel, cudaFuncAttributeMaxDynamicSharedMemorySize,
                         GEMM_SMEM_B);
    cudaFuncSetAttribute(gemm2_f16_kernel, cudaFuncAttributeMaxDynamicSharedMemorySize,
                         GEMM2_SMEM_B);
    cudaFuncSetAttribute(attn_mma_kernel, cudaFuncAttributeMaxDynamicSharedMemorySize,
                         ATTN_SMEM);

    const int nbig4 = NTOK * D_MODEL / 4;
    const int nw4 = D_MODEL * D_MODEL / 4;

    zero_o_kernel<<<3072, 256>>>();
    split2_kernel<<<(nbig4 + 255) / 256, 256>>>(x, nbig4, 0);
    split2_kernel<<<(nw4 + 255) / 256, 256>>>(w_in, nw4, 1);
    split2_kernel<<<(nw4 + 255) / 256, 256>>>(w_out, nw4, 2);
    gemm_mma_kernel<<<dim3(6, 128), 256, GEMM_SMEM_B>>>(b_in);
    attn_mma_kernel<<<dim3(32, 56), 128, ATTN_SMEM>>>();
    reduce1_kernel<<<dim3(6, 32), 256>>>();
    reduce2_kernel<<<6, 256>>>();
    ln_kernel<<<NTOK, 256>>>(gamma, beta);
    gemm2_f16_kernel<<<dim3(6, 128), 256, GEMM2_SMEM_B>>>(b_out, out);
}